// round 10
// baseline (speedup 1.0000x reference)
#include <cuda_runtime.h>
#include <cuda_bf16.h>
#include <math.h>
#include <stdint.h>
#include <string.h>

// ---------------- problem constants ----------------
#define BB   4
#define SS   1024
#define EE   1024
#define HH   16
#define KDIM 64
#define VDIM 64
#define DD   4096
#define MTOK 4096            // B*S tokens
#define LNEPS 1e-5f

// ---------------- device scratch (static globals; no allocations) ----------------
__device__ float g_x1[MTOK * EE];
__device__ __nv_bfloat16 g_sah[(size_t)MTOK * DD];
__device__ __nv_bfloat16 g_sal[(size_t)MTOK * DD];
__device__ __nv_bfloat16 g_sbh[(size_t)MTOK * DD];
__device__ __nv_bfloat16 g_sbl[(size_t)MTOK * DD];
__device__ __nv_bfloat16 g_wh[(size_t)DD * DD];
__device__ __nv_bfloat16 g_wl[(size_t)DD * DD];
__device__ __nv_bfloat16 g_qh[HH * MTOK * KDIM];
__device__ __nv_bfloat16 g_ql[HH * MTOK * KDIM];
__device__ __nv_bfloat16 g_kh[HH * MTOK * KDIM];
__device__ __nv_bfloat16 g_kl[HH * MTOK * KDIM];
__device__ __nv_bfloat16 g_vh[HH * MTOK * VDIM];
__device__ __nv_bfloat16 g_vl[HH * MTOK * VDIM];

// ================= low-level helpers (sm_80+ base-target PTX only) =================
__device__ __forceinline__ uint32_t smem_to_u32(const void* p) {
    uint32_t a;
    asm("{ .reg .u64 t; cvta.to.shared.u64 t, %1; cvt.u32.u64 %0, t; }"
        : "=r"(a) : "l"(p));
    return a;
}
__device__ __forceinline__ void cp_async16(uint32_t dst, const void* src) {
    asm volatile("cp.async.cg.shared.global [%0], [%1], 16;"
                 :: "r"(dst), "l"(src) : "memory");
}
#define CP_COMMIT() asm volatile("cp.async.commit_group;" ::: "memory")
#define CP_WAIT(n)  asm volatile("cp.async.wait_group %0;" :: "n"(n) : "memory")

__device__ __forceinline__ void ldmatrix_x4(uint32_t& r0, uint32_t& r1,
                                            uint32_t& r2, uint32_t& r3, uint32_t addr) {
    asm volatile("ldmatrix.sync.aligned.m8n8.x4.shared.b16 {%0,%1,%2,%3}, [%4];"
                 : "=r"(r0), "=r"(r1), "=r"(r2), "=r"(r3) : "r"(addr));
}
__device__ __forceinline__ void ldmatrix_x4_trans(uint32_t& r0, uint32_t& r1,
                                                  uint32_t& r2, uint32_t& r3, uint32_t addr) {
    asm volatile("ldmatrix.sync.aligned.m8n8.x4.trans.shared.b16 {%0,%1,%2,%3}, [%4];"
                 : "=r"(r0), "=r"(r1), "=r"(r2), "=r"(r3) : "r"(addr));
}
__device__ __forceinline__ void mma_bf16(float* d, const uint32_t* a, const uint32_t* b) {
    asm volatile(
        "mma.sync.aligned.m16n8k16.row.col.f32.bf16.bf16.f32 "
        "{%0,%1,%2,%3}, {%4,%5,%6,%7}, {%8,%9}, {%0,%1,%2,%3};"
        : "+f"(d[0]), "+f"(d[1]), "+f"(d[2]), "+f"(d[3])
        : "r"(a[0]), "r"(a[1]), "r"(a[2]), "r"(a[3]), "r"(b[0]), "r"(b[1]));
}
__device__ __forceinline__ uint32_t pack_bf16x2(__nv_bfloat16 a, __nv_bfloat16 b) {
    return (uint32_t)__bfloat16_as_ushort(a) | ((uint32_t)__bfloat16_as_ushort(b) << 16);
}

// ================= split-bf16 tensor-core GEMM (HMMA path) =================
// C[M,N] = (Ah+Al)[M,K] @ (Bh+Bl)[N,K]^T (+bias)(+res)(relu).
// OSPLIT: write result as bf16 hi/lo pair instead of fp32.
// CTA tile 256 x 128, BK=64 (128B rows, XOR-8-group swizzle). 8 warps 4(M)x2(N),
// warp tile 64 x 64. B fragments streamed in halves to cap register pressure.
template<bool BIAS, bool RELU, bool RES, bool OSPLIT>
__global__ __launch_bounds__(256, 1) void mma_gemm(
    const __nv_bfloat16* __restrict__ Ah, const __nv_bfloat16* __restrict__ Al,
    const __nv_bfloat16* __restrict__ Bh, const __nv_bfloat16* __restrict__ Bl,
    const float* __restrict__ bias, const float* __restrict__ res,
    float* __restrict__ C, __nv_bfloat16* __restrict__ Ch,
    __nv_bfloat16* __restrict__ Cl, int M, int N, int K)
{
    constexpr int BM = 256, BN = 128, BK = 64;
    constexpr int ASZ = BM * 128;               // 32768 bytes per matrix per stage
    constexpr int BSZ = BN * 128;               // 16384
    constexpr int STAGE = 2 * ASZ + 2 * BSZ;    // 98304

    extern __shared__ char smem[];
    const uint32_t sb = smem_to_u32(smem);

    const int m0 = blockIdx.y * BM;
    const int n0 = blockIdx.x * BN;
    const int tid = threadIdx.x;
    const int lane = tid & 31;
    const int wid = tid >> 5;
    const int wm = wid >> 1;                    // 0..3, 64 rows each
    const int wn = wid & 1;                     // 0..1, 64 cols each

    auto load_stage = [&](int kc, int s) {
        const uint32_t st = sb + s * STAGE;
        const int koff = kc * BK;
#pragma unroll
        for (int i = 0; i < 8; i++) {           // A: 256 rows x 8 groups of 16B
            const int idx = tid + i * 256;
            const int row = idx >> 3, g = idx & 7;
            const uint32_t d = st + row * 128 + ((g ^ (row & 7)) << 4);
            const size_t src = (size_t)(m0 + row) * K + koff + g * 8;
            cp_async16(d,        Ah + src);
            cp_async16(d + ASZ,  Al + src);
        }
#pragma unroll
        for (int i = 0; i < 4; i++) {           // B: 128 rows x 8 groups
            const int idx = tid + i * 256;
            const int row = idx >> 3, g = idx & 7;
            const uint32_t d = st + 2 * ASZ + row * 128 + ((g ^ (row & 7)) << 4);
            const size_t src = (size_t)(n0 + row) * K + koff + g * 8;
            cp_async16(d,        Bh + src);
            cp_async16(d + BSZ,  Bl + src);
        }
    };

    float acc[4][8][4];
#pragma unroll
    for (int i = 0; i < 4; i++)
#pragma unroll
        for (int j = 0; j < 8; j++)
#pragma unroll
            for (int c = 0; c < 4; c++) acc[i][j][c] = 0.f;

    const int KC = K / BK;
    load_stage(0, 0);
    CP_COMMIT();

    for (int kc = 0; kc < KC; kc++) {
        CP_WAIT(0);
        __syncthreads();                         // stage kc ready; prev buffer free
        if (kc + 1 < KC) {
            load_stage(kc + 1, (kc + 1) & 1);    // overlaps with compute below
            CP_COMMIT();
        }
        const uint32_t st = sb + (kc & 1) * STAGE;
#pragma unroll
        for (int ks = 0; ks < 4; ks++) {         // 4 x K=16 per chunk
            uint32_t afh[4][4], afl[4][4];
#pragma unroll
            for (int mf = 0; mf < 4; mf++) {
                const int row = wm * 64 + mf * 16 + (lane & 15);
                const int g = (ks * 2 + (lane >> 4)) ^ (row & 7);
                const uint32_t addr = st + row * 128 + (g << 4);
                ldmatrix_x4(afh[mf][0], afh[mf][1], afh[mf][2], afh[mf][3], addr);
                ldmatrix_x4(afl[mf][0], afl[mf][1], afl[mf][2], afl[mf][3], addr + ASZ);
            }
#pragma unroll
            for (int half = 0; half < 2; half++) {   // stream B in 32-col halves
                uint32_t bfh[4][2], bfl[4][2];
#pragma unroll
                for (int nq = 0; nq < 2; nq++) {
                    const int row = wn * 64 + half * 32 + nq * 16 + (lane & 15);
                    const int g = (ks * 2 + (lane >> 4)) ^ (row & 7);
                    const uint32_t addr = st + 2 * ASZ + row * 128 + (g << 4);
                    uint32_t r0, r1, r2, r3;
                    ldmatrix_x4(r0, r1, r2, r3, addr);
                    bfh[2 * nq][0] = r0; bfh[2 * nq][1] = r2;
                    bfh[2 * nq + 1][0] = r1; bfh[2 * nq + 1][1] = r3;
                    ldmatrix_x4(r0, r1, r2, r3, addr + BSZ);
                    bfl[2 * nq][0] = r0; bfl[2 * nq][1] = r2;
                    bfl[2 * nq + 1][0] = r1; bfl[2 * nq + 1][1] = r3;
                }
#pragma unroll
                for (int mf = 0; mf < 4; mf++)
#pragma unroll
                    for (int nf = 0; nf < 4; nf++) {
                        float* a = acc[mf][half * 4 + nf];
                        mma_bf16(a, afh[mf], bfh[nf]);
                        mma_bf16(a, afh[mf], bfl[nf]);
                        mma_bf16(a, afl[mf], bfh[nf]);
                    }
            }
        }
        __syncthreads();                         // done reading stage kc
    }

    // ---- epilogue ----
#pragma unroll
    for (int mf = 0; mf < 4; mf++) {
        const int r0i = m0 + wm * 64 + mf * 16 + (lane >> 2);
#pragma unroll
        for (int nf = 0; nf < 8; nf++) {
            const int col = n0 + wn * 64 + nf * 8 + (lane & 3) * 2;
            float2 bv = make_float2(0.f, 0.f);
            if (BIAS) { bv.x = bias[col]; bv.y = bias[col + 1]; }
#pragma unroll
            for (int hrow = 0; hrow < 2; hrow++) {
                const int rr = r0i + hrow * 8;
                float2 v;
                v.x = acc[mf][nf][2 * hrow + 0] + bv.x;
                v.y = acc[mf][nf][2 * hrow + 1] + bv.y;
                if (RES) {
                    const float2 rv = *(const float2*)(res + (size_t)rr * N + col);
                    v.x += rv.x; v.y += rv.y;
                }
                if (RELU) { v.x = fmaxf(v.x, 0.f); v.y = fmaxf(v.y, 0.f); }
                if (OSPLIT) {
                    const __nv_bfloat16 h0 = __float2bfloat16(v.x);
                    const __nv_bfloat16 h1 = __float2bfloat16(v.y);
                    const __nv_bfloat16 l0 = __float2bfloat16(v.x - __bfloat162float(h0));
                    const __nv_bfloat16 l1 = __float2bfloat16(v.y - __bfloat162float(h1));
                    *(uint32_t*)(Ch + (size_t)rr * N + col) = pack_bf16x2(h0, h1);
                    *(uint32_t*)(Cl + (size_t)rr * N + col) = pack_bf16x2(l0, l1);
                } else {
                    *(float2*)(C + (size_t)rr * N + col) = v;
                }
            }
        }
    }
}

// ================= flash attention (causal, faithful ==0 mask) =================
// grid (qt=8, hb=64); block 256 = 8 warps, warp w owns rows [16w,16w+16).
// q/k/v split bf16 [hb][S][64]; output split bf16 in concat layout [token][EE].
__global__ __launch_bounds__(256, 1) void flash_kernel(
    const __nv_bfloat16* __restrict__ qh, const __nv_bfloat16* __restrict__ ql,
    const __nv_bfloat16* __restrict__ kh, const __nv_bfloat16* __restrict__ kl,
    const __nv_bfloat16* __restrict__ vh, const __nv_bfloat16* __restrict__ vl,
    __nv_bfloat16* __restrict__ oh, __nv_bfloat16* __restrict__ ol)
{
    extern __shared__ char smem[];
    const uint32_t sb = smem_to_u32(smem);
    const int qt = blockIdx.x;
    const int hb = blockIdx.y;
    const int tid = threadIdx.x, lane = tid & 31, w = tid >> 5;

    const size_t hbase = (size_t)hb * SS * 64;
    const __nv_bfloat16* Qh = qh + hbase + (size_t)qt * 128 * 64;
    const __nv_bfloat16* Ql = ql + hbase + (size_t)qt * 128 * 64;
    const __nv_bfloat16* Kh = kh + hbase;
    const __nv_bfloat16* Kl = kl + hbase;
    const __nv_bfloat16* Vh = vh + hbase;
    const __nv_bfloat16* Vl = vl + hbase;

    // SMEM: [0,16K) Qh, [16K,32K) Ql; stage s at 32768+s*65536: Kh|Kl|Vh|Vl 16K each
#pragma unroll
    for (int i = 0; i < 4; i++) {
        const int idx = tid + i * 256;
        const int row = idx >> 3, g = idx & 7;
        const uint32_t off = row * 128 + ((g ^ (row & 7)) << 4);
        const size_t src = (size_t)row * 64 + g * 8;
        cp_async16(sb + off,         Qh + src);
        cp_async16(sb + 16384 + off, Ql + src);
    }
    auto load_kv = [&](int jt, int s) {
        const uint32_t st = sb + 32768 + s * 65536;
        const size_t base = (size_t)jt * 128 * 64;
#pragma unroll
        for (int i = 0; i < 4; i++) {
            const int idx = tid + i * 256;
            const int row = idx >> 3, g = idx & 7;
            const uint32_t off = row * 128 + ((g ^ (row & 7)) << 4);
            const size_t src = base + (size_t)row * 64 + g * 8;
            cp_async16(st + off,         Kh + src);
            cp_async16(st + 16384 + off, Kl + src);
            cp_async16(st + 32768 + off, Vh + src);
            cp_async16(st + 49152 + off, Vl + src);
        }
    };
    load_kv(0, 0);
    CP_COMMIT();

    uint32_t qfh[4][4], qfl[4][4];
    float ofr[8][4];
    float mrow[2] = {-INFINITY, -INFINITY};
    float lrow[2] = {0.f, 0.f};
#pragma unroll
    for (int f = 0; f < 8; f++)
#pragma unroll
        for (int c = 0; c < 4; c++) ofr[f][c] = 0.f;

    const int rb = qt * 128 + w * 16 + (lane >> 2);

    for (int jt = 0; jt <= qt; jt++) {
        if (jt < qt) { load_kv(jt + 1, (jt + 1) & 1); CP_COMMIT(); CP_WAIT(1); }
        else CP_WAIT(0);
        __syncthreads();

        if (jt == 0) {
#pragma unroll
            for (int kk = 0; kk < 4; kk++) {
                const int row = w * 16 + (lane & 15);
                const uint32_t c = (uint32_t)((kk * 2 + (lane >> 4)) ^ (row & 7));
                const uint32_t addr = sb + row * 128 + (c << 4);
                ldmatrix_x4(qfh[kk][0], qfh[kk][1], qfh[kk][2], qfh[kk][3], addr);
                ldmatrix_x4(qfl[kk][0], qfl[kk][1], qfl[kk][2], qfl[kk][3], addr + 16384);
            }
        }

        const uint32_t st = sb + 32768 + (jt & 1) * 65536;

        // ---- S = Q K^T (split: hh + hl + lh) ----
        float cfr[16][4];
#pragma unroll
        for (int f = 0; f < 16; f++)
#pragma unroll
            for (int c = 0; c < 4; c++) cfr[f][c] = 0.f;

#pragma unroll
        for (int kk = 0; kk < 4; kk++) {
#pragma unroll
            for (int nq = 0; nq < 8; nq++) {
                const int row = nq * 16 + (lane & 15);
                const uint32_t c = (uint32_t)((kk * 2 + (lane >> 4)) ^ (row & 7));
                const uint32_t addr = st + row * 128 + (c << 4);
                uint32_t r0, r1, r2, r3, s0, s1, s2, s3;
                ldmatrix_x4(r0, r1, r2, r3, addr);
                ldmatrix_x4(s0, s1, s2, s3, addr + 16384);
                uint32_t bh0[2] = {r0, r2}, bh1[2] = {r1, r3};
                uint32_t bl0[2] = {s0, s2}, bl1[2] = {s1, s3};
                mma_bf16(cfr[2 * nq],     qfh[kk], bh0);
                mma_bf16(cfr[2 * nq],     qfh[kk], bl0);
                mma_bf16(cfr[2 * nq],     qfl[kk], bh0);
                mma_bf16(cfr[2 * nq + 1], qfh[kk], bh1);
                mma_bf16(cfr[2 * nq + 1], qfh[kk], bl1);
                mma_bf16(cfr[2 * nq + 1], qfl[kk], bh1);
            }
        }

        // ---- mask + scale + row max ----
        float tm[2] = {-INFINITY, -INFINITY};
#pragma unroll
        for (int f = 0; f < 16; f++) {
            const int col = jt * 128 + f * 8 + (lane & 3) * 2;
#pragma unroll
            for (int h2 = 0; h2 < 2; h2++) {
                const int rg = rb + h2 * 8;
                float v0 = cfr[f][2 * h2], v1 = cfr[f][2 * h2 + 1];
                v0 = (v0 == 0.f || col > rg)     ? -INFINITY : v0 * 0.125f;
                v1 = (v1 == 0.f || col + 1 > rg) ? -INFINITY : v1 * 0.125f;
                cfr[f][2 * h2] = v0; cfr[f][2 * h2 + 1] = v1;
                tm[h2] = fmaxf(tm[h2], fmaxf(v0, v1));
            }
        }
#pragma unroll
        for (int h2 = 0; h2 < 2; h2++) {
            tm[h2] = fmaxf(tm[h2], __shfl_xor_sync(0xffffffffu, tm[h2], 1));
            tm[h2] = fmaxf(tm[h2], __shfl_xor_sync(0xffffffffu, tm[h2], 2));
            const float mn = fmaxf(mrow[h2], tm[h2]);
            const float alpha = __expf(mrow[h2] - mn);
            mrow[h2] = mn;
            lrow[h2] *= alpha;
#pragma unroll
            for (int f = 0; f < 8; f++) {
                ofr[f][2 * h2]     *= alpha;
                ofr[f][2 * h2 + 1] *= alpha;
            }
        }
        // ---- exponentiate + row sum ----
        float rs[2] = {0.f, 0.f};
#pragma unroll
        for (int f = 0; f < 16; f++) {
#pragma unroll
            for (int h2 = 0; h2 < 2; h2++) {
                const float p0 = __expf(cfr[f][2 * h2]     - mrow[h2]);
                const float p1 = __expf(cfr[f][2 * h2 + 1] - mrow[h2]);
                cfr[f][2 * h2] = p0; cfr[f][2 * h2 + 1] = p1;
                rs[h2] += p0 + p1;
            }
        }
#pragma unroll
        for (int h2 = 0; h2 < 2; h2++) {
            rs[h2] += __shfl_xor_sync(0xffffffffu, rs[h2], 1);
            rs[h2] += __shfl_xor_sync(0xffffffffu, rs[h2], 2);
            lrow[h2] += rs[h2];
        }

        // ---- O += P V (P split in registers; V split from SMEM via trans) ----
#pragma unroll
        for (int kk2 = 0; kk2 < 8; kk2++) {
            uint32_t pah[4], pal[4];
#pragma unroll
            for (int r = 0; r < 4; r++) {
                const int f = 2 * kk2 + (r >> 1);
                const int c0 = (r & 1) * 2;
                const float f0 = cfr[f][c0], f1 = cfr[f][c0 + 1];
                const __nv_bfloat16 h0 = __float2bfloat16(f0);
                const __nv_bfloat16 h1 = __float2bfloat16(f1);
                const __nv_bfloat16 l0 = __float2bfloat16(f0 - __bfloat162float(h0));
                const __nv_bfloat16 l1 = __float2bfloat16(f1 - __bfloat162float(h1));
                pah[r] = pack_bf16x2(h0, h1);
                pal[r] = pack_bf16x2(l0, l1);
            }
#pragma unroll
            for (int of2 = 0; of2 < 4; of2++) {
                const int row = kk2 * 16 + (lane & 15);
                const uint32_t c = (uint32_t)((of2 * 2 + (lane >> 4)) ^ (row & 7));
                const uint32_t addr = st + 32768 + row * 128 + (c << 4);
                uint32_t d0, d1, d2, d3, e0, e1, e2, e3;
                ldmatrix_x4_trans(d0, d1, d2, d3, addr);
                ldmatrix_x4_trans(e0, e1, e2, e3, addr + 16384);
                uint32_t v0h[2] = {d0, d1}, v1h[2] = {d2, d3};
                uint32_t v0l[2] = {e0, e1}, v1l[2] = {e2, e3};
                mma_bf16(ofr[2 * of2],     pah, v0h);
                mma_bf16(ofr[2 * of2],     pah, v0l);
                mma_bf16(ofr[2 * of2],     pal, v0h);
                mma_bf16(ofr[2 * of2 + 1], pah, v1h);
                mma_bf16(ofr[2 * of2 + 1], pah, v1l);
                mma_bf16(ofr[2 * of2 + 1], pal, v1h);
            }
        }
        __syncthreads();
    }

    // ---- finalize: O /= l, write split bf16 in concat layout ----
    const float inv0 = 1.f / lrow[0], inv1 = 1.f / lrow[1];
    const int hI = hb >> 2, bI = hb & 3;
    const int s0 = qt * 128 + w * 16 + (lane >> 2);
#pragma unroll
    for (int f = 0; f < 8; f++) {
        const int col = hI * 64 + f * 8 + (lane & 3) * 2;
#pragma unroll
        for (int h2 = 0; h2 < 2; h2++) {
            const int token = bI * SS + s0 + h2 * 8;
            const float inv = h2 ? inv1 : inv0;
            const float a = ofr[f][2 * h2] * inv;
            const float b = ofr[f][2 * h2 + 1] * inv;
            const __nv_bfloat16 h0 = __float2bfloat16(a);
            const __nv_bfloat16 h1 = __float2bfloat16(b);
            const __nv_bfloat16 l0 = __float2bfloat16(a - __bfloat162float(h0));
            const __nv_bfloat16 l1 = __float2bfloat16(b - __bfloat162float(h1));
            *(uint32_t*)(oh + (size_t)token * EE + col) = pack_bf16x2(h0, h1);
            *(uint32_t*)(ol + (size_t)token * EE + col) = pack_bf16x2(l0, l1);
        }
    }
}

// ================= fused LayerNorm -> split bf16 =================
__global__ __launch_bounds__(256) void ln_split_kernel(
    const float* __restrict__ x, const float* __restrict__ g,
    const float* __restrict__ b, __nv_bfloat16* __restrict__ hi,
    __nv_bfloat16* __restrict__ lo)
{
    __shared__ float row[EE];
    __shared__ float red[256];
    const int r = blockIdx.x;
    const int t = threadIdx.x;
    const float* xr = x + (size_t)r * EE;

    float s = 0.f;
    for (int i = t; i < EE; i += 256) { float v = xr[i]; row[i] = v; s += v; }
    red[t] = s; __syncthreads();
    for (int o = 128; o > 0; o >>= 1) { if (t < o) red[t] += red[t + o]; __syncthreads(); }
    const float mean = red[0] * (1.0f / EE);
    __syncthreads();

    float vs = 0.f;
    for (int i = t; i < EE; i += 256) { float d = row[i] - mean; vs += d * d; }
    red[t] = vs; __syncthreads();
    for (int o = 128; o > 0; o >>= 1) { if (t < o) red[t] += red[t + o]; __syncthreads(); }
    const float rstd = rsqrtf(red[0] * (1.0f / EE) + LNEPS);

    __nv_bfloat16* hrow = hi + (size_t)r * EE;
    __nv_bfloat16* lrow = lo + (size_t)r * EE;
    for (int i = t; i < EE; i += 256) {
        const float v = (row[i] - mean) * rstd * g[i] + b[i];
        const __nv_bfloat16 h = __float2bfloat16(v);
        hrow[i] = h;
        lrow[i] = __float2bfloat16(v - __bfloat162float(h));
    }
}

// fp32 W[R,C] -> bf16 split transpose Th/Tl[C,R]; batched over z with strides.
// 64x64 tiles, float4 loads, paired-uint32 bf16 stores.
__global__ __launch_bounds__(256) void trsplit_kernel(
    const float* __restrict__ W, __nv_bfloat16* __restrict__ Th,
    __nv_bfloat16* __restrict__ Tl, int R, int C, long long sIn, long long sOut)
{
    __shared__ float t[64][65];
    const int z = blockIdx.z;
    W  += (long long)z * sIn;
    Th += (long long)z * sOut;
    Tl += (long long)z * sOut;
    const int r0 = blockIdx.y * 64, c0 = blockIdx.x * 64;
    const int tid = threadIdx.x;
    const int rr = tid >> 2;                    // 0..63
    const int f0 = tid & 3;

    // load 64x64 fp32 via float4 (each thread: 4 float4 = 16 floats)
#pragma unroll
    for (int it = 0; it < 4; it++) {
        const int f = f0 + it * 4;              // float4 col group 0..15
        const float4 v = *(const float4*)(W + (long long)(r0 + rr) * C + c0 + f * 4);
        t[rr][f * 4 + 0] = v.x;
        t[rr][f * 4 + 1] = v.y;
        t[rr][f * 4 + 2] = v.z;
        t[rr][f * 4 + 3] = v.w;
    }
    __syncthreads();

    // write transposed: out row c (0..63), 32 uint32 pairs over r
    const int c = tid >> 2;                     // 0..63
#pragma unroll
    for (int it = 0; it < 8; it++) {
        const int p = (tid & 3) + it * 4;       // r-pair index 0..31
        const float v0 = t[2 * p][c];
        const float v1 = t[2 * p + 1][c];
        const __nv_bfloat16 h0 = __float2bfloat16(v0);
        const __nv_bfloat16 h1 = __float2bfloat16(v1);
        const __nv_bfloat16 l0 = __float2bfloat16(v0 - __bfloat162float(h0));
        const __nv_bfloat16 l1 = __float2bfloat16(v1 - __bfloat162float(h1));
        const long long o = (long long)(c0 + c) * R + r0 + 2 * p;
        *(uint32_t*)(Th + o) = pack_bf16x2(h0, h1);
        *(uint32_t*)(Tl + o) = pack_bf16x2(l0, l1);
    }
}

// split QKV GEMM output [t][3072] -> q/k/v [hb][s][64] (hb = h*BB + b, t = b*SS + s)
__global__ __launch_bounds__(256) void qkv_reorder_bf(
    const __nv_bfloat16* __restrict__ sh, const __nv_bfloat16* __restrict__ sl,
    __nv_bfloat16* __restrict__ qh, __nv_bfloat16* __restrict__ ql,
    __nv_bfloat16* __restrict__ kh, __nv_bfloat16* __restrict__ kl,
    __nv_bfloat16* __restrict__ vh, __nv_bfloat16* __restrict__ vl)
{
    const int idx = blockIdx.x * 256 + threadIdx.x;
    const int kd = idx & 63;
    const int t  = (idx >> 6) & (MTOK - 1);
    const int h  = idx >> 18;
    const size_t src = (size_t)t * 3072 + h * 64 + kd;
    qh[idx] = sh[src];          ql[idx] = sl[src];
    kh[idx] = sh[src + 1024];   kl[idx] = sl[src + 1024];
    vh[idx] = sh[src + 2048];   vl[idx] = sl[src + 2048];
}

// ================= launcher =================
extern "C" void kernel_launch(void* const* d_in, const int* in_sizes, int n_in,
                              void* d_out, int out_size)
{
    (void)in_sizes; (void)n_in; (void)out_size;
    const float* x      = (const float*)d_in[0];
    const float* ln1_g  = (const float*)d_in[1];
    const float* ln1_b  = (const float*)d_in[2];
    const float* Wq     = (const float*)d_in[3];
    const float* Wk     = (const float*)d_in[4];
    const float* Wv     = (const float*)d_in[5];
    const float* proj_W = (const float*)d_in[6];
    const float* proj_b = (const float*)d_in[7];
    const float* ln2_g  = (const float*)d_in[8];
    const float* ln2_b  = (const float*)d_in[9];
    const float* fin_W  = (const float*)d_in[10];
    const float* fin_b  = (const float*)d_in[11];
    const float* hid_W  = (const float*)d_in[12];
    const float* hid_b  = (const float*)d_in[13];
    const float* fout_W = (const float*)d_in[14];
    const float* fout_b = (const float*)d_in[15];
    float* out = (float*)d_out;

    float *x1;
    __nv_bfloat16 *sah, *sal, *sbh, *sbl, *wh, *wl, *qh, *ql, *kh, *kl, *vh, *vl;
    cudaGetSymbolAddress((void**)&x1,  g_x1);
    cudaGetSymbolAddress((void**)&sah, g_sah);
    cudaGetSymbolAddress((void**)&sal, g_sal);
    cudaGetSymbolAddress((void**)&sbh, g_sbh);
    cudaGetSymbolAddress((void**)&sbl, g_sbl);
    cudaGetSymbolAddress((void**)&wh,  g_wh);
    cudaGetSymbolAddress((void**)&wl,  g_wl);
    cudaGetSymbolAddress((void**)&qh,  g_qh);
    cudaGetSymbolAddress((void**)&ql,  g_ql);
    cudaGetSymbolAddress((void**)&kh,  g_kh);
    cudaGetSymbolAddress((void**)&kl,  g_kl);
    cudaGetSymbolAddress((void**)&vh,  g_vh);
    cudaGetSymbolAddress((void**)&vl,  g_vl);

    constexpr int SMG = 196608;    // gemm: 2 stages x 96KB
    constexpr int SMF = 163840;    // flash: Q 32K + 2 x 64K
    cudaFuncSetAttribute((const void*)mma_gemm<false, false, false, true>,
                         cudaFuncAttributeMaxDynamicSharedMemorySize, SMG);
    cudaFuncSetAttribute((const void*)mma_gemm<true, false, true, false>,
                         cudaFuncAttributeMaxDynamicSharedMemorySize, SMG);
    cudaFuncSetAttribute((const void*)mma_gemm<true, true, false, true>,
                         cudaFuncAttributeMaxDynamicSharedMemorySize, SMG);
    cudaFuncSetAttribute((const void*)flash_kernel,
                         cudaFuncAttributeMaxDynamicSharedMemorySize, SMF);

    // ---------- attention ----------
    ln_split_kernel<<<MTOK, 256>>>(x, ln1_g, ln1_b, sah, sal);
    {
        dim3 g(KDIM / 64, EE / 64, HH);
        trsplit_kernel<<<g, 256>>>(Wq, wh, wl, EE, KDIM,
                                   (long long)EE * KDIM, (long long)KDIM * EE);
        trsplit_kernel<<<g, 256>>>(Wk, wh + (size_t)1024 * EE, wl + (size_t)1024 * EE,
                                   EE, KDIM, (long long)EE * KDIM, (long long)KDIM * EE);
        trsplit_kernel<<<g, 256>>>(Wv, wh + (size_t)2048 * EE, wl + (size_t)2048 * EE,
                                   EE, KDIM, (long long)EE * KDIM, (long long)KDIM * EE);
    }
    // QKV: [4096,1024] @ [3072,1024]^T -> split bf16 [t][3072]
    mma_gemm<false, false, false, true><<<dim3(3072 / 128, MTOK / 256), 256, SMG>>>(
        sah, sal, wh, wl, nullptr, nullptr, nullptr, sbh, sbl, MTOK, 3072, EE);
    qkv_reorder_bf<<<HH * MTOK * KDIM / 256, 256>>>(sbh, sbl, qh, ql, kh, kl, vh, vl);

    // fused causal attention -> split output in concat layout (sa buffers)
    flash_kernel<<<dim3(SS / 128, HH * BB), 256, SMF>>>(
        qh, ql, kh, kl, vh, vl, sah, sal);

    // x1 = x + o @ proj_W + proj_b
    trsplit_kernel<<<dim3(EE / 64, EE / 64, 1), 256>>>(proj_W, wh, wl, EE, EE, 0LL, 0LL);
    mma_gemm<true, false, true, false><<<dim3(EE / 128, MTOK / 256), 256, SMG>>>(
        sah, sal, wh, wl, proj_b, x, x1, nullptr, nullptr, MTOK, EE, EE);

    // ---------- FFN (split bf16 chain) ----------
    ln_split_kernel<<<MTOK, 256>>>(x1, ln2_g, ln2_b, sah, sal);

    trsplit_kernel<<<dim3(DD / 64, EE / 64, 1), 256>>>(fin_W, wh, wl, EE, DD, 0LL, 0LL);
    mma_gemm<true, true, false, true><<<dim3(DD / 128, MTOK / 256), 256, SMG>>>(
        sah, sal, wh, wl, fin_b, nullptr, nullptr, sbh, sbl, MTOK, DD, EE);

    trsplit_kernel<<<dim3(DD / 64, DD / 64, 1), 256>>>(hid_W, wh, wl, DD, DD, 0LL, 0LL);
    mma_gemm<true, true, false, true><<<dim3(DD / 128, MTOK / 256), 256, SMG>>>(
        sbh, sbl, wh, wl, hid_b, nullptr, nullptr, sah, sal, MTOK, DD, DD);

    trsplit_kernel<<<dim3(DD / 64, DD / 64, 1), 256>>>(
        hid_W + (size_t)DD * DD, wh, wl, DD, DD, 0LL, 0LL);
    mma_gemm<true, true, false, true><<<dim3(DD / 128, MTOK / 256), 256, SMG>>>(
        sah, sal, wh, wl, hid_b + DD, nullptr, nullptr, sbh, sbl, MTOK, DD, DD);

    trsplit_kernel<<<dim3(EE / 64, DD / 64, 1), 256>>>(fout_W, wh, wl, DD, EE, 0LL, 0LL);
    mma_gemm<true, false, true, false><<<dim3(EE / 128, MTOK / 256), 256, SMG>>>(
        sbh, sbl, wh, wl, fout_b, x1, out, nullptr, nullptr, MTOK, EE, DD);
}

// round 11
// speedup vs baseline: 1.2371x; 1.2371x over previous
#include <cuda_runtime.h>
#include <cuda_bf16.h>
#include <math.h>
#include <stdint.h>
#include <string.h>

// ---------------- problem constants ----------------
#define BB   4
#define SS   1024
#define EE   1024
#define HH   16
#define KDIM 64
#define VDIM 64
#define DD   4096
#define MTOK 4096            // B*S tokens
#define LNEPS 1e-5f

// ---------------- device scratch (static globals; no allocations) ----------------
__device__ float g_x1[MTOK * EE];
__device__ __nv_bfloat16 g_sah[(size_t)MTOK * DD];
__device__ __nv_bfloat16 g_sal[(size_t)MTOK * DD];
__device__ __nv_bfloat16 g_sbh[(size_t)MTOK * DD];
__device__ __nv_bfloat16 g_sbl[(size_t)MTOK * DD];
__device__ __nv_bfloat16 g_wh[(size_t)DD * DD];
__device__ __nv_bfloat16 g_wl[(size_t)DD * DD];
__device__ __nv_bfloat16 g_qh[HH * MTOK * KDIM];
__device__ __nv_bfloat16 g_ql[HH * MTOK * KDIM];
__device__ __nv_bfloat16 g_kh[HH * MTOK * KDIM];
__device__ __nv_bfloat16 g_kl[HH * MTOK * KDIM];
__device__ __nv_bfloat16 g_vh[HH * MTOK * VDIM];
__device__ __nv_bfloat16 g_vl[HH * MTOK * VDIM];

// ================= low-level helpers (sm_80+ base-target PTX only) =================
__device__ __forceinline__ uint32_t smem_to_u32(const void* p) {
    uint32_t a;
    asm("{ .reg .u64 t; cvta.to.shared.u64 t, %1; cvt.u32.u64 %0, t; }"
        : "=r"(a) : "l"(p));
    return a;
}
__device__ __forceinline__ void cp_async16(uint32_t dst, const void* src) {
    asm volatile("cp.async.cg.shared.global [%0], [%1], 16;"
                 :: "r"(dst), "l"(src) : "memory");
}
#define CP_COMMIT() asm volatile("cp.async.commit_group;" ::: "memory")
#define CP_WAIT(n)  asm volatile("cp.async.wait_group %0;" :: "n"(n) : "memory")

__device__ __forceinline__ void ldmatrix_x4(uint32_t& r0, uint32_t& r1,
                                            uint32_t& r2, uint32_t& r3, uint32_t addr) {
    asm volatile("ldmatrix.sync.aligned.m8n8.x4.shared.b16 {%0,%1,%2,%3}, [%4];"
                 : "=r"(r0), "=r"(r1), "=r"(r2), "=r"(r3) : "r"(addr));
}
__device__ __forceinline__ void ldmatrix_x4_trans(uint32_t& r0, uint32_t& r1,
                                                  uint32_t& r2, uint32_t& r3, uint32_t addr) {
    asm volatile("ldmatrix.sync.aligned.m8n8.x4.trans.shared.b16 {%0,%1,%2,%3}, [%4];"
                 : "=r"(r0), "=r"(r1), "=r"(r2), "=r"(r3) : "r"(addr));
}
__device__ __forceinline__ void mma_bf16(float* d, const uint32_t* a, const uint32_t* b) {
    asm volatile(
        "mma.sync.aligned.m16n8k16.row.col.f32.bf16.bf16.f32 "
        "{%0,%1,%2,%3}, {%4,%5,%6,%7}, {%8,%9}, {%0,%1,%2,%3};"
        : "+f"(d[0]), "+f"(d[1]), "+f"(d[2]), "+f"(d[3])
        : "r"(a[0]), "r"(a[1]), "r"(a[2]), "r"(a[3]), "r"(b[0]), "r"(b[1]));
}
__device__ __forceinline__ uint32_t pack_bf16x2(__nv_bfloat16 a, __nv_bfloat16 b) {
    return (uint32_t)__bfloat16_as_ushort(a) | ((uint32_t)__bfloat16_as_ushort(b) << 16);
}

// ================= split-bf16 tensor-core GEMM (HMMA path) =================
// C[M,N] = (Ah+Al)[M,K] @ (Bh+Bl)[K,N] (+bias)(+res)(relu).
// B is in NATURAL [K,N] layout (no weight transpose needed); B fragments come
// from ldmatrix.trans (same pattern as flash PV). OSPLIT: bf16 hi/lo output.
// CTA tile 128 x 128, BK=64. 8 warps 4(M) x 2(N), warp tile 32 x 64.
template<bool BIAS, bool RELU, bool RES, bool OSPLIT>
__global__ __launch_bounds__(256, 1) void mma_gemm(
    const __nv_bfloat16* __restrict__ Ah, const __nv_bfloat16* __restrict__ Al,
    const __nv_bfloat16* __restrict__ Bh, const __nv_bfloat16* __restrict__ Bl,
    const float* __restrict__ bias, const float* __restrict__ res,
    float* __restrict__ C, __nv_bfloat16* __restrict__ Ch,
    __nv_bfloat16* __restrict__ Cl, int M, int N, int K)
{
    constexpr int BM = 128, BN = 128, BK = 64;
    constexpr int NFRAG = BN / 16;              // 8 per warp (warp n-extent 64)
    constexpr int ASZ = BM * 128;               // A: 128 rows x 128B  = 16384
    constexpr int BSZ = BK * 256;               // B: 64 k-rows x 256B = 16384
    constexpr int STAGE = 2 * ASZ + 2 * BSZ;    // 65536

    extern __shared__ char smem[];
    const uint32_t sb = smem_to_u32(smem);

    const int m0 = blockIdx.y * BM;
    const int n0 = blockIdx.x * BN;
    const int tid = threadIdx.x;
    const int lane = tid & 31;
    const int wid = tid >> 5;
    const int wm = wid >> 1;
    const int wn = wid & 1;

    auto load_stage = [&](int kc, int s) {
        const uint32_t st = sb + s * STAGE;
        const int koff = kc * BK;
#pragma unroll
        for (int i = 0; i < 4; i++) {           // A: 128 rows x 8 groups of 16B
            const int idx = tid + i * 256;
            const int row = idx >> 3, g = idx & 7;
            const uint32_t d = st + row * 128 + ((g ^ (row & 7)) << 4);
            const size_t src = (size_t)(m0 + row) * K + koff + g * 8;
            cp_async16(d,        Ah + src);
            cp_async16(d + ASZ,  Al + src);
        }
#pragma unroll
        for (int i = 0; i < 4; i++) {           // B: 64 k-rows x 16 groups of 16B
            const int idx = tid + i * 256;
            const int row = idx >> 4, g = idx & 15;
            const uint32_t d = st + 2 * ASZ + row * 256 + ((g ^ (row & 7)) << 4);
            const size_t src = (size_t)(koff + row) * N + n0 + g * 8;
            cp_async16(d,        Bh + src);
            cp_async16(d + BSZ,  Bl + src);
        }
    };

    float acc[2][NFRAG][4];
#pragma unroll
    for (int i = 0; i < 2; i++)
#pragma unroll
        for (int j = 0; j < NFRAG; j++)
#pragma unroll
            for (int c = 0; c < 4; c++) acc[i][j][c] = 0.f;

    const int KC = K / BK;
    load_stage(0, 0);
    CP_COMMIT();

    for (int kc = 0; kc < KC; kc++) {
        CP_WAIT(0);
        __syncthreads();                         // stage kc ready; prev buffer free
        if (kc + 1 < KC) {
            load_stage(kc + 1, (kc + 1) & 1);    // overlaps with compute below
            CP_COMMIT();
        }
        const uint32_t st = sb + (kc & 1) * STAGE;
#pragma unroll
        for (int ks = 0; ks < 4; ks++) {         // 4 x K=16 per chunk
            uint32_t afh[2][4], afl[2][4];
#pragma unroll
            for (int mf = 0; mf < 2; mf++) {
                const int row = wm * 32 + mf * 16 + (lane & 15);
                const int g = (ks * 2 + (lane >> 4)) ^ (row & 7);
                const uint32_t addr = st + row * 128 + (g << 4);
                ldmatrix_x4(afh[mf][0], afh[mf][1], afh[mf][2], afh[mf][3], addr);
                ldmatrix_x4(afl[mf][0], afl[mf][1], afl[mf][2], afl[mf][3], addr + ASZ);
            }
            uint32_t bfh[NFRAG][2], bfl[NFRAG][2];
#pragma unroll
            for (int nq = 0; nq < NFRAG / 2; nq++) {
                // B tile [k=64][n=128]: fragment for k [ks*16,+16), n [wn*64+nq*16,+16)
                const int row = ks * 16 + (lane & 15);
                const int g = (wn * 8 + nq * 2 + (lane >> 4)) ^ (row & 7);
                const uint32_t addr = st + 2 * ASZ + row * 256 + (g << 4);
                uint32_t d0, d1, d2, d3;
                ldmatrix_x4_trans(d0, d1, d2, d3, addr);
                bfh[2 * nq][0] = d0; bfh[2 * nq][1] = d1;
                bfh[2 * nq + 1][0] = d2; bfh[2 * nq + 1][1] = d3;
                ldmatrix_x4_trans(d0, d1, d2, d3, addr + BSZ);
                bfl[2 * nq][0] = d0; bfl[2 * nq][1] = d1;
                bfl[2 * nq + 1][0] = d2; bfl[2 * nq + 1][1] = d3;
            }
#pragma unroll
            for (int mf = 0; mf < 2; mf++)
#pragma unroll
                for (int nf = 0; nf < NFRAG; nf++) {
                    mma_bf16(acc[mf][nf], afh[mf], bfh[nf]);
                    mma_bf16(acc[mf][nf], afh[mf], bfl[nf]);
                    mma_bf16(acc[mf][nf], afl[mf], bfh[nf]);
                }
        }
        __syncthreads();                         // done reading stage kc
    }

    // ---- epilogue ----
#pragma unroll
    for (int mf = 0; mf < 2; mf++) {
        const int r0i = m0 + wm * 32 + mf * 16 + (lane >> 2);
#pragma unroll
        for (int nf = 0; nf < NFRAG; nf++) {
            const int col = n0 + wn * 64 + nf * 8 + (lane & 3) * 2;
            float2 bv = make_float2(0.f, 0.f);
            if (BIAS) { bv.x = bias[col]; bv.y = bias[col + 1]; }
#pragma unroll
            for (int hrow = 0; hrow < 2; hrow++) {
                const int rr = r0i + hrow * 8;
                float2 v;
                v.x = acc[mf][nf][2 * hrow + 0] + bv.x;
                v.y = acc[mf][nf][2 * hrow + 1] + bv.y;
                if (RES) {
                    const float2 rv = *(const float2*)(res + (size_t)rr * N + col);
                    v.x += rv.x; v.y += rv.y;
                }
                if (RELU) { v.x = fmaxf(v.x, 0.f); v.y = fmaxf(v.y, 0.f); }
                if (OSPLIT) {
                    const __nv_bfloat16 h0 = __float2bfloat16(v.x);
                    const __nv_bfloat16 h1 = __float2bfloat16(v.y);
                    const __nv_bfloat16 l0 = __float2bfloat16(v.x - __bfloat162float(h0));
                    const __nv_bfloat16 l1 = __float2bfloat16(v.y - __bfloat162float(h1));
                    *(uint32_t*)(Ch + (size_t)rr * N + col) = pack_bf16x2(h0, h1);
                    *(uint32_t*)(Cl + (size_t)rr * N + col) = pack_bf16x2(l0, l1);
                } else {
                    *(float2*)(C + (size_t)rr * N + col) = v;
                }
            }
        }
    }
}

// ================= flash attention (causal, faithful ==0 mask) =================
// grid (qt=8, hb=64); block 256 = 8 warps, warp w owns rows [16w,16w+16).
// q/k/v split bf16 [hb][S][64]; output split bf16 in concat layout [token][EE].
__global__ __launch_bounds__(256, 1) void flash_kernel(
    const __nv_bfloat16* __restrict__ qh, const __nv_bfloat16* __restrict__ ql,
    const __nv_bfloat16* __restrict__ kh, const __nv_bfloat16* __restrict__ kl,
    const __nv_bfloat16* __restrict__ vh, const __nv_bfloat16* __restrict__ vl,
    __nv_bfloat16* __restrict__ oh, __nv_bfloat16* __restrict__ ol)
{
    extern __shared__ char smem[];
    const uint32_t sb = smem_to_u32(smem);
    const int qt = blockIdx.x;
    const int hb = blockIdx.y;
    const int tid = threadIdx.x, lane = tid & 31, w = tid >> 5;

    const size_t hbase = (size_t)hb * SS * 64;
    const __nv_bfloat16* Qh = qh + hbase + (size_t)qt * 128 * 64;
    const __nv_bfloat16* Ql = ql + hbase + (size_t)qt * 128 * 64;
    const __nv_bfloat16* Kh = kh + hbase;
    const __nv_bfloat16* Kl = kl + hbase;
    const __nv_bfloat16* Vh = vh + hbase;
    const __nv_bfloat16* Vl = vl + hbase;

    // SMEM: [0,16K) Qh, [16K,32K) Ql; stage s at 32768+s*65536: Kh|Kl|Vh|Vl 16K each
#pragma unroll
    for (int i = 0; i < 4; i++) {
        const int idx = tid + i * 256;
        const int row = idx >> 3, g = idx & 7;
        const uint32_t off = row * 128 + ((g ^ (row & 7)) << 4);
        const size_t src = (size_t)row * 64 + g * 8;
        cp_async16(sb + off,         Qh + src);
        cp_async16(sb + 16384 + off, Ql + src);
    }
    auto load_kv = [&](int jt, int s) {
        const uint32_t st = sb + 32768 + s * 65536;
        const size_t base = (size_t)jt * 128 * 64;
#pragma unroll
        for (int i = 0; i < 4; i++) {
            const int idx = tid + i * 256;
            const int row = idx >> 3, g = idx & 7;
            const uint32_t off = row * 128 + ((g ^ (row & 7)) << 4);
            const size_t src = base + (size_t)row * 64 + g * 8;
            cp_async16(st + off,         Kh + src);
            cp_async16(st + 16384 + off, Kl + src);
            cp_async16(st + 32768 + off, Vh + src);
            cp_async16(st + 49152 + off, Vl + src);
        }
    };
    load_kv(0, 0);
    CP_COMMIT();

    uint32_t qfh[4][4], qfl[4][4];
    float ofr[8][4];
    float mrow[2] = {-INFINITY, -INFINITY};
    float lrow[2] = {0.f, 0.f};
#pragma unroll
    for (int f = 0; f < 8; f++)
#pragma unroll
        for (int c = 0; c < 4; c++) ofr[f][c] = 0.f;

    const int rb = qt * 128 + w * 16 + (lane >> 2);

    for (int jt = 0; jt <= qt; jt++) {
        if (jt < qt) { load_kv(jt + 1, (jt + 1) & 1); CP_COMMIT(); CP_WAIT(1); }
        else CP_WAIT(0);
        __syncthreads();

        if (jt == 0) {
#pragma unroll
            for (int kk = 0; kk < 4; kk++) {
                const int row = w * 16 + (lane & 15);
                const uint32_t c = (uint32_t)((kk * 2 + (lane >> 4)) ^ (row & 7));
                const uint32_t addr = sb + row * 128 + (c << 4);
                ldmatrix_x4(qfh[kk][0], qfh[kk][1], qfh[kk][2], qfh[kk][3], addr);
                ldmatrix_x4(qfl[kk][0], qfl[kk][1], qfl[kk][2], qfl[kk][3], addr + 16384);
            }
        }

        const uint32_t st = sb + 32768 + (jt & 1) * 65536;

        // ---- S = Q K^T (split: hh + hl + lh) ----
        float cfr[16][4];
#pragma unroll
        for (int f = 0; f < 16; f++)
#pragma unroll
            for (int c = 0; c < 4; c++) cfr[f][c] = 0.f;

#pragma unroll
        for (int kk = 0; kk < 4; kk++) {
#pragma unroll
            for (int nq = 0; nq < 8; nq++) {
                const int row = nq * 16 + (lane & 15);
                const uint32_t c = (uint32_t)((kk * 2 + (lane >> 4)) ^ (row & 7));
                const uint32_t addr = st + row * 128 + (c << 4);
                uint32_t r0, r1, r2, r3, s0, s1, s2, s3;
                ldmatrix_x4(r0, r1, r2, r3, addr);
                ldmatrix_x4(s0, s1, s2, s3, addr + 16384);
                uint32_t bh0[2] = {r0, r2}, bh1[2] = {r1, r3};
                uint32_t bl0[2] = {s0, s2}, bl1[2] = {s1, s3};
                mma_bf16(cfr[2 * nq],     qfh[kk], bh0);
                mma_bf16(cfr[2 * nq],     qfh[kk], bl0);
                mma_bf16(cfr[2 * nq],     qfl[kk], bh0);
                mma_bf16(cfr[2 * nq + 1], qfh[kk], bh1);
                mma_bf16(cfr[2 * nq + 1], qfh[kk], bl1);
                mma_bf16(cfr[2 * nq + 1], qfl[kk], bh1);
            }
        }

        // ---- mask + scale + row max ----
        float tm[2] = {-INFINITY, -INFINITY};
#pragma unroll
        for (int f = 0; f < 16; f++) {
            const int col = jt * 128 + f * 8 + (lane & 3) * 2;
#pragma unroll
            for (int h2 = 0; h2 < 2; h2++) {
                const int rg = rb + h2 * 8;
                float v0 = cfr[f][2 * h2], v1 = cfr[f][2 * h2 + 1];
                v0 = (v0 == 0.f || col > rg)     ? -INFINITY : v0 * 0.125f;
                v1 = (v1 == 0.f || col + 1 > rg) ? -INFINITY : v1 * 0.125f;
                cfr[f][2 * h2] = v0; cfr[f][2 * h2 + 1] = v1;
                tm[h2] = fmaxf(tm[h2], fmaxf(v0, v1));
            }
        }
#pragma unroll
        for (int h2 = 0; h2 < 2; h2++) {
            tm[h2] = fmaxf(tm[h2], __shfl_xor_sync(0xffffffffu, tm[h2], 1));
            tm[h2] = fmaxf(tm[h2], __shfl_xor_sync(0xffffffffu, tm[h2], 2));
            const float mn = fmaxf(mrow[h2], tm[h2]);
            const float alpha = __expf(mrow[h2] - mn);
            mrow[h2] = mn;
            lrow[h2] *= alpha;
#pragma unroll
            for (int f = 0; f < 8; f++) {
                ofr[f][2 * h2]     *= alpha;
                ofr[f][2 * h2 + 1] *= alpha;
            }
        }
        // ---- exponentiate + row sum ----
        float rs[2] = {0.f, 0.f};
#pragma unroll
        for (int f = 0; f < 16; f++) {
#pragma unroll
            for (int h2 = 0; h2 < 2; h2++) {
                const float p0 = __expf(cfr[f][2 * h2]     - mrow[h2]);
                const float p1 = __expf(cfr[f][2 * h2 + 1] - mrow[h2]);
                cfr[f][2 * h2] = p0; cfr[f][2 * h2 + 1] = p1;
                rs[h2] += p0 + p1;
            }
        }
#pragma unroll
        for (int h2 = 0; h2 < 2; h2++) {
            rs[h2] += __shfl_xor_sync(0xffffffffu, rs[h2], 1);
            rs[h2] += __shfl_xor_sync(0xffffffffu, rs[h2], 2);
            lrow[h2] += rs[h2];
        }

        // ---- O += P V (P split in registers; V split from SMEM via trans) ----
#pragma unroll
        for (int kk2 = 0; kk2 < 8; kk2++) {
            uint32_t pah[4], pal[4];
#pragma unroll
            for (int r = 0; r < 4; r++) {
                const int f = 2 * kk2 + (r >> 1);
                const int c0 = (r & 1) * 2;
                const float f0 = cfr[f][c0], f1 = cfr[f][c0 + 1];
                const __nv_bfloat16 h0 = __float2bfloat16(f0);
                const __nv_bfloat16 h1 = __float2bfloat16(f1);
                const __nv_bfloat16 l0 = __float2bfloat16(f0 - __bfloat162float(h0));
                const __nv_bfloat16 l1 = __float2bfloat16(f1 - __bfloat162float(h1));
                pah[r] = pack_bf16x2(h0, h1);
                pal[r] = pack_bf16x2(l0, l1);
            }
#pragma unroll
            for (int of2 = 0; of2 < 4; of2++) {
                const int row = kk2 * 16 + (lane & 15);
                const uint32_t c = (uint32_t)((of2 * 2 + (lane >> 4)) ^ (row & 7));
                const uint32_t addr = st + 32768 + row * 128 + (c << 4);
                uint32_t d0, d1, d2, d3, e0, e1, e2, e3;
                ldmatrix_x4_trans(d0, d1, d2, d3, addr);
                ldmatrix_x4_trans(e0, e1, e2, e3, addr + 16384);
                uint32_t v0h[2] = {d0, d1}, v1h[2] = {d2, d3};
                uint32_t v0l[2] = {e0, e1}, v1l[2] = {e2, e3};
                mma_bf16(ofr[2 * of2],     pah, v0h);
                mma_bf16(ofr[2 * of2],     pah, v0l);
                mma_bf16(ofr[2 * of2],     pal, v0h);
                mma_bf16(ofr[2 * of2 + 1], pah, v1h);
                mma_bf16(ofr[2 * of2 + 1], pah, v1l);
                mma_bf16(ofr[2 * of2 + 1], pal, v1h);
            }
        }
        __syncthreads();
    }

    // ---- finalize: O /= l, write split bf16 in concat layout ----
    const float inv0 = 1.f / lrow[0], inv1 = 1.f / lrow[1];
    const int hI = hb >> 2, bI = hb & 3;
    const int s0 = qt * 128 + w * 16 + (lane >> 2);
#pragma unroll
    for (int f = 0; f < 8; f++) {
        const int col = hI * 64 + f * 8 + (lane & 3) * 2;
#pragma unroll
        for (int h2 = 0; h2 < 2; h2++) {
            const int token = bI * SS + s0 + h2 * 8;
            const float inv = h2 ? inv1 : inv0;
            const float a = ofr[f][2 * h2] * inv;
            const float b = ofr[f][2 * h2 + 1] * inv;
            const __nv_bfloat16 h0 = __float2bfloat16(a);
            const __nv_bfloat16 h1 = __float2bfloat16(b);
            const __nv_bfloat16 l0 = __float2bfloat16(a - __bfloat162float(h0));
            const __nv_bfloat16 l1 = __float2bfloat16(b - __bfloat162float(h1));
            *(uint32_t*)(oh + (size_t)token * EE + col) = pack_bf16x2(h0, h1);
            *(uint32_t*)(ol + (size_t)token * EE + col) = pack_bf16x2(l0, l1);
        }
    }
}

// ================= fused LayerNorm -> split bf16 =================
__global__ __launch_bounds__(256) void ln_split_kernel(
    const float* __restrict__ x, const float* __restrict__ g,
    const float* __restrict__ b, __nv_bfloat16* __restrict__ hi,
    __nv_bfloat16* __restrict__ lo)
{
    __shared__ float row[EE];
    __shared__ float red[256];
    const int r = blockIdx.x;
    const int t = threadIdx.x;
    const float* xr = x + (size_t)r * EE;

    float s = 0.f;
    for (int i = t; i < EE; i += 256) { float v = xr[i]; row[i] = v; s += v; }
    red[t] = s; __syncthreads();
    for (int o = 128; o > 0; o >>= 1) { if (t < o) red[t] += red[t + o]; __syncthreads(); }
    const float mean = red[0] * (1.0f / EE);
    __syncthreads();

    float vs = 0.f;
    for (int i = t; i < EE; i += 256) { float d = row[i] - mean; vs += d * d; }
    red[t] = vs; __syncthreads();
    for (int o = 128; o > 0; o >>= 1) { if (t < o) red[t] += red[t + o]; __syncthreads(); }
    const float rstd = rsqrtf(red[0] * (1.0f / EE) + LNEPS);

    __nv_bfloat16* hrow = hi + (size_t)r * EE;
    __nv_bfloat16* lrow = lo + (size_t)r * EE;
    for (int i = t; i < EE; i += 256) {
        const float v = (row[i] - mean) * rstd * g[i] + b[i];
        const __nv_bfloat16 h = __float2bfloat16(v);
        hrow[i] = h;
        lrow[i] = __float2bfloat16(v - __bfloat162float(h));
    }
}

// ================= elementwise fp32 -> split bf16 (same layout) =================
__global__ __launch_bounds__(256) void split_kernel(
    const float* __restrict__ x, __nv_bfloat16* __restrict__ hi,
    __nv_bfloat16* __restrict__ lo, int n)
{
    const int i = (blockIdx.x * 256 + threadIdx.x) * 4;
    if (i >= n) return;
    const float4 v = *(const float4*)(x + i);
    const __nv_bfloat16 h0 = __float2bfloat16(v.x);
    const __nv_bfloat16 h1 = __float2bfloat16(v.y);
    const __nv_bfloat16 h2 = __float2bfloat16(v.z);
    const __nv_bfloat16 h3 = __float2bfloat16(v.w);
    const __nv_bfloat16 l0 = __float2bfloat16(v.x - __bfloat162float(h0));
    const __nv_bfloat16 l1 = __float2bfloat16(v.y - __bfloat162float(h1));
    const __nv_bfloat16 l2 = __float2bfloat16(v.z - __bfloat162float(h2));
    const __nv_bfloat16 l3 = __float2bfloat16(v.w - __bfloat162float(h3));
    uint2* ph = (uint2*)(hi + i);
    uint2* pl = (uint2*)(lo + i);
    *ph = make_uint2(pack_bf16x2(h0, h1), pack_bf16x2(h2, h3));
    *pl = make_uint2(pack_bf16x2(l0, l1), pack_bf16x2(l2, l3));
}

// QKV weights [H][E][64] x3 -> combined [E][3072] split bf16 (n = which*1024 + h*64 + kd)
__global__ __launch_bounds__(256) void qkvw_split_kernel(
    const float* __restrict__ Wq, const float* __restrict__ Wk,
    const float* __restrict__ Wv, __nv_bfloat16* __restrict__ wh,
    __nv_bfloat16* __restrict__ wl)
{
    const int idx = blockIdx.x * 256 + threadIdx.x;   // over E*3072
    const int e = idx / 3072;
    const int c = idx % 3072;
    const float* W = (c < 1024) ? Wq : (c < 2048 ? Wk : Wv);
    const int cc = c & 1023;
    const int h = cc >> 6, kd = cc & 63;
    const float v = W[(size_t)h * EE * 64 + (size_t)e * 64 + kd];
    const __nv_bfloat16 hh = __float2bfloat16(v);
    wh[idx] = hh;
    wl[idx] = __float2bfloat16(v - __bfloat162float(hh));
}

// split QKV GEMM output [t][3072] -> q/k/v [hb][s][64] (hb = h*BB + b, t = b*SS + s)
__global__ __launch_bounds__(256) void qkv_reorder_bf(
    const __nv_bfloat16* __restrict__ sh, const __nv_bfloat16* __restrict__ sl,
    __nv_bfloat16* __restrict__ qh, __nv_bfloat16* __restrict__ ql,
    __nv_bfloat16* __restrict__ kh, __nv_bfloat16* __restrict__ kl,
    __nv_bfloat16* __restrict__ vh, __nv_bfloat16* __restrict__ vl)
{
    const int idx = blockIdx.x * 256 + threadIdx.x;
    const int kd = idx & 63;
    const int t  = (idx >> 6) & (MTOK - 1);
    const int h  = idx >> 18;
    const size_t src = (size_t)t * 3072 + h * 64 + kd;
    qh[idx] = sh[src];          ql[idx] = sl[src];
    kh[idx] = sh[src + 1024];   kl[idx] = sl[src + 1024];
    vh[idx] = sh[src + 2048];   vl[idx] = sl[src + 2048];
}

// ================= launcher =================
extern "C" void kernel_launch(void* const* d_in, const int* in_sizes, int n_in,
                              void* d_out, int out_size)
{
    (void)in_sizes; (void)n_in; (void)out_size;
    const float* x      = (const float*)d_in[0];
    const float* ln1_g  = (const float*)d_in[1];
    const float* ln1_b  = (const float*)d_in[2];
    const float* Wq     = (const float*)d_in[3];
    const float* Wk     = (const float*)d_in[4];
    const float* Wv     = (const float*)d_in[5];
    const float* proj_W = (const float*)d_in[6];
    const float* proj_b = (const float*)d_in[7];
    const float* ln2_g  = (const float*)d_in[8];
    const float* ln2_b  = (const float*)d_in[9];
    const float* fin_W  = (const float*)d_in[10];
    const float* fin_b  = (const float*)d_in[11];
    const float* hid_W  = (const float*)d_in[12];
    const float* hid_b  = (const float*)d_in[13];
    const float* fout_W = (const float*)d_in[14];
    const float* fout_b = (const float*)d_in[15];
    float* out = (float*)d_out;

    float *x1;
    __nv_bfloat16 *sah, *sal, *sbh, *sbl, *wh, *wl, *qh, *ql, *kh, *kl, *vh, *vl;
    cudaGetSymbolAddress((void**)&x1,  g_x1);
    cudaGetSymbolAddress((void**)&sah, g_sah);
    cudaGetSymbolAddress((void**)&sal, g_sal);
    cudaGetSymbolAddress((void**)&sbh, g_sbh);
    cudaGetSymbolAddress((void**)&sbl, g_sbl);
    cudaGetSymbolAddress((void**)&wh,  g_wh);
    cudaGetSymbolAddress((void**)&wl,  g_wl);
    cudaGetSymbolAddress((void**)&qh,  g_qh);
    cudaGetSymbolAddress((void**)&ql,  g_ql);
    cudaGetSymbolAddress((void**)&kh,  g_kh);
    cudaGetSymbolAddress((void**)&kl,  g_kl);
    cudaGetSymbolAddress((void**)&vh,  g_vh);
    cudaGetSymbolAddress((void**)&vl,  g_vl);

    constexpr int SMG = 131072;    // gemm: 2 stages x 64KB
    constexpr int SMF = 163840;    // flash: Q 32K + 2 x 64K
    cudaFuncSetAttribute((const void*)mma_gemm<false, false, false, true>,
                         cudaFuncAttributeMaxDynamicSharedMemorySize, SMG);
    cudaFuncSetAttribute((const void*)mma_gemm<true, false, true, false>,
                         cudaFuncAttributeMaxDynamicSharedMemorySize, SMG);
    cudaFuncSetAttribute((const void*)mma_gemm<true, true, false, true>,
                         cudaFuncAttributeMaxDynamicSharedMemorySize, SMG);
    cudaFuncSetAttribute((const void*)flash_kernel,
                         cudaFuncAttributeMaxDynamicSharedMemorySize, SMF);

    // ---------- attention ----------
    ln_split_kernel<<<MTOK, 256>>>(x, ln1_g, ln1_b, sah, sal);
    qkvw_split_kernel<<<EE * 3072 / 256, 256>>>(Wq, Wk, Wv, wh, wl);

    // QKV: [4096,1024] @ [1024,3072] -> split bf16 [t][3072]
    mma_gemm<false, false, false, true><<<dim3(3072 / 128, MTOK / 128), 256, SMG>>>(
        sah, sal, wh, wl, nullptr, nullptr, nullptr, sbh, sbl, MTOK, 3072, EE);
    qkv_reorder_bf<<<HH * MTOK * KDIM / 256, 256>>>(sbh, sbl, qh, ql, kh, kl, vh, vl);

    // fused causal attention -> split output in concat layout (sa buffers)
    flash_kernel<<<dim3(SS / 128, HH * BB), 256, SMF>>>(
        qh, ql, kh, kl, vh, vl, sah, sal);

    // x1 = x + o @ proj_W + proj_b   (proj_W already [K,N])
    split_kernel<<<EE * EE / 1024, 256>>>(proj_W, wh, wl, EE * EE);
    mma_gemm<true, false, true, false><<<dim3(EE / 128, MTOK / 128), 256, SMG>>>(
        sah, sal, wh, wl, proj_b, x, x1, nullptr, nullptr, MTOK, EE, EE);

    // ---------- FFN (split bf16 chain; weights already [K,N]) ----------
    ln_split_kernel<<<MTOK, 256>>>(x1, ln2_g, ln2_b, sah, sal);

    split_kernel<<<EE * DD / 1024, 256>>>(fin_W, wh, wl, EE * DD);
    mma_gemm<true, true, false, true><<<dim3(DD / 128, MTOK / 128), 256, SMG>>>(
        sah, sal, wh, wl, fin_b, nullptr, nullptr, sbh, sbl, MTOK, DD, EE);

    split_kernel<<<DD * DD / 1024, 256>>>(hid_W, wh, wl, DD * DD);
    mma_gemm<true, true, false, true><<<dim3(DD / 128, MTOK / 128), 256, SMG>>>(
        sbh, sbl, wh, wl, hid_b, nullptr, nullptr, sah, sal, MTOK, DD, DD);

    split_kernel<<<DD * DD / 1024, 256>>>(hid_W + (size_t)DD * DD, wh, wl, DD * DD);
    mma_gemm<true, true, false, true><<<dim3(DD / 128, MTOK / 128), 256, SMG>>>(
        sah, sal, wh, wl, hid_b + DD, nullptr, nullptr, sbh, sbl, MTOK, DD, DD);

    split_kernel<<<DD * EE / 1024, 256>>>(fout_W, wh, wl, DD * EE);
    mma_gemm<true, false, true, false><<<dim3(EE / 128, MTOK / 128), 256, SMG>>>(
        sbh, sbl, wh, wl, fout_b, x1, out, nullptr, nullptr, MTOK, EE, DD);
}

// round 12
// speedup vs baseline: 1.2714x; 1.0277x over previous
#include <cuda_runtime.h>
#include <cuda_bf16.h>
#include <math.h>
#include <stdint.h>
#include <string.h>

// ---------------- problem constants ----------------
#define BB   4
#define SS   1024
#define EE   1024
#define HH   16
#define KDIM 64
#define VDIM 64
#define DD   4096
#define MTOK 4096            // B*S tokens
#define LNEPS 1e-5f

// ---------------- device scratch (static globals; no allocations) ----------------
__device__ float g_x1[MTOK * EE];
__device__ __nv_bfloat16 g_sah[(size_t)MTOK * DD];
__device__ __nv_bfloat16 g_sal[(size_t)MTOK * DD];
__device__ __nv_bfloat16 g_sbh[(size_t)MTOK * DD];
__device__ __nv_bfloat16 g_sbl[(size_t)MTOK * DD];
__device__ __nv_bfloat16 g_wh[(size_t)DD * DD];
__device__ __nv_bfloat16 g_wl[(size_t)DD * DD];
__device__ __nv_bfloat16 g_qh[HH * MTOK * KDIM];
__device__ __nv_bfloat16 g_ql[HH * MTOK * KDIM];
__device__ __nv_bfloat16 g_kh[HH * MTOK * KDIM];
__device__ __nv_bfloat16 g_kl[HH * MTOK * KDIM];
__device__ __nv_bfloat16 g_vh[HH * MTOK * VDIM];
__device__ __nv_bfloat16 g_vl[HH * MTOK * VDIM];

// ================= low-level helpers (sm_80+ base-target PTX only) =================
__device__ __forceinline__ uint32_t smem_to_u32(const void* p) {
    uint32_t a;
    asm("{ .reg .u64 t; cvta.to.shared.u64 t, %1; cvt.u32.u64 %0, t; }"
        : "=r"(a) : "l"(p));
    return a;
}
__device__ __forceinline__ void cp_async16(uint32_t dst, const void* src) {
    asm volatile("cp.async.cg.shared.global [%0], [%1], 16;"
                 :: "r"(dst), "l"(src) : "memory");
}
#define CP_COMMIT() asm volatile("cp.async.commit_group;" ::: "memory")
#define CP_WAIT(n)  asm volatile("cp.async.wait_group %0;" :: "n"(n) : "memory")

__device__ __forceinline__ void ldmatrix_x4(uint32_t& r0, uint32_t& r1,
                                            uint32_t& r2, uint32_t& r3, uint32_t addr) {
    asm volatile("ldmatrix.sync.aligned.m8n8.x4.shared.b16 {%0,%1,%2,%3}, [%4];"
                 : "=r"(r0), "=r"(r1), "=r"(r2), "=r"(r3) : "r"(addr));
}
__device__ __forceinline__ void ldmatrix_x4_trans(uint32_t& r0, uint32_t& r1,
                                                  uint32_t& r2, uint32_t& r3, uint32_t addr) {
    asm volatile("ldmatrix.sync.aligned.m8n8.x4.trans.shared.b16 {%0,%1,%2,%3}, [%4];"
                 : "=r"(r0), "=r"(r1), "=r"(r2), "=r"(r3) : "r"(addr));
}
__device__ __forceinline__ void mma_bf16(float* d, const uint32_t* a, const uint32_t* b) {
    asm volatile(
        "mma.sync.aligned.m16n8k16.row.col.f32.bf16.bf16.f32 "
        "{%0,%1,%2,%3}, {%4,%5,%6,%7}, {%8,%9}, {%0,%1,%2,%3};"
        : "+f"(d[0]), "+f"(d[1]), "+f"(d[2]), "+f"(d[3])
        : "r"(a[0]), "r"(a[1]), "r"(a[2]), "r"(a[3]), "r"(b[0]), "r"(b[1]));
}
__device__ __forceinline__ uint32_t pack_bf16x2(__nv_bfloat16 a, __nv_bfloat16 b) {
    return (uint32_t)__bfloat16_as_ushort(a) | ((uint32_t)__bfloat16_as_ushort(b) << 16);
}

// ================= split-bf16 tensor-core GEMM (HMMA path) =================
// C[M,N] = (Ah+Al)[M,K] @ (Bh+Bl)[K,N] (+bias)(+res)(relu).
// B in natural [K,N] layout; B fragments via ldmatrix.trans.
// CTA tile 128 x 128, BK=64, THREE-stage cp.async pipeline (2-chunk lookahead).
template<bool BIAS, bool RELU, bool RES, bool OSPLIT>
__global__ __launch_bounds__(256, 1) void mma_gemm(
    const __nv_bfloat16* __restrict__ Ah, const __nv_bfloat16* __restrict__ Al,
    const __nv_bfloat16* __restrict__ Bh, const __nv_bfloat16* __restrict__ Bl,
    const float* __restrict__ bias, const float* __restrict__ res,
    float* __restrict__ C, __nv_bfloat16* __restrict__ Ch,
    __nv_bfloat16* __restrict__ Cl, int M, int N, int K)
{
    constexpr int BM = 128, BN = 128, BK = 64;
    constexpr int NFRAG = BN / 16;              // 8 per warp (warp n-extent 64)
    constexpr int ASZ = BM * 128;               // A: 128 rows x 128B  = 16384
    constexpr int BSZ = BK * 256;               // B: 64 k-rows x 256B = 16384
    constexpr int STAGE = 2 * ASZ + 2 * BSZ;    // 65536

    extern __shared__ char smem[];
    const uint32_t sb = smem_to_u32(smem);

    const int m0 = blockIdx.y * BM;
    const int n0 = blockIdx.x * BN;
    const int tid = threadIdx.x;
    const int lane = tid & 31;
    const int wid = tid >> 5;
    const int wm = wid >> 1;
    const int wn = wid & 1;

    auto load_stage = [&](int kc, int s) {
        const uint32_t st = sb + s * STAGE;
        const int koff = kc * BK;
#pragma unroll
        for (int i = 0; i < 4; i++) {           // A: 128 rows x 8 groups of 16B
            const int idx = tid + i * 256;
            const int row = idx >> 3, g = idx & 7;
            const uint32_t d = st + row * 128 + ((g ^ (row & 7)) << 4);
            const size_t src = (size_t)(m0 + row) * K + koff + g * 8;
            cp_async16(d,        Ah + src);
            cp_async16(d + ASZ,  Al + src);
        }
#pragma unroll
        for (int i = 0; i < 4; i++) {           // B: 64 k-rows x 16 groups of 16B
            const int idx = tid + i * 256;
            const int row = idx >> 4, g = idx & 15;
            const uint32_t d = st + 2 * ASZ + row * 256 + ((g ^ (row & 7)) << 4);
            const size_t src = (size_t)(koff + row) * N + n0 + g * 8;
            cp_async16(d,        Bh + src);
            cp_async16(d + BSZ,  Bl + src);
        }
    };

    float acc[2][NFRAG][4];
#pragma unroll
    for (int i = 0; i < 2; i++)
#pragma unroll
        for (int j = 0; j < NFRAG; j++)
#pragma unroll
            for (int c = 0; c < 4; c++) acc[i][j][c] = 0.f;

    const int KC = K / BK;
    // prologue: prefetch two chunks
    load_stage(0, 0);
    CP_COMMIT();
    if (KC > 1) { load_stage(1, 1); CP_COMMIT(); }

    int sidx = 0;                                // stage of chunk kc
    for (int kc = 0; kc < KC; kc++) {
        if (kc + 1 < KC) CP_WAIT(1); else CP_WAIT(0);   // stage kc landed
        __syncthreads();                         // all warps done with buffer being refilled
        if (kc + 2 < KC) {
            int ns = sidx + 2; if (ns >= 3) ns -= 3;
            load_stage(kc + 2, ns);              // overlaps with compute below
            CP_COMMIT();
        }
        const uint32_t st = sb + sidx * STAGE;
#pragma unroll
        for (int ks = 0; ks < 4; ks++) {         // 4 x K=16 per chunk
            uint32_t afh[2][4], afl[2][4];
#pragma unroll
            for (int mf = 0; mf < 2; mf++) {
                const int row = wm * 32 + mf * 16 + (lane & 15);
                const int g = (ks * 2 + (lane >> 4)) ^ (row & 7);
                const uint32_t addr = st + row * 128 + (g << 4);
                ldmatrix_x4(afh[mf][0], afh[mf][1], afh[mf][2], afh[mf][3], addr);
                ldmatrix_x4(afl[mf][0], afl[mf][1], afl[mf][2], afl[mf][3], addr + ASZ);
            }
            uint32_t bfh[NFRAG][2], bfl[NFRAG][2];
#pragma unroll
            for (int nq = 0; nq < NFRAG / 2; nq++) {
                const int row = ks * 16 + (lane & 15);
                const int g = (wn * 8 + nq * 2 + (lane >> 4)) ^ (row & 7);
                const uint32_t addr = st + 2 * ASZ + row * 256 + (g << 4);
                uint32_t d0, d1, d2, d3;
                ldmatrix_x4_trans(d0, d1, d2, d3, addr);
                bfh[2 * nq][0] = d0; bfh[2 * nq][1] = d1;
                bfh[2 * nq + 1][0] = d2; bfh[2 * nq + 1][1] = d3;
                ldmatrix_x4_trans(d0, d1, d2, d3, addr + BSZ);
                bfl[2 * nq][0] = d0; bfl[2 * nq][1] = d1;
                bfl[2 * nq + 1][0] = d2; bfl[2 * nq + 1][1] = d3;
            }
#pragma unroll
            for (int mf = 0; mf < 2; mf++)
#pragma unroll
                for (int nf = 0; nf < NFRAG; nf++) {
                    mma_bf16(acc[mf][nf], afh[mf], bfh[nf]);
                    mma_bf16(acc[mf][nf], afh[mf], bfl[nf]);
                    mma_bf16(acc[mf][nf], afl[mf], bfh[nf]);
                }
        }
        if (++sidx == 3) sidx = 0;
    }

    // ---- epilogue ----
#pragma unroll
    for (int mf = 0; mf < 2; mf++) {
        const int r0i = m0 + wm * 32 + mf * 16 + (lane >> 2);
#pragma unroll
        for (int nf = 0; nf < NFRAG; nf++) {
            const int col = n0 + wn * 64 + nf * 8 + (lane & 3) * 2;
            float2 bv = make_float2(0.f, 0.f);
            if (BIAS) { bv.x = bias[col]; bv.y = bias[col + 1]; }
#pragma unroll
            for (int hrow = 0; hrow < 2; hrow++) {
                const int rr = r0i + hrow * 8;
                float2 v;
                v.x = acc[mf][nf][2 * hrow + 0] + bv.x;
                v.y = acc[mf][nf][2 * hrow + 1] + bv.y;
                if (RES) {
                    const float2 rv = *(const float2*)(res + (size_t)rr * N + col);
                    v.x += rv.x; v.y += rv.y;
                }
                if (RELU) { v.x = fmaxf(v.x, 0.f); v.y = fmaxf(v.y, 0.f); }
                if (OSPLIT) {
                    const __nv_bfloat16 h0 = __float2bfloat16(v.x);
                    const __nv_bfloat16 h1 = __float2bfloat16(v.y);
                    const __nv_bfloat16 l0 = __float2bfloat16(v.x - __bfloat162float(h0));
                    const __nv_bfloat16 l1 = __float2bfloat16(v.y - __bfloat162float(h1));
                    *(uint32_t*)(Ch + (size_t)rr * N + col) = pack_bf16x2(h0, h1);
                    *(uint32_t*)(Cl + (size_t)rr * N + col) = pack_bf16x2(l0, l1);
                } else {
                    *(float2*)(C + (size_t)rr * N + col) = v;
                }
            }
        }
    }
}

// ================= flash attention (causal, faithful ==0 mask) =================
// grid (qt=8, hb=64); block 256 = 8 warps, warp w owns rows [16w,16w+16).
// q/k/v split bf16 [hb][S][64]; output split bf16 in concat layout [token][EE].
__global__ __launch_bounds__(256, 1) void flash_kernel(
    const __nv_bfloat16* __restrict__ qh, const __nv_bfloat16* __restrict__ ql,
    const __nv_bfloat16* __restrict__ kh, const __nv_bfloat16* __restrict__ kl,
    const __nv_bfloat16* __restrict__ vh, const __nv_bfloat16* __restrict__ vl,
    __nv_bfloat16* __restrict__ oh, __nv_bfloat16* __restrict__ ol)
{
    extern __shared__ char smem[];
    const uint32_t sb = smem_to_u32(smem);
    const int qt = blockIdx.x;
    const int hb = blockIdx.y;
    const int tid = threadIdx.x, lane = tid & 31, w = tid >> 5;

    const size_t hbase = (size_t)hb * SS * 64;
    const __nv_bfloat16* Qh = qh + hbase + (size_t)qt * 128 * 64;
    const __nv_bfloat16* Ql = ql + hbase + (size_t)qt * 128 * 64;
    const __nv_bfloat16* Kh = kh + hbase;
    const __nv_bfloat16* Kl = kl + hbase;
    const __nv_bfloat16* Vh = vh + hbase;
    const __nv_bfloat16* Vl = vl + hbase;

    // SMEM: [0,16K) Qh, [16K,32K) Ql; stage s at 32768+s*65536: Kh|Kl|Vh|Vl 16K each
#pragma unroll
    for (int i = 0; i < 4; i++) {
        const int idx = tid + i * 256;
        const int row = idx >> 3, g = idx & 7;
        const uint32_t off = row * 128 + ((g ^ (row & 7)) << 4);
        const size_t src = (size_t)row * 64 + g * 8;
        cp_async16(sb + off,         Qh + src);
        cp_async16(sb + 16384 + off, Ql + src);
    }
    auto load_kv = [&](int jt, int s) {
        const uint32_t st = sb + 32768 + s * 65536;
        const size_t base = (size_t)jt * 128 * 64;
#pragma unroll
        for (int i = 0; i < 4; i++) {
            const int idx = tid + i * 256;
            const int row = idx >> 3, g = idx & 7;
            const uint32_t off = row * 128 + ((g ^ (row & 7)) << 4);
            const size_t src = base + (size_t)row * 64 + g * 8;
            cp_async16(st + off,         Kh + src);
            cp_async16(st + 16384 + off, Kl + src);
            cp_async16(st + 32768 + off, Vh + src);
            cp_async16(st + 49152 + off, Vl + src);
        }
    };
    load_kv(0, 0);
    CP_COMMIT();

    uint32_t qfh[4][4], qfl[4][4];
    float ofr[8][4];
    float mrow[2] = {-INFINITY, -INFINITY};
    float lrow[2] = {0.f, 0.f};
#pragma unroll
    for (int f = 0; f < 8; f++)
#pragma unroll
        for (int c = 0; c < 4; c++) ofr[f][c] = 0.f;

    const int rb = qt * 128 + w * 16 + (lane >> 2);

    for (int jt = 0; jt <= qt; jt++) {
        if (jt < qt) { load_kv(jt + 1, (jt + 1) & 1); CP_COMMIT(); CP_WAIT(1); }
        else CP_WAIT(0);
        __syncthreads();

        if (jt == 0) {
#pragma unroll
            for (int kk = 0; kk < 4; kk++) {
                const int row = w * 16 + (lane & 15);
                const uint32_t c = (uint32_t)((kk * 2 + (lane >> 4)) ^ (row & 7));
                const uint32_t addr = sb + row * 128 + (c << 4);
                ldmatrix_x4(qfh[kk][0], qfh[kk][1], qfh[kk][2], qfh[kk][3], addr);
                ldmatrix_x4(qfl[kk][0], qfl[kk][1], qfl[kk][2], qfl[kk][3], addr + 16384);
            }
        }

        const uint32_t st = sb + 32768 + (jt & 1) * 65536;

        // ---- S = Q K^T (split: hh + hl + lh) ----
        float cfr[16][4];
#pragma unroll
        for (int f = 0; f < 16; f++)
#pragma unroll
            for (int c = 0; c < 4; c++) cfr[f][c] = 0.f;

#pragma unroll
        for (int kk = 0; kk < 4; kk++) {
#pragma unroll
            for (int nq = 0; nq < 8; nq++) {
                const int row = nq * 16 + (lane & 15);
                const uint32_t c = (uint32_t)((kk * 2 + (lane >> 4)) ^ (row & 7));
                const uint32_t addr = st + row * 128 + (c << 4);
                uint32_t r0, r1, r2, r3, s0, s1, s2, s3;
                ldmatrix_x4(r0, r1, r2, r3, addr);
                ldmatrix_x4(s0, s1, s2, s3, addr + 16384);
                uint32_t bh0[2] = {r0, r2}, bh1[2] = {r1, r3};
                uint32_t bl0[2] = {s0, s2}, bl1[2] = {s1, s3};
                mma_bf16(cfr[2 * nq],     qfh[kk], bh0);
                mma_bf16(cfr[2 * nq],     qfh[kk], bl0);
                mma_bf16(cfr[2 * nq],     qfl[kk], bh0);
                mma_bf16(cfr[2 * nq + 1], qfh[kk], bh1);
                mma_bf16(cfr[2 * nq + 1], qfh[kk], bl1);
                mma_bf16(cfr[2 * nq + 1], qfl[kk], bh1);
            }
        }

        // ---- mask + scale + row max ----
        float tm[2] = {-INFINITY, -INFINITY};
#pragma unroll
        for (int f = 0; f < 16; f++) {
            const int col = jt * 128 + f * 8 + (lane & 3) * 2;
#pragma unroll
            for (int h2 = 0; h2 < 2; h2++) {
                const int rg = rb + h2 * 8;
                float v0 = cfr[f][2 * h2], v1 = cfr[f][2 * h2 + 1];
                v0 = (v0 == 0.f || col > rg)     ? -INFINITY : v0 * 0.125f;
                v1 = (v1 == 0.f || col + 1 > rg) ? -INFINITY : v1 * 0.125f;
                cfr[f][2 * h2] = v0; cfr[f][2 * h2 + 1] = v1;
                tm[h2] = fmaxf(tm[h2], fmaxf(v0, v1));
            }
        }
#pragma unroll
        for (int h2 = 0; h2 < 2; h2++) {
            tm[h2] = fmaxf(tm[h2], __shfl_xor_sync(0xffffffffu, tm[h2], 1));
            tm[h2] = fmaxf(tm[h2], __shfl_xor_sync(0xffffffffu, tm[h2], 2));
            const float mn = fmaxf(mrow[h2], tm[h2]);
            const float alpha = __expf(mrow[h2] - mn);
            mrow[h2] = mn;
            lrow[h2] *= alpha;
#pragma unroll
            for (int f = 0; f < 8; f++) {
                ofr[f][2 * h2]     *= alpha;
                ofr[f][2 * h2 + 1] *= alpha;
            }
        }
        // ---- exponentiate + row sum ----
        float rs[2] = {0.f, 0.f};
#pragma unroll
        for (int f = 0; f < 16; f++) {
#pragma unroll
            for (int h2 = 0; h2 < 2; h2++) {
                const float p0 = __expf(cfr[f][2 * h2]     - mrow[h2]);
                const float p1 = __expf(cfr[f][2 * h2 + 1] - mrow[h2]);
                cfr[f][2 * h2] = p0; cfr[f][2 * h2 + 1] = p1;
                rs[h2] += p0 + p1;
            }
        }
#pragma unroll
        for (int h2 = 0; h2 < 2; h2++) {
            rs[h2] += __shfl_xor_sync(0xffffffffu, rs[h2], 1);
            rs[h2] += __shfl_xor_sync(0xffffffffu, rs[h2], 2);
            lrow[h2] += rs[h2];
        }

        // ---- O += P V (P split in registers; V split from SMEM via trans) ----
#pragma unroll
        for (int kk2 = 0; kk2 < 8; kk2++) {
            uint32_t pah[4], pal[4];
#pragma unroll
            for (int r = 0; r < 4; r++) {
                const int f = 2 * kk2 + (r >> 1);
                const int c0 = (r & 1) * 2;
                const float f0 = cfr[f][c0], f1 = cfr[f][c0 + 1];
                const __nv_bfloat16 h0 = __float2bfloat16(f0);
                const __nv_bfloat16 h1 = __float2bfloat16(f1);
                const __nv_bfloat16 l0 = __float2bfloat16(f0 - __bfloat162float(h0));
                const __nv_bfloat16 l1 = __float2bfloat16(f1 - __bfloat162float(h1));
                pah[r] = pack_bf16x2(h0, h1);
                pal[r] = pack_bf16x2(l0, l1);
            }
#pragma unroll
            for (int of2 = 0; of2 < 4; of2++) {
                const int row = kk2 * 16 + (lane & 15);
                const uint32_t c = (uint32_t)((of2 * 2 + (lane >> 4)) ^ (row & 7));
                const uint32_t addr = st + 32768 + row * 128 + (c << 4);
                uint32_t d0, d1, d2, d3, e0, e1, e2, e3;
                ldmatrix_x4_trans(d0, d1, d2, d3, addr);
                ldmatrix_x4_trans(e0, e1, e2, e3, addr + 16384);
                uint32_t v0h[2] = {d0, d1}, v1h[2] = {d2, d3};
                uint32_t v0l[2] = {e0, e1}, v1l[2] = {e2, e3};
                mma_bf16(ofr[2 * of2],     pah, v0h);
                mma_bf16(ofr[2 * of2],     pah, v0l);
                mma_bf16(ofr[2 * of2],     pal, v0h);
                mma_bf16(ofr[2 * of2 + 1], pah, v1h);
                mma_bf16(ofr[2 * of2 + 1], pah, v1l);
                mma_bf16(ofr[2 * of2 + 1], pal, v1h);
            }
        }
        __syncthreads();
    }

    // ---- finalize: O /= l, write split bf16 in concat layout ----
    const float inv0 = 1.f / lrow[0], inv1 = 1.f / lrow[1];
    const int hI = hb >> 2, bI = hb & 3;
    const int s0 = qt * 128 + w * 16 + (lane >> 2);
#pragma unroll
    for (int f = 0; f < 8; f++) {
        const int col = hI * 64 + f * 8 + (lane & 3) * 2;
#pragma unroll
        for (int h2 = 0; h2 < 2; h2++) {
            const int token = bI * SS + s0 + h2 * 8;
            const float inv = h2 ? inv1 : inv0;
            const float a = ofr[f][2 * h2] * inv;
            const float b = ofr[f][2 * h2 + 1] * inv;
            const __nv_bfloat16 h0 = __float2bfloat16(a);
            const __nv_bfloat16 h1 = __float2bfloat16(b);
            const __nv_bfloat16 l0 = __float2bfloat16(a - __bfloat162float(h0));
            const __nv_bfloat16 l1 = __float2bfloat16(b - __bfloat162float(h1));
            *(uint32_t*)(oh + (size_t)token * EE + col) = pack_bf16x2(h0, h1);
            *(uint32_t*)(ol + (size_t)token * EE + col) = pack_bf16x2(l0, l1);
        }
    }
}

// ================= fused LayerNorm -> split bf16 =================
__global__ __launch_bounds__(256) void ln_split_kernel(
    const float* __restrict__ x, const float* __restrict__ g,
    const float* __restrict__ b, __nv_bfloat16* __restrict__ hi,
    __nv_bfloat16* __restrict__ lo)
{
    __shared__ float row[EE];
    __shared__ float red[256];
    const int r = blockIdx.x;
    const int t = threadIdx.x;
    const float* xr = x + (size_t)r * EE;

    float s = 0.f;
    for (int i = t; i < EE; i += 256) { float v = xr[i]; row[i] = v; s += v; }
    red[t] = s; __syncthreads();
    for (int o = 128; o > 0; o >>= 1) { if (t < o) red[t] += red[t + o]; __syncthreads(); }
    const float mean = red[0] * (1.0f / EE);
    __syncthreads();

    float vs = 0.f;
    for (int i = t; i < EE; i += 256) { float d = row[i] - mean; vs += d * d; }
    red[t] = vs; __syncthreads();
    for (int o = 128; o > 0; o >>= 1) { if (t < o) red[t] += red[t + o]; __syncthreads(); }
    const float rstd = rsqrtf(red[0] * (1.0f / EE) + LNEPS);

    __nv_bfloat16* hrow = hi + (size_t)r * EE;
    __nv_bfloat16* lrow = lo + (size_t)r * EE;
    for (int i = t; i < EE; i += 256) {
        const float v = (row[i] - mean) * rstd * g[i] + b[i];
        const __nv_bfloat16 h = __float2bfloat16(v);
        hrow[i] = h;
        lrow[i] = __float2bfloat16(v - __bfloat162float(h));
    }
}

// ================= elementwise fp32 -> split bf16 (same layout) =================
__global__ __launch_bounds__(256) void split_kernel(
    const float* __restrict__ x, __nv_bfloat16* __restrict__ hi,
    __nv_bfloat16* __restrict__ lo, int n)
{
    const int i = (blockIdx.x * 256 + threadIdx.x) * 4;
    if (i >= n) return;
    const float4 v = *(const float4*)(x + i);
    const __nv_bfloat16 h0 = __float2bfloat16(v.x);
    const __nv_bfloat16 h1 = __float2bfloat16(v.y);
    const __nv_bfloat16 h2 = __float2bfloat16(v.z);
    const __nv_bfloat16 h3 = __float2bfloat16(v.w);
    const __nv_bfloat16 l0 = __float2bfloat16(v.x - __bfloat162float(h0));
    const __nv_bfloat16 l1 = __float2bfloat16(v.y - __bfloat162float(h1));
    const __nv_bfloat16 l2 = __float2bfloat16(v.z - __bfloat162float(h2));
    const __nv_bfloat16 l3 = __float2bfloat16(v.w - __bfloat162float(h3));
    uint2* ph = (uint2*)(hi + i);
    uint2* pl = (uint2*)(lo + i);
    *ph = make_uint2(pack_bf16x2(h0, h1), pack_bf16x2(h2, h3));
    *pl = make_uint2(pack_bf16x2(l0, l1), pack_bf16x2(l2, l3));
}

// QKV weights [H][E][64] x3 -> combined [E][3072] split bf16 (n = which*1024 + h*64 + kd)
__global__ __launch_bounds__(256) void qkvw_split_kernel(
    const float* __restrict__ Wq, const float* __restrict__ Wk,
    const float* __restrict__ Wv, __nv_bfloat16* __restrict__ wh,
    __nv_bfloat16* __restrict__ wl)
{
    const int idx = blockIdx.x * 256 + threadIdx.x;   // over E*3072
    const int e = idx / 3072;
    const int c = idx % 3072;
    const float* W = (c < 1024) ? Wq : (c < 2048 ? Wk : Wv);
    const int cc = c & 1023;
    const int h = cc >> 6, kd = cc & 63;
    const float v = W[(size_t)h * EE * 64 + (size_t)e * 64 + kd];
    const __nv_bfloat16 hh = __float2bfloat16(v);
    wh[idx] = hh;
    wl[idx] = __float2bfloat16(v - __bfloat162float(hh));
}

// split QKV GEMM output [t][3072] -> q/k/v [hb][s][64] (hb = h*BB + b, t = b*SS + s)
__global__ __launch_bounds__(256) void qkv_reorder_bf(
    const __nv_bfloat16* __restrict__ sh, const __nv_bfloat16* __restrict__ sl,
    __nv_bfloat16* __restrict__ qh, __nv_bfloat16* __restrict__ ql,
    __nv_bfloat16* __restrict__ kh, __nv_bfloat16* __restrict__ kl,
    __nv_bfloat16* __restrict__ vh, __nv_bfloat16* __restrict__ vl)
{
    const int idx = blockIdx.x * 256 + threadIdx.x;
    const int kd = idx & 63;
    const int t  = (idx >> 6) & (MTOK - 1);
    const int h  = idx >> 18;
    const size_t src = (size_t)t * 3072 + h * 64 + kd;
    qh[idx] = sh[src];          ql[idx] = sl[src];
    kh[idx] = sh[src + 1024];   kl[idx] = sl[src + 1024];
    vh[idx] = sh[src + 2048];   vl[idx] = sl[src + 2048];
}

// ================= launcher =================
extern "C" void kernel_launch(void* const* d_in, const int* in_sizes, int n_in,
                              void* d_out, int out_size)
{
    (void)in_sizes; (void)n_in; (void)out_size;
    const float* x      = (const float*)d_in[0];
    const float* ln1_g  = (const float*)d_in[1];
    const float* ln1_b  = (const float*)d_in[2];
    const float* Wq     = (const float*)d_in[3];
    const float* Wk     = (const float*)d_in[4];
    const float* Wv     = (const float*)d_in[5];
    const float* proj_W = (const float*)d_in[6];
    const float* proj_b = (const float*)d_in[7];
    const float* ln2_g  = (const float*)d_in[8];
    const float* ln2_b  = (const float*)d_in[9];
    const float* fin_W  = (const float*)d_in[10];
    const float* fin_b  = (const float*)d_in[11];
    const float* hid_W  = (const float*)d_in[12];
    const float* hid_b  = (const float*)d_in[13];
    const float* fout_W = (const float*)d_in[14];
    const float* fout_b = (const float*)d_in[15];
    float* out = (float*)d_out;

    float *x1;
    __nv_bfloat16 *sah, *sal, *sbh, *sbl, *wh, *wl, *qh, *ql, *kh, *kl, *vh, *vl;
    cudaGetSymbolAddress((void**)&x1,  g_x1);
    cudaGetSymbolAddress((void**)&sah, g_sah);
    cudaGetSymbolAddress((void**)&sal, g_sal);
    cudaGetSymbolAddress((void**)&sbh, g_sbh);
    cudaGetSymbolAddress((void**)&sbl, g_sbl);
    cudaGetSymbolAddress((void**)&wh,  g_wh);
    cudaGetSymbolAddress((void**)&wl,  g_wl);
    cudaGetSymbolAddress((void**)&qh,  g_qh);
    cudaGetSymbolAddress((void**)&ql,  g_ql);
    cudaGetSymbolAddress((void**)&kh,  g_kh);
    cudaGetSymbolAddress((void**)&kl,  g_kl);
    cudaGetSymbolAddress((void**)&vh,  g_vh);
    cudaGetSymbolAddress((void**)&vl,  g_vl);

    constexpr int SMG = 196608;    // gemm: 3 stages x 64KB
    constexpr int SMF = 163840;    // flash: Q 32K + 2 x 64K
    cudaFuncSetAttribute((const void*)mma_gemm<false, false, false, true>,
                         cudaFuncAttributeMaxDynamicSharedMemorySize, SMG);
    cudaFuncSetAttribute((const void*)mma_gemm<true, false, true, false>,
                         cudaFuncAttributeMaxDynamicSharedMemorySize, SMG);
    cudaFuncSetAttribute((const void*)mma_gemm<true, true, false, true>,
                         cudaFuncAttributeMaxDynamicSharedMemorySize, SMG);
    cudaFuncSetAttribute((const void*)flash_kernel,
                         cudaFuncAttributeMaxDynamicSharedMemorySize, SMF);

    // ---------- attention ----------
    ln_split_kernel<<<MTOK, 256>>>(x, ln1_g, ln1_b, sah, sal);
    qkvw_split_kernel<<<EE * 3072 / 256, 256>>>(Wq, Wk, Wv, wh, wl);

    // QKV: [4096,1024] @ [1024,3072] -> split bf16 [t][3072]
    mma_gemm<false, false, false, true><<<dim3(3072 / 128, MTOK / 128), 256, SMG>>>(
        sah, sal, wh, wl, nullptr, nullptr, nullptr, sbh, sbl, MTOK, 3072, EE);
    qkv_reorder_bf<<<HH * MTOK * KDIM / 256, 256>>>(sbh, sbl, qh, ql, kh, kl, vh, vl);

    // fused causal attention -> split output in concat layout (sa buffers)
    flash_kernel<<<dim3(SS / 128, HH * BB), 256, SMF>>>(
        qh, ql, kh, kl, vh, vl, sah, sal);

    // x1 = x + o @ proj_W + proj_b   (proj_W already [K,N])
    split_kernel<<<EE * EE / 1024, 256>>>(proj_W, wh, wl, EE * EE);
    mma_gemm<true, false, true, false><<<dim3(EE / 128, MTOK / 128), 256, SMG>>>(
        sah, sal, wh, wl, proj_b, x, x1, nullptr, nullptr, MTOK, EE, EE);

    // ---------- FFN (split bf16 chain; weights already [K,N]) ----------
    ln_split_kernel<<<MTOK, 256>>>(x1, ln2_g, ln2_b, sah, sal);

    split_kernel<<<EE * DD / 1024, 256>>>(fin_W, wh, wl, EE * DD);
    mma_gemm<true, true, false, true><<<dim3(DD / 128, MTOK / 128), 256, SMG>>>(
        sah, sal, wh, wl, fin_b, nullptr, nullptr, sbh, sbl, MTOK, DD, EE);

    split_kernel<<<DD * DD / 1024, 256>>>(hid_W, wh, wl, DD * DD);
    mma_gemm<true, true, false, true><<<dim3(DD / 128, MTOK / 128), 256, SMG>>>(
        sbh, sbl, wh, wl, hid_b, nullptr, nullptr, sah, sal, MTOK, DD, DD);

    split_kernel<<<DD * DD / 1024, 256>>>(hid_W + (size_t)DD * DD, wh, wl, DD * DD);
    mma_gemm<true, true, false, true><<<dim3(DD / 128, MTOK / 128), 256, SMG>>>(
        sah, sal, wh, wl, hid_b + DD, nullptr, nullptr, sbh, sbl, MTOK, DD, DD);

    split_kernel<<<DD * EE / 1024, 256>>>(fout_W, wh, wl, DD * EE);
    mma_gemm<true, false, true, false><<<dim3(EE / 128, MTOK / 128), 256, SMG>>>(
        sbh, sbl, wh, wl, fout_b, x1, out, nullptr, nullptr, MTOK, EE, DD);
}

// round 14
// speedup vs baseline: 1.4725x; 1.1582x over previous
#include <cuda_runtime.h>
#include <cuda_bf16.h>
#include <math.h>
#include <stdint.h>
#include <string.h>

// ---------------- problem constants ----------------
#define BB   4
#define SS   1024
#define EE   1024
#define HH   16
#define KDIM 64
#define VDIM 64
#define DD   4096
#define MTOK 4096            // B*S tokens
#define LNEPS 1e-5f

// ---------------- device scratch (static globals; no allocations) ----------------
__device__ float g_x1[MTOK * EE];
__device__ float g_fa[(size_t)MTOK * DD];              // FFN fp32 (tf32-rounded) activations
__device__ float g_fb[(size_t)MTOK * DD];
__device__ float g_wt[(size_t)DD * DD];                // prepped tf32 weights (fragment order)
__device__ __nv_bfloat16 g_sah[(size_t)MTOK * DD];
__device__ __nv_bfloat16 g_sal[(size_t)MTOK * DD];
__device__ __nv_bfloat16 g_sbh[(size_t)MTOK * DD];
__device__ __nv_bfloat16 g_sbl[(size_t)MTOK * DD];
__device__ __nv_bfloat16 g_wh[(size_t)DD * DD];
__device__ __nv_bfloat16 g_wl[(size_t)DD * DD];
__device__ __nv_bfloat16 g_qh[HH * MTOK * KDIM];
__device__ __nv_bfloat16 g_ql[HH * MTOK * KDIM];
__device__ __nv_bfloat16 g_kh[HH * MTOK * KDIM];
__device__ __nv_bfloat16 g_kl[HH * MTOK * KDIM];
__device__ __nv_bfloat16 g_vh[HH * MTOK * VDIM];
__device__ __nv_bfloat16 g_vl[HH * MTOK * VDIM];

// ================= low-level helpers (sm_80+ base-target PTX only) =================
__device__ __forceinline__ uint32_t smem_to_u32(const void* p) {
    uint32_t a;
    asm("{ .reg .u64 t; cvta.to.shared.u64 t, %1; cvt.u32.u64 %0, t; }"
        : "=r"(a) : "l"(p));
    return a;
}
__device__ __forceinline__ void cp_async16(uint32_t dst, const void* src) {
    asm volatile("cp.async.cg.shared.global [%0], [%1], 16;"
                 :: "r"(dst), "l"(src) : "memory");
}
#define CP_COMMIT() asm volatile("cp.async.commit_group;" ::: "memory")
#define CP_WAIT(n)  asm volatile("cp.async.wait_group %0;" :: "n"(n) : "memory")

__device__ __forceinline__ void ldmatrix_x4(uint32_t& r0, uint32_t& r1,
                                            uint32_t& r2, uint32_t& r3, uint32_t addr) {
    asm volatile("ldmatrix.sync.aligned.m8n8.x4.shared.b16 {%0,%1,%2,%3}, [%4];"
                 : "=r"(r0), "=r"(r1), "=r"(r2), "=r"(r3) : "r"(addr));
}
__device__ __forceinline__ void ldmatrix_x4_trans(uint32_t& r0, uint32_t& r1,
                                                  uint32_t& r2, uint32_t& r3, uint32_t addr) {
    asm volatile("ldmatrix.sync.aligned.m8n8.x4.trans.shared.b16 {%0,%1,%2,%3}, [%4];"
                 : "=r"(r0), "=r"(r1), "=r"(r2), "=r"(r3) : "r"(addr));
}
__device__ __forceinline__ void mma_bf16(float* d, const uint32_t* a, const uint32_t* b) {
    asm volatile(
        "mma.sync.aligned.m16n8k16.row.col.f32.bf16.bf16.f32 "
        "{%0,%1,%2,%3}, {%4,%5,%6,%7}, {%8,%9}, {%0,%1,%2,%3};"
        : "+f"(d[0]), "+f"(d[1]), "+f"(d[2]), "+f"(d[3])
        : "r"(a[0]), "r"(a[1]), "r"(a[2]), "r"(a[3]), "r"(b[0]), "r"(b[1]));
}
__device__ __forceinline__ void mma_tf32(float* d, const uint32_t* a, const uint32_t* b) {
    asm volatile(
        "mma.sync.aligned.m16n8k8.row.col.f32.tf32.tf32.f32 "
        "{%0,%1,%2,%3}, {%4,%5,%6,%7}, {%8,%9}, {%0,%1,%2,%3};"
        : "+f"(d[0]), "+f"(d[1]), "+f"(d[2]), "+f"(d[3])
        : "r"(a[0]), "r"(a[1]), "r"(a[2]), "r"(a[3]), "r"(b[0]), "r"(b[1]));
}
__device__ __forceinline__ void lds64(uint32_t& r0, uint32_t& r1, uint32_t addr) {
    asm volatile("ld.shared.v2.b32 {%0,%1}, [%2];"
                 : "=r"(r0), "=r"(r1) : "r"(addr));
}
__device__ __forceinline__ uint32_t pack_bf16x2(__nv_bfloat16 a, __nv_bfloat16 b) {
    return (uint32_t)__bfloat16_as_ushort(a) | ((uint32_t)__bfloat16_as_ushort(b) << 16);
}
__device__ __forceinline__ float to_tf32(float x) {
    uint32_t u;
    asm("cvt.rna.tf32.f32 %0, %1;" : "=r"(u) : "f"(x));
    return __uint_as_float(u);
}

// ================= split-bf16 tensor-core GEMM (HMMA) =================
// C[M,N] = (Ah+Al)[M,K] @ (Bh+Bl)[K,N] (+bias)(+relu)(+res). B natural [K,N].
// Output modes: fp32 (optionally tf32-rounded) or split-bf16 pair.
// CTA 128 x 128, BK=64, 3-stage cp.async pipeline.
template<bool BIAS, bool RELU, bool RES, bool OSPLIT, bool OTF32>
__global__ __launch_bounds__(256, 1) void mma_gemm(
    const __nv_bfloat16* __restrict__ Ah, const __nv_bfloat16* __restrict__ Al,
    const __nv_bfloat16* __restrict__ Bh, const __nv_bfloat16* __restrict__ Bl,
    const float* __restrict__ bias, const float* __restrict__ res,
    float* __restrict__ C, __nv_bfloat16* __restrict__ Ch,
    __nv_bfloat16* __restrict__ Cl, int M, int N, int K)
{
    constexpr int BK = 64;
    constexpr int NFRAG = 8;
    constexpr int ASZ = 128 * 128;              // 16384
    constexpr int BSZ = BK * 256;               // 16384
    constexpr int STAGE = 2 * ASZ + 2 * BSZ;    // 65536

    extern __shared__ char smem[];
    const uint32_t sb = smem_to_u32(smem);

    const int m0 = blockIdx.y * 128;
    const int n0 = blockIdx.x * 128;
    const int tid = threadIdx.x;
    const int lane = tid & 31;
    const int wid = tid >> 5;
    const int wm = wid >> 1;
    const int wn = wid & 1;

    auto load_stage = [&](int kc, int s) {
        const uint32_t st = sb + s * STAGE;
        const int koff = kc * BK;
#pragma unroll
        for (int i = 0; i < 4; i++) {
            const int idx = tid + i * 256;
            const int row = idx >> 3, g = idx & 7;
            const uint32_t d = st + row * 128 + ((g ^ (row & 7)) << 4);
            const size_t src = (size_t)(m0 + row) * K + koff + g * 8;
            cp_async16(d,        Ah + src);
            cp_async16(d + ASZ,  Al + src);
        }
#pragma unroll
        for (int i = 0; i < 4; i++) {
            const int idx = tid + i * 256;
            const int row = idx >> 4, g = idx & 15;
            const uint32_t d = st + 2 * ASZ + row * 256 + ((g ^ (row & 7)) << 4);
            const size_t src = (size_t)(koff + row) * N + n0 + g * 8;
            cp_async16(d,        Bh + src);
            cp_async16(d + BSZ,  Bl + src);
        }
    };

    float acc[2][NFRAG][4];
#pragma unroll
    for (int i = 0; i < 2; i++)
#pragma unroll
        for (int j = 0; j < NFRAG; j++)
#pragma unroll
            for (int c = 0; c < 4; c++) acc[i][j][c] = 0.f;

    const int KC = K / BK;
    load_stage(0, 0);
    CP_COMMIT();
    if (KC > 1) { load_stage(1, 1); CP_COMMIT(); }

    int sidx = 0;
    for (int kc = 0; kc < KC; kc++) {
        if (kc + 1 < KC) CP_WAIT(1); else CP_WAIT(0);
        __syncthreads();
        if (kc + 2 < KC) {
            int ns = sidx + 2; if (ns >= 3) ns -= 3;
            load_stage(kc + 2, ns);
            CP_COMMIT();
        }
        const uint32_t st = sb + sidx * STAGE;
#pragma unroll
        for (int ks = 0; ks < 4; ks++) {
            uint32_t afh[2][4], afl[2][4];
#pragma unroll
            for (int mf = 0; mf < 2; mf++) {
                const int row = wm * 32 + mf * 16 + (lane & 15);
                const int g = (ks * 2 + (lane >> 4)) ^ (row & 7);
                const uint32_t addr = st + row * 128 + (g << 4);
                ldmatrix_x4(afh[mf][0], afh[mf][1], afh[mf][2], afh[mf][3], addr);
                ldmatrix_x4(afl[mf][0], afl[mf][1], afl[mf][2], afl[mf][3], addr + ASZ);
            }
            uint32_t bfh[NFRAG][2], bfl[NFRAG][2];
#pragma unroll
            for (int nq = 0; nq < NFRAG / 2; nq++) {
                const int row = ks * 16 + (lane & 15);
                const int g = (wn * 8 + nq * 2 + (lane >> 4)) ^ (row & 7);
                const uint32_t addr = st + 2 * ASZ + row * 256 + (g << 4);
                uint32_t d0, d1, d2, d3;
                ldmatrix_x4_trans(d0, d1, d2, d3, addr);
                bfh[2 * nq][0] = d0; bfh[2 * nq][1] = d1;
                bfh[2 * nq + 1][0] = d2; bfh[2 * nq + 1][1] = d3;
                ldmatrix_x4_trans(d0, d1, d2, d3, addr + BSZ);
                bfl[2 * nq][0] = d0; bfl[2 * nq][1] = d1;
                bfl[2 * nq + 1][0] = d2; bfl[2 * nq + 1][1] = d3;
            }
#pragma unroll
            for (int mf = 0; mf < 2; mf++)
#pragma unroll
                for (int nf = 0; nf < NFRAG; nf++) {
                    mma_bf16(acc[mf][nf], afh[mf], bfh[nf]);
                    mma_bf16(acc[mf][nf], afh[mf], bfl[nf]);
                    mma_bf16(acc[mf][nf], afl[mf], bfh[nf]);
                }
        }
        if (++sidx == 3) sidx = 0;
    }

    // ---- epilogue ----
#pragma unroll
    for (int mf = 0; mf < 2; mf++) {
        const int r0i = m0 + wm * 32 + mf * 16 + (lane >> 2);
#pragma unroll
        for (int nf = 0; nf < NFRAG; nf++) {
            const int col = n0 + wn * 64 + nf * 8 + (lane & 3) * 2;
            float2 bv = make_float2(0.f, 0.f);
            if (BIAS) { bv.x = bias[col]; bv.y = bias[col + 1]; }
#pragma unroll
            for (int hrow = 0; hrow < 2; hrow++) {
                const int rr = r0i + hrow * 8;
                float2 v;
                v.x = acc[mf][nf][2 * hrow + 0] + bv.x;
                v.y = acc[mf][nf][2 * hrow + 1] + bv.y;
                if (RES) {
                    const float2 rv = *(const float2*)(res + (size_t)rr * N + col);
                    v.x += rv.x; v.y += rv.y;
                }
                if (RELU) { v.x = fmaxf(v.x, 0.f); v.y = fmaxf(v.y, 0.f); }
                if (OSPLIT) {
                    const __nv_bfloat16 h0 = __float2bfloat16(v.x);
                    const __nv_bfloat16 h1 = __float2bfloat16(v.y);
                    const __nv_bfloat16 l0 = __float2bfloat16(v.x - __bfloat162float(h0));
                    const __nv_bfloat16 l1 = __float2bfloat16(v.y - __bfloat162float(h1));
                    *(uint32_t*)(Ch + (size_t)rr * N + col) = pack_bf16x2(h0, h1);
                    *(uint32_t*)(Cl + (size_t)rr * N + col) = pack_bf16x2(l0, l1);
                } else {
                    if (OTF32) { v.x = to_tf32(v.x); v.y = to_tf32(v.y); }
                    *(float2*)(C + (size_t)rr * N + col) = v;
                }
            }
        }
    }
}

// ================= tf32 single-pass GEMM (hidden layers) =================
// C[M,N] = A[M,K] @ B[K,N] (+bias)(+relu). A: row-major fp32 (tf32-rounded).
// B: PRE-PACKED fragment-order tf32 tiles: [K/64][N/128][kt:8][nt:16][64 words],
//   word 2l   = B[kt*8 + (l&3)    ][nt*8 + (l>>2)]
//   word 2l+1 = B[kt*8 + 4 + (l&3)][nt*8 + (l>>2)]     (l = lane 0..31)
// OTF32: round fp32 output to tf32. OSPLIT: emit bf16 hi/lo instead.
template<bool BIAS, bool RELU, bool OTF32, bool OSPLIT>
__global__ __launch_bounds__(256, 1) void tf32_gemm(
    const float* __restrict__ A, const float* __restrict__ Bt,
    const float* __restrict__ bias, float* __restrict__ C,
    __nv_bfloat16* __restrict__ Ch, __nv_bfloat16* __restrict__ Cl,
    int M, int N, int K)
{
    constexpr int BK = 64;
    constexpr int ASZ = 32768;                  // 2 halves x 128 rows x 128B
    constexpr int BSZ = 32768;                  // 8192 words fragment-order
    constexpr int STAGE = ASZ + BSZ;            // 65536

    extern __shared__ char smem[];
    const uint32_t sb = smem_to_u32(smem);

    const int m0 = blockIdx.y * 128;
    const int tid = threadIdx.x;
    const int lane = tid & 31;
    const int wid = tid >> 5;
    const int wm = wid >> 1;                    // 0..3 (32 rows each)
    const int wn = wid & 1;                     // 0..1 (64 cols each)

    auto load_stage = [&](int kc, int s) {
        const uint32_t st = sb + s * STAGE;
        const int koff = kc * BK;
#pragma unroll
        for (int i = 0; i < 8; i++) {           // A: 128 rows x 16 x 16B (two 128B halves)
            const int idx = tid + i * 256;
            const int row = idx >> 4, kg = idx & 15;
            const uint32_t d = st + ((kg >> 3) << 14) + row * 128
                             + (((kg & 7) ^ (row & 7)) << 4);
            cp_async16(d, A + (size_t)(m0 + row) * K + koff + kg * 4);
        }
        const float* bsrc = Bt + ((size_t)kc * (N >> 7) + blockIdx.x) * 8192;
#pragma unroll
        for (int i = 0; i < 8; i++) {           // B: 2048 x 16B linear
            const int idx = tid + i * 256;
            cp_async16(st + ASZ + idx * 16, bsrc + idx * 4);
        }
    };

    float acc[2][8][4];
#pragma unroll
    for (int i = 0; i < 2; i++)
#pragma unroll
        for (int j = 0; j < 8; j++)
#pragma unroll
            for (int c = 0; c < 4; c++) acc[i][j][c] = 0.f;

    const int KC = K / BK;
    load_stage(0, 0);
    CP_COMMIT();
    if (KC > 1) { load_stage(1, 1); CP_COMMIT(); }

    int sidx = 0;
    for (int kc = 0; kc < KC; kc++) {
        if (kc + 1 < KC) CP_WAIT(1); else CP_WAIT(0);
        __syncthreads();
        if (kc + 2 < KC) {
            int ns = sidx + 2; if (ns >= 3) ns -= 3;
            load_stage(kc + 2, ns);
            CP_COMMIT();
        }
        const uint32_t st = sb + sidx * STAGE;
#pragma unroll
        for (int ks = 0; ks < 8; ks++) {         // 8 x K=8 per chunk
            uint32_t af[2][4];
#pragma unroll
            for (int mf = 0; mf < 2; mf++) {
                const int r0 = wm * 32 + mf * 16;
                const int row = r0 + ((lane >> 3) & 1) * 8 + (lane & 7);
                const int g = (((ks & 3) * 2 + (lane >> 4)) ^ (row & 7));
                const uint32_t addr = st + ((ks >> 2) << 14) + row * 128 + (g << 4);
                ldmatrix_x4(af[mf][0], af[mf][1], af[mf][2], af[mf][3], addr);
            }
            uint32_t bf[8][2];
#pragma unroll
            for (int nf = 0; nf < 8; nf++) {
                const int nt = wn * 8 + nf;
                const uint32_t addr = st + ASZ + (ks * 16 + nt) * 256 + lane * 8;
                lds64(bf[nf][0], bf[nf][1], addr);
            }
#pragma unroll
            for (int mf = 0; mf < 2; mf++)
#pragma unroll
                for (int nf = 0; nf < 8; nf++)
                    mma_tf32(acc[mf][nf], af[mf], bf[nf]);
        }
        if (++sidx == 3) sidx = 0;
    }

    // ---- epilogue ----
    const int n0 = blockIdx.x * 128;
#pragma unroll
    for (int mf = 0; mf < 2; mf++) {
        const int r0i = m0 + wm * 32 + mf * 16 + (lane >> 2);
#pragma unroll
        for (int nf = 0; nf < 8; nf++) {
            const int col = n0 + wn * 64 + nf * 8 + (lane & 3) * 2;
            float2 bv = make_float2(0.f, 0.f);
            if (BIAS) { bv.x = bias[col]; bv.y = bias[col + 1]; }
#pragma unroll
            for (int hrow = 0; hrow < 2; hrow++) {
                const int rr = r0i + hrow * 8;
                float2 v;
                v.x = acc[mf][nf][2 * hrow + 0] + bv.x;
                v.y = acc[mf][nf][2 * hrow + 1] + bv.y;
                if (RELU) { v.x = fmaxf(v.x, 0.f); v.y = fmaxf(v.y, 0.f); }
                if (OSPLIT) {
                    const __nv_bfloat16 h0 = __float2bfloat16(v.x);
                    const __nv_bfloat16 h1 = __float2bfloat16(v.y);
                    const __nv_bfloat16 l0 = __float2bfloat16(v.x - __bfloat162float(h0));
                    const __nv_bfloat16 l1 = __float2bfloat16(v.y - __bfloat162float(h1));
                    *(uint32_t*)(Ch + (size_t)rr * N + col) = pack_bf16x2(h0, h1);
                    *(uint32_t*)(Cl + (size_t)rr * N + col) = pack_bf16x2(l0, l1);
                } else {
                    if (OTF32) { v.x = to_tf32(v.x); v.y = to_tf32(v.y); }
                    *(float2*)(C + (size_t)rr * N + col) = v;
                }
            }
        }
    }
}

// ================= flash attention (causal, faithful ==0 mask) =================
__global__ __launch_bounds__(256, 1) void flash_kernel(
    const __nv_bfloat16* __restrict__ qh, const __nv_bfloat16* __restrict__ ql,
    const __nv_bfloat16* __restrict__ kh, const __nv_bfloat16* __restrict__ kl,
    const __nv_bfloat16* __restrict__ vh, const __nv_bfloat16* __restrict__ vl,
    __nv_bfloat16* __restrict__ oh, __nv_bfloat16* __restrict__ ol)
{
    extern __shared__ char smem[];
    const uint32_t sb = smem_to_u32(smem);
    const int qt = blockIdx.x;
    const int hb = blockIdx.y;
    const int tid = threadIdx.x, lane = tid & 31, w = tid >> 5;

    const size_t hbase = (size_t)hb * SS * 64;
    const __nv_bfloat16* Qh = qh + hbase + (size_t)qt * 128 * 64;
    const __nv_bfloat16* Ql = ql + hbase + (size_t)qt * 128 * 64;
    const __nv_bfloat16* Kh = kh + hbase;
    const __nv_bfloat16* Kl = kl + hbase;
    const __nv_bfloat16* Vh = vh + hbase;
    const __nv_bfloat16* Vl = vl + hbase;

#pragma unroll
    for (int i = 0; i < 4; i++) {
        const int idx = tid + i * 256;
        const int row = idx >> 3, g = idx & 7;
        const uint32_t off = row * 128 + ((g ^ (row & 7)) << 4);
        const size_t src = (size_t)row * 64 + g * 8;
        cp_async16(sb + off,         Qh + src);
        cp_async16(sb + 16384 + off, Ql + src);
    }
    auto load_kv = [&](int jt, int s) {
        const uint32_t st = sb + 32768 + s * 65536;
        const size_t base = (size_t)jt * 128 * 64;
#pragma unroll
        for (int i = 0; i < 4; i++) {
            const int idx = tid + i * 256;
            const int row = idx >> 3, g = idx & 7;
            const uint32_t off = row * 128 + ((g ^ (row & 7)) << 4);
            const size_t src = base + (size_t)row * 64 + g * 8;
            cp_async16(st + off,         Kh + src);
            cp_async16(st + 16384 + off, Kl + src);
            cp_async16(st + 32768 + off, Vh + src);
            cp_async16(st + 49152 + off, Vl + src);
        }
    };
    load_kv(0, 0);
    CP_COMMIT();

    uint32_t qfh[4][4], qfl[4][4];
    float ofr[8][4];
    float mrow[2] = {-INFINITY, -INFINITY};
    float lrow[2] = {0.f, 0.f};
#pragma unroll
    for (int f = 0; f < 8; f++)
#pragma unroll
        for (int c = 0; c < 4; c++) ofr[f][c] = 0.f;

    const int rb = qt * 128 + w * 16 + (lane >> 2);

    for (int jt = 0; jt <= qt; jt++) {
        if (jt < qt) { load_kv(jt + 1, (jt + 1) & 1); CP_COMMIT(); CP_WAIT(1); }
        else CP_WAIT(0);
        __syncthreads();

        if (jt == 0) {
#pragma unroll
            for (int kk = 0; kk < 4; kk++) {
                const int row = w * 16 + (lane & 15);
                const uint32_t c = (uint32_t)((kk * 2 + (lane >> 4)) ^ (row & 7));
                const uint32_t addr = sb + row * 128 + (c << 4);
                ldmatrix_x4(qfh[kk][0], qfh[kk][1], qfh[kk][2], qfh[kk][3], addr);
                ldmatrix_x4(qfl[kk][0], qfl[kk][1], qfl[kk][2], qfl[kk][3], addr + 16384);
            }
        }

        const uint32_t st = sb + 32768 + (jt & 1) * 65536;

        float cfr[16][4];
#pragma unroll
        for (int f = 0; f < 16; f++)
#pragma unroll
            for (int c = 0; c < 4; c++) cfr[f][c] = 0.f;

#pragma unroll
        for (int kk = 0; kk < 4; kk++) {
#pragma unroll
            for (int nq = 0; nq < 8; nq++) {
                const int row = nq * 16 + (lane & 15);
                const uint32_t c = (uint32_t)((kk * 2 + (lane >> 4)) ^ (row & 7));
                const uint32_t addr = st + row * 128 + (c << 4);
                uint32_t r0, r1, r2, r3, s0, s1, s2, s3;
                ldmatrix_x4(r0, r1, r2, r3, addr);
                ldmatrix_x4(s0, s1, s2, s3, addr + 16384);
                uint32_t bh0[2] = {r0, r2}, bh1[2] = {r1, r3};
                uint32_t bl0[2] = {s0, s2}, bl1[2] = {s1, s3};
                mma_bf16(cfr[2 * nq],     qfh[kk], bh0);
                mma_bf16(cfr[2 * nq],     qfh[kk], bl0);
                mma_bf16(cfr[2 * nq],     qfl[kk], bh0);
                mma_bf16(cfr[2 * nq + 1], qfh[kk], bh1);
                mma_bf16(cfr[2 * nq + 1], qfh[kk], bl1);
                mma_bf16(cfr[2 * nq + 1], qfl[kk], bh1);
            }
        }

        float tm[2] = {-INFINITY, -INFINITY};
#pragma unroll
        for (int f = 0; f < 16; f++) {
            const int col = jt * 128 + f * 8 + (lane & 3) * 2;
#pragma unroll
            for (int h2 = 0; h2 < 2; h2++) {
                const int rg = rb + h2 * 8;
                float v0 = cfr[f][2 * h2], v1 = cfr[f][2 * h2 + 1];
                v0 = (v0 == 0.f || col > rg)     ? -INFINITY : v0 * 0.125f;
                v1 = (v1 == 0.f || col + 1 > rg) ? -INFINITY : v1 * 0.125f;
                cfr[f][2 * h2] = v0; cfr[f][2 * h2 + 1] = v1;
                tm[h2] = fmaxf(tm[h2], fmaxf(v0, v1));
            }
        }
#pragma unroll
        for (int h2 = 0; h2 < 2; h2++) {
            tm[h2] = fmaxf(tm[h2], __shfl_xor_sync(0xffffffffu, tm[h2], 1));
            tm[h2] = fmaxf(tm[h2], __shfl_xor_sync(0xffffffffu, tm[h2], 2));
            const float mn = fmaxf(mrow[h2], tm[h2]);
            const float alpha = __expf(mrow[h2] - mn);
            mrow[h2] = mn;
            lrow[h2] *= alpha;
#pragma unroll
            for (int f = 0; f < 8; f++) {
                ofr[f][2 * h2]     *= alpha;
                ofr[f][2 * h2 + 1] *= alpha;
            }
        }
        float rs[2] = {0.f, 0.f};
#pragma unroll
        for (int f = 0; f < 16; f++) {
#pragma unroll
            for (int h2 = 0; h2 < 2; h2++) {
                const float p0 = __expf(cfr[f][2 * h2]     - mrow[h2]);
                const float p1 = __expf(cfr[f][2 * h2 + 1] - mrow[h2]);
                cfr[f][2 * h2] = p0; cfr[f][2 * h2 + 1] = p1;
                rs[h2] += p0 + p1;
            }
        }
#pragma unroll
        for (int h2 = 0; h2 < 2; h2++) {
            rs[h2] += __shfl_xor_sync(0xffffffffu, rs[h2], 1);
            rs[h2] += __shfl_xor_sync(0xffffffffu, rs[h2], 2);
            lrow[h2] += rs[h2];
        }

#pragma unroll
        for (int kk2 = 0; kk2 < 8; kk2++) {
            uint32_t pah[4], pal[4];
#pragma unroll
            for (int r = 0; r < 4; r++) {
                const int f = 2 * kk2 + (r >> 1);
                const int c0 = (r & 1) * 2;
                const float f0 = cfr[f][c0], f1 = cfr[f][c0 + 1];
                const __nv_bfloat16 h0 = __float2bfloat16(f0);
                const __nv_bfloat16 h1 = __float2bfloat16(f1);
                const __nv_bfloat16 l0 = __float2bfloat16(f0 - __bfloat162float(h0));
                const __nv_bfloat16 l1 = __float2bfloat16(f1 - __bfloat162float(h1));
                pah[r] = pack_bf16x2(h0, h1);
                pal[r] = pack_bf16x2(l0, l1);
            }
#pragma unroll
            for (int of2 = 0; of2 < 4; of2++) {
                const int row = kk2 * 16 + (lane & 15);
                const uint32_t c = (uint32_t)((of2 * 2 + (lane >> 4)) ^ (row & 7));
                const uint32_t addr = st + 32768 + row * 128 + (c << 4);
                uint32_t d0, d1, d2, d3, e0, e1, e2, e3;
                ldmatrix_x4_trans(d0, d1, d2, d3, addr);
                ldmatrix_x4_trans(e0, e1, e2, e3, addr + 16384);
                uint32_t v0h[2] = {d0, d1}, v1h[2] = {d2, d3};
                uint32_t v0l[2] = {e0, e1}, v1l[2] = {e2, e3};
                mma_bf16(ofr[2 * of2],     pah, v0h);
                mma_bf16(ofr[2 * of2],     pah, v0l);
                mma_bf16(ofr[2 * of2],     pal, v0h);
                mma_bf16(ofr[2 * of2 + 1], pah, v1h);
                mma_bf16(ofr[2 * of2 + 1], pah, v1l);
                mma_bf16(ofr[2 * of2 + 1], pal, v1h);
            }
        }
        __syncthreads();
    }

    const float inv0 = 1.f / lrow[0], inv1 = 1.f / lrow[1];
    const int hI = hb >> 2, bI = hb & 3;
    const int s0 = qt * 128 + w * 16 + (lane >> 2);
#pragma unroll
    for (int f = 0; f < 8; f++) {
        const int col = hI * 64 + f * 8 + (lane & 3) * 2;
#pragma unroll
        for (int h2 = 0; h2 < 2; h2++) {
            const int token = bI * SS + s0 + h2 * 8;
            const float inv = h2 ? inv1 : inv0;
            const float a = ofr[f][2 * h2] * inv;
            const float b = ofr[f][2 * h2 + 1] * inv;
            const __nv_bfloat16 h0 = __float2bfloat16(a);
            const __nv_bfloat16 h1 = __float2bfloat16(b);
            const __nv_bfloat16 l0 = __float2bfloat16(a - __bfloat162float(h0));
            const __nv_bfloat16 l1 = __float2bfloat16(b - __bfloat162float(h1));
            *(uint32_t*)(oh + (size_t)token * EE + col) = pack_bf16x2(h0, h1);
            *(uint32_t*)(ol + (size_t)token * EE + col) = pack_bf16x2(l0, l1);
        }
    }
}

// ================= fused LayerNorm -> split bf16 =================
__global__ __launch_bounds__(256) void ln_split_kernel(
    const float* __restrict__ x, const float* __restrict__ g,
    const float* __restrict__ b, __nv_bfloat16* __restrict__ hi,
    __nv_bfloat16* __restrict__ lo)
{
    __shared__ float row[EE];
    __shared__ float red[256];
    const int r = blockIdx.x;
    const int t = threadIdx.x;
    const float* xr = x + (size_t)r * EE;

    float s = 0.f;
    for (int i = t; i < EE; i += 256) { float v = xr[i]; row[i] = v; s += v; }
    red[t] = s; __syncthreads();
    for (int o = 128; o > 0; o >>= 1) { if (t < o) red[t] += red[t + o]; __syncthreads(); }
    const float mean = red[0] * (1.0f / EE);
    __syncthreads();

    float vs = 0.f;
    for (int i = t; i < EE; i += 256) { float d = row[i] - mean; vs += d * d; }
    red[t] = vs; __syncthreads();
    for (int o = 128; o > 0; o >>= 1) { if (t < o) red[t] += red[t + o]; __syncthreads(); }
    const float rstd = rsqrtf(red[0] * (1.0f / EE) + LNEPS);

    __nv_bfloat16* hrow = hi + (size_t)r * EE;
    __nv_bfloat16* lrow = lo + (size_t)r * EE;
    for (int i = t; i < EE; i += 256) {
        const float v = (row[i] - mean) * rstd * g[i] + b[i];
        const __nv_bfloat16 h = __float2bfloat16(v);
        hrow[i] = h;
        lrow[i] = __float2bfloat16(v - __bfloat162float(h));
    }
}

// ================= elementwise fp32 -> split bf16 (weights [K,N]) =================
__global__ __launch_bounds__(256) void split_kernel(
    const float* __restrict__ x, __nv_bfloat16* __restrict__ hi,
    __nv_bfloat16* __restrict__ lo, int n)
{
    const int i = (blockIdx.x * 256 + threadIdx.x) * 4;
    if (i >= n) return;
    const float4 v = *(const float4*)(x + i);
    const __nv_bfloat16 h0 = __float2bfloat16(v.x);
    const __nv_bfloat16 h1 = __float2bfloat16(v.y);
    const __nv_bfloat16 h2 = __float2bfloat16(v.z);
    const __nv_bfloat16 h3 = __float2bfloat16(v.w);
    const __nv_bfloat16 l0 = __float2bfloat16(v.x - __bfloat162float(h0));
    const __nv_bfloat16 l1 = __float2bfloat16(v.y - __bfloat162float(h1));
    const __nv_bfloat16 l2 = __float2bfloat16(v.z - __bfloat162float(h2));
    const __nv_bfloat16 l3 = __float2bfloat16(v.w - __bfloat162float(h3));
    uint2* ph = (uint2*)(hi + i);
    uint2* pl = (uint2*)(lo + i);
    *ph = make_uint2(pack_bf16x2(h0, h1), pack_bf16x2(h2, h3));
    *pl = make_uint2(pack_bf16x2(l0, l1), pack_bf16x2(l2, l3));
}

// FFN hidden weight prep: W fp32 [K,N] -> fragment-order tf32 tiles
// layout [K/64][N/128][kt:8][nt:16][64 words]
__global__ __launch_bounds__(256) void ffnw_prep(
    const float* __restrict__ W, float* __restrict__ outw, int K, int N)
{
    const int gid = blockIdx.x * 256 + threadIdx.x;
    const int w  = gid & 63;
    const int nt = (gid >> 6) & 15;
    const int kt = (gid >> 10) & 7;
    const int rest = gid >> 13;
    const int nx = rest % (N >> 7);
    const int kc = rest / (N >> 7);
    const int l = w >> 1, h = w & 1;
    const int k = kc * 64 + kt * 8 + h * 4 + (l & 3);
    const int n = nx * 128 + nt * 8 + (l >> 2);
    outw[gid] = to_tf32(W[(size_t)k * N + n]);
}

// QKV weights [H][E][64] x3 -> combined [E][3072] split bf16
__global__ __launch_bounds__(256) void qkvw_split_kernel(
    const float* __restrict__ Wq, const float* __restrict__ Wk,
    const float* __restrict__ Wv, __nv_bfloat16* __restrict__ wh,
    __nv_bfloat16* __restrict__ wl)
{
    const int idx = blockIdx.x * 256 + threadIdx.x;
    const int e = idx / 3072;
    const int c = idx % 3072;
    const float* W = (c < 1024) ? Wq : (c < 2048 ? Wk : Wv);
    const int cc = c & 1023;
    const int h = cc >> 6, kd = cc & 63;
    const float v = W[(size_t)h * EE * 64 + (size_t)e * 64 + kd];
    const __nv_bfloat16 hh = __float2bfloat16(v);
    wh[idx] = hh;
    wl[idx] = __float2bfloat16(v - __bfloat162float(hh));
}

// split QKV GEMM output [t][3072] -> q/k/v [hb][s][64]
__global__ __launch_bounds__(256) void qkv_reorder_bf(
    const __nv_bfloat16* __restrict__ sh, const __nv_bfloat16* __restrict__ sl,
    __nv_bfloat16* __restrict__ qh, __nv_bfloat16* __restrict__ ql,
    __nv_bfloat16* __restrict__ kh, __nv_bfloat16* __restrict__ kl,
    __nv_bfloat16* __restrict__ vh, __nv_bfloat16* __restrict__ vl)
{
    const int idx = blockIdx.x * 256 + threadIdx.x;
    const int kd = idx & 63;
    const int t  = (idx >> 6) & (MTOK - 1);
    const int h  = idx >> 18;
    const size_t src = (size_t)t * 3072 + h * 64 + kd;
    qh[idx] = sh[src];          ql[idx] = sl[src];
    kh[idx] = sh[src + 1024];   kl[idx] = sl[src + 1024];
    vh[idx] = sh[src + 2048];   vl[idx] = sl[src + 2048];
}

// ================= launcher =================
extern "C" void kernel_launch(void* const* d_in, const int* in_sizes, int n_in,
                              void* d_out, int out_size)
{
    (void)in_sizes; (void)n_in; (void)out_size;
    const float* x      = (const float*)d_in[0];
    const float* ln1_g  = (const float*)d_in[1];
    const float* ln1_b  = (const float*)d_in[2];
    const float* Wq     = (const float*)d_in[3];
    const float* Wk     = (const float*)d_in[4];
    const float* Wv     = (const float*)d_in[5];
    const float* proj_W = (const float*)d_in[6];
    const float* proj_b = (const float*)d_in[7];
    const float* ln2_g  = (const float*)d_in[8];
    const float* ln2_b  = (const float*)d_in[9];
    const float* fin_W  = (const float*)d_in[10];
    const float* fin_b  = (const float*)d_in[11];
    const float* hid_W  = (const float*)d_in[12];
    const float* hid_b  = (const float*)d_in[13];
    const float* fout_W = (const float*)d_in[14];
    const float* fout_b = (const float*)d_in[15];
    float* out = (float*)d_out;

    float *x1, *fa, *fb, *wt;
    __nv_bfloat16 *sah, *sal, *sbh, *sbl, *wh, *wl, *qh, *ql, *kh, *kl, *vh, *vl;
    cudaGetSymbolAddress((void**)&x1,  g_x1);
    cudaGetSymbolAddress((void**)&fa,  g_fa);
    cudaGetSymbolAddress((void**)&fb,  g_fb);
    cudaGetSymbolAddress((void**)&wt,  g_wt);
    cudaGetSymbolAddress((void**)&sah, g_sah);
    cudaGetSymbolAddress((void**)&sal, g_sal);
    cudaGetSymbolAddress((void**)&sbh, g_sbh);
    cudaGetSymbolAddress((void**)&sbl, g_sbl);
    cudaGetSymbolAddress((void**)&wh,  g_wh);
    cudaGetSymbolAddress((void**)&wl,  g_wl);
    cudaGetSymbolAddress((void**)&qh,  g_qh);
    cudaGetSymbolAddress((void**)&ql,  g_ql);
    cudaGetSymbolAddress((void**)&kh,  g_kh);
    cudaGetSymbolAddress((void**)&kl,  g_kl);
    cudaGetSymbolAddress((void**)&vh,  g_vh);
    cudaGetSymbolAddress((void**)&vl,  g_vl);

    constexpr int SMG = 196608;    // 3 stages x 64KB (both gemm flavors)
    constexpr int SMF = 163840;    // flash
    cudaFuncSetAttribute((const void*)mma_gemm<false, false, false, true, false>,
                         cudaFuncAttributeMaxDynamicSharedMemorySize, SMG);
    cudaFuncSetAttribute((const void*)mma_gemm<true, false, true, false, false>,
                         cudaFuncAttributeMaxDynamicSharedMemorySize, SMG);
    cudaFuncSetAttribute((const void*)mma_gemm<true, true, false, false, true>,
                         cudaFuncAttributeMaxDynamicSharedMemorySize, SMG);
    cudaFuncSetAttribute((const void*)tf32_gemm<true, true, true, false>,
                         cudaFuncAttributeMaxDynamicSharedMemorySize, SMG);
    cudaFuncSetAttribute((const void*)tf32_gemm<true, true, false, true>,
                         cudaFuncAttributeMaxDynamicSharedMemorySize, SMG);
    cudaFuncSetAttribute((const void*)flash_kernel,
                         cudaFuncAttributeMaxDynamicSharedMemorySize, SMF);

    // ---------- attention (split-bf16, unchanged) ----------
    ln_split_kernel<<<MTOK, 256>>>(x, ln1_g, ln1_b, sah, sal);
    qkvw_split_kernel<<<EE * 3072 / 256, 256>>>(Wq, Wk, Wv, wh, wl);

    mma_gemm<false, false, false, true, false><<<dim3(3072 / 128, MTOK / 128), 256, SMG>>>(
        sah, sal, wh, wl, nullptr, nullptr, nullptr, sbh, sbl, MTOK, 3072, EE);
    qkv_reorder_bf<<<HH * MTOK * KDIM / 256, 256>>>(sbh, sbl, qh, ql, kh, kl, vh, vl);

    flash_kernel<<<dim3(SS / 128, HH * BB), 256, SMF>>>(
        qh, ql, kh, kl, vh, vl, sah, sal);

    split_kernel<<<EE * EE / 1024, 256>>>(proj_W, wh, wl, EE * EE);
    mma_gemm<true, false, true, false, false><<<dim3(EE / 128, MTOK / 128), 256, SMG>>>(
        sah, sal, wh, wl, proj_b, x, x1, nullptr, nullptr, MTOK, EE, EE);

    // ---------- FFN: fin (bf16-split, tf32-rounded out) -> hid1/hid2 (tf32) -> fout (bf16-split) ----------
    ln_split_kernel<<<MTOK, 256>>>(x1, ln2_g, ln2_b, sah, sal);

    split_kernel<<<EE * DD / 1024, 256>>>(fin_W, wh, wl, EE * DD);
    mma_gemm<true, true, false, false, true><<<dim3(DD / 128, MTOK / 128), 256, SMG>>>(
        sah, sal, wh, wl, fin_b, nullptr, fa, nullptr, nullptr, MTOK, DD, EE);

    ffnw_prep<<<DD * DD / 256, 256>>>(hid_W, wt, DD, DD);
    tf32_gemm<true, true, true, false><<<dim3(DD / 128, MTOK / 128), 256, SMG>>>(
        fa, wt, hid_b, fb, nullptr, nullptr, MTOK, DD, DD);

    ffnw_prep<<<DD * DD / 256, 256>>>(hid_W + (size_t)DD * DD, wt, DD, DD);
    tf32_gemm<true, true, false, true><<<dim3(DD / 128, MTOK / 128), 256, SMG>>>(
        fb, wt, hid_b + DD, nullptr, sbh, sbl, MTOK, DD, DD);

    split_kernel<<<DD * EE / 1024, 256>>>(fout_W, wh, wl, DD * EE);
    mma_gemm<true, false, true, false, false><<<dim3(EE / 128, MTOK / 128), 256, SMG>>>(
        sbh, sbl, wh, wl, fout_b, x1, out, nullptr, nullptr, MTOK, EE, DD);
}

// round 15
// speedup vs baseline: 1.5891x; 1.0792x over previous
#include <cuda_runtime.h>
#include <cuda_bf16.h>
#include <math.h>
#include <stdint.h>
#include <string.h>

// ---------------- problem constants ----------------
#define BB   4
#define SS   1024
#define EE   1024
#define HH   16
#define KDIM 64
#define VDIM 64
#define DD   4096
#define MTOK 4096            // B*S tokens
#define LNEPS 1e-5f

// ---------------- device scratch (static globals; no allocations) ----------------
__device__ float g_x1[MTOK * EE];
__device__ float g_fa[(size_t)MTOK * DD];              // fp32 (tf32-rounded) activations
__device__ float g_fb[(size_t)MTOK * DD];
__device__ float g_wt[(size_t)DD * DD];                // prepped tf32 weights (fragment order)
__device__ __nv_bfloat16 g_sbh[(size_t)MTOK * 3072];   // QKV gemm split output
__device__ __nv_bfloat16 g_sbl[(size_t)MTOK * 3072];
__device__ __nv_bfloat16 g_qh[HH * MTOK * KDIM];
__device__ __nv_bfloat16 g_ql[HH * MTOK * KDIM];
__device__ __nv_bfloat16 g_kh[HH * MTOK * KDIM];
__device__ __nv_bfloat16 g_kl[HH * MTOK * KDIM];
__device__ __nv_bfloat16 g_vh[HH * MTOK * VDIM];
__device__ __nv_bfloat16 g_vl[HH * MTOK * VDIM];

// ================= low-level helpers (sm_80+ base-target PTX only) =================
__device__ __forceinline__ uint32_t smem_to_u32(const void* p) {
    uint32_t a;
    asm("{ .reg .u64 t; cvta.to.shared.u64 t, %1; cvt.u32.u64 %0, t; }"
        : "=r"(a) : "l"(p));
    return a;
}
__device__ __forceinline__ void cp_async16(uint32_t dst, const void* src) {
    asm volatile("cp.async.cg.shared.global [%0], [%1], 16;"
                 :: "r"(dst), "l"(src) : "memory");
}
#define CP_COMMIT() asm volatile("cp.async.commit_group;" ::: "memory")
#define CP_WAIT(n)  asm volatile("cp.async.wait_group %0;" :: "n"(n) : "memory")

__device__ __forceinline__ void ldmatrix_x4(uint32_t& r0, uint32_t& r1,
                                            uint32_t& r2, uint32_t& r3, uint32_t addr) {
    asm volatile("ldmatrix.sync.aligned.m8n8.x4.shared.b16 {%0,%1,%2,%3}, [%4];"
                 : "=r"(r0), "=r"(r1), "=r"(r2), "=r"(r3) : "r"(addr));
}
__device__ __forceinline__ void ldmatrix_x4_trans(uint32_t& r0, uint32_t& r1,
                                                  uint32_t& r2, uint32_t& r3, uint32_t addr) {
    asm volatile("ldmatrix.sync.aligned.m8n8.x4.trans.shared.b16 {%0,%1,%2,%3}, [%4];"
                 : "=r"(r0), "=r"(r1), "=r"(r2), "=r"(r3) : "r"(addr));
}
__device__ __forceinline__ void mma_bf16(float* d, const uint32_t* a, const uint32_t* b) {
    asm volatile(
        "mma.sync.aligned.m16n8k16.row.col.f32.bf16.bf16.f32 "
        "{%0,%1,%2,%3}, {%4,%5,%6,%7}, {%8,%9}, {%0,%1,%2,%3};"
        : "+f"(d[0]), "+f"(d[1]), "+f"(d[2]), "+f"(d[3])
        : "r"(a[0]), "r"(a[1]), "r"(a[2]), "r"(a[3]), "r"(b[0]), "r"(b[1]));
}
__device__ __forceinline__ void mma_tf32(float* d, const uint32_t* a, const uint32_t* b) {
    asm volatile(
        "mma.sync.aligned.m16n8k8.row.col.f32.tf32.tf32.f32 "
        "{%0,%1,%2,%3}, {%4,%5,%6,%7}, {%8,%9}, {%0,%1,%2,%3};"
        : "+f"(d[0]), "+f"(d[1]), "+f"(d[2]), "+f"(d[3])
        : "r"(a[0]), "r"(a[1]), "r"(a[2]), "r"(a[3]), "r"(b[0]), "r"(b[1]));
}
__device__ __forceinline__ void lds64(uint32_t& r0, uint32_t& r1, uint32_t addr) {
    asm volatile("ld.shared.v2.b32 {%0,%1}, [%2];"
                 : "=r"(r0), "=r"(r1) : "r"(addr));
}
__device__ __forceinline__ uint32_t pack_bf16x2(__nv_bfloat16 a, __nv_bfloat16 b) {
    return (uint32_t)__bfloat16_as_ushort(a) | ((uint32_t)__bfloat16_as_ushort(b) << 16);
}
__device__ __forceinline__ float to_tf32(float x) {
    uint32_t u;
    asm("cvt.rna.tf32.f32 %0, %1;" : "=r"(u) : "f"(x));
    return __uint_as_float(u);
}

// ================= tf32 single-pass GEMM (all linear layers) =================
// C[M,N] = A[M,K] @ B[K,N] (+bias)(+relu)(+res). A: row-major fp32 (tf32-rounded).
// B: PRE-PACKED fragment-order tf32 tiles: [K/64][N/128][kt:8][nt:16][64 words],
//   word 2l   = B[kt*8 + (l&3)    ][nt*8 + (l>>2)]
//   word 2l+1 = B[kt*8 + 4 + (l&3)][nt*8 + (l>>2)]     (l = lane 0..31)
// OTF32: round fp32 output to tf32 (next-GEMM A). OSPLIT: emit bf16 hi/lo.
template<bool BIAS, bool RELU, bool RES, bool OTF32, bool OSPLIT>
__global__ __launch_bounds__(256, 1) void tf32_gemm(
    const float* __restrict__ A, const float* __restrict__ Bt,
    const float* __restrict__ bias, const float* __restrict__ res,
    float* __restrict__ C, __nv_bfloat16* __restrict__ Ch,
    __nv_bfloat16* __restrict__ Cl, int M, int N, int K)
{
    constexpr int BK = 64;
    constexpr int ASZ = 32768;                  // 2 halves x 128 rows x 128B
    constexpr int BSZ = 32768;                  // 8192 words fragment-order
    constexpr int STAGE = ASZ + BSZ;            // 65536

    extern __shared__ char smem[];
    const uint32_t sb = smem_to_u32(smem);

    const int m0 = blockIdx.y * 128;
    const int tid = threadIdx.x;
    const int lane = tid & 31;
    const int wid = tid >> 5;
    const int wm = wid >> 1;                    // 0..3 (32 rows each)
    const int wn = wid & 1;                     // 0..1 (64 cols each)

    auto load_stage = [&](int kc, int s) {
        const uint32_t st = sb + s * STAGE;
        const int koff = kc * BK;
#pragma unroll
        for (int i = 0; i < 8; i++) {           // A: 128 rows x 16 x 16B (two 128B halves)
            const int idx = tid + i * 256;
            const int row = idx >> 4, kg = idx & 15;
            const uint32_t d = st + ((kg >> 3) << 14) + row * 128
                             + (((kg & 7) ^ (row & 7)) << 4);
            cp_async16(d, A + (size_t)(m0 + row) * K + koff + kg * 4);
        }
        const float* bsrc = Bt + ((size_t)kc * (N >> 7) + blockIdx.x) * 8192;
#pragma unroll
        for (int i = 0; i < 8; i++) {           // B: 2048 x 16B linear
            const int idx = tid + i * 256;
            cp_async16(st + ASZ + idx * 16, bsrc + idx * 4);
        }
    };

    float acc[2][8][4];
#pragma unroll
    for (int i = 0; i < 2; i++)
#pragma unroll
        for (int j = 0; j < 8; j++)
#pragma unroll
            for (int c = 0; c < 4; c++) acc[i][j][c] = 0.f;

    const int KC = K / BK;
    load_stage(0, 0);
    CP_COMMIT();
    if (KC > 1) { load_stage(1, 1); CP_COMMIT(); }

    int sidx = 0;
    for (int kc = 0; kc < KC; kc++) {
        if (kc + 1 < KC) CP_WAIT(1); else CP_WAIT(0);
        __syncthreads();
        if (kc + 2 < KC) {
            int ns = sidx + 2; if (ns >= 3) ns -= 3;
            load_stage(kc + 2, ns);
            CP_COMMIT();
        }
        const uint32_t st = sb + sidx * STAGE;
#pragma unroll
        for (int ks = 0; ks < 8; ks++) {         // 8 x K=8 per chunk
            uint32_t af[2][4];
#pragma unroll
            for (int mf = 0; mf < 2; mf++) {
                const int r0 = wm * 32 + mf * 16;
                const int row = r0 + ((lane >> 3) & 1) * 8 + (lane & 7);
                const int g = (((ks & 3) * 2 + (lane >> 4)) ^ (row & 7));
                const uint32_t addr = st + ((ks >> 2) << 14) + row * 128 + (g << 4);
                ldmatrix_x4(af[mf][0], af[mf][1], af[mf][2], af[mf][3], addr);
            }
            uint32_t bf[8][2];
#pragma unroll
            for (int nf = 0; nf < 8; nf++) {
                const int nt = wn * 8 + nf;
                const uint32_t addr = st + ASZ + (ks * 16 + nt) * 256 + lane * 8;
                lds64(bf[nf][0], bf[nf][1], addr);
            }
#pragma unroll
            for (int mf = 0; mf < 2; mf++)
#pragma unroll
                for (int nf = 0; nf < 8; nf++)
                    mma_tf32(acc[mf][nf], af[mf], bf[nf]);
        }
        if (++sidx == 3) sidx = 0;
    }

    // ---- epilogue ----
    const int n0 = blockIdx.x * 128;
#pragma unroll
    for (int mf = 0; mf < 2; mf++) {
        const int r0i = m0 + wm * 32 + mf * 16 + (lane >> 2);
#pragma unroll
        for (int nf = 0; nf < 8; nf++) {
            const int col = n0 + wn * 64 + nf * 8 + (lane & 3) * 2;
            float2 bv = make_float2(0.f, 0.f);
            if (BIAS) { bv.x = bias[col]; bv.y = bias[col + 1]; }
#pragma unroll
            for (int hrow = 0; hrow < 2; hrow++) {
                const int rr = r0i + hrow * 8;
                float2 v;
                v.x = acc[mf][nf][2 * hrow + 0] + bv.x;
                v.y = acc[mf][nf][2 * hrow + 1] + bv.y;
                if (RES) {
                    const float2 rv = *(const float2*)(res + (size_t)rr * N + col);
                    v.x += rv.x; v.y += rv.y;
                }
                if (RELU) { v.x = fmaxf(v.x, 0.f); v.y = fmaxf(v.y, 0.f); }
                if (OSPLIT) {
                    const __nv_bfloat16 h0 = __float2bfloat16(v.x);
                    const __nv_bfloat16 h1 = __float2bfloat16(v.y);
                    const __nv_bfloat16 l0 = __float2bfloat16(v.x - __bfloat162float(h0));
                    const __nv_bfloat16 l1 = __float2bfloat16(v.y - __bfloat162float(h1));
                    *(uint32_t*)(Ch + (size_t)rr * N + col) = pack_bf16x2(h0, h1);
                    *(uint32_t*)(Cl + (size_t)rr * N + col) = pack_bf16x2(l0, l1);
                } else {
                    if (OTF32) { v.x = to_tf32(v.x); v.y = to_tf32(v.y); }
                    *(float2*)(C + (size_t)rr * N + col) = v;
                }
            }
        }
    }
}

// ================= flash attention (causal, faithful ==0 mask) =================
// grid (qt=8, hb=64); block 256 = 8 warps, warp w owns rows [16w,16w+16).
// q/k/v split bf16 [hb][S][64]; output fp32 (tf32-rounded) concat layout [token][EE].
__global__ __launch_bounds__(256, 1) void flash_kernel(
    const __nv_bfloat16* __restrict__ qh, const __nv_bfloat16* __restrict__ ql,
    const __nv_bfloat16* __restrict__ kh, const __nv_bfloat16* __restrict__ kl,
    const __nv_bfloat16* __restrict__ vh, const __nv_bfloat16* __restrict__ vl,
    float* __restrict__ o)
{
    extern __shared__ char smem[];
    const uint32_t sb = smem_to_u32(smem);
    const int qt = blockIdx.x;
    const int hb = blockIdx.y;
    const int tid = threadIdx.x, lane = tid & 31, w = tid >> 5;

    const size_t hbase = (size_t)hb * SS * 64;
    const __nv_bfloat16* Qh = qh + hbase + (size_t)qt * 128 * 64;
    const __nv_bfloat16* Ql = ql + hbase + (size_t)qt * 128 * 64;
    const __nv_bfloat16* Kh = kh + hbase;
    const __nv_bfloat16* Kl = kl + hbase;
    const __nv_bfloat16* Vh = vh + hbase;
    const __nv_bfloat16* Vl = vl + hbase;

#pragma unroll
    for (int i = 0; i < 4; i++) {
        const int idx = tid + i * 256;
        const int row = idx >> 3, g = idx & 7;
        const uint32_t off = row * 128 + ((g ^ (row & 7)) << 4);
        const size_t src = (size_t)row * 64 + g * 8;
        cp_async16(sb + off,         Qh + src);
        cp_async16(sb + 16384 + off, Ql + src);
    }
    auto load_kv = [&](int jt, int s) {
        const uint32_t st = sb + 32768 + s * 65536;
        const size_t base = (size_t)jt * 128 * 64;
#pragma unroll
        for (int i = 0; i < 4; i++) {
            const int idx = tid + i * 256;
            const int row = idx >> 3, g = idx & 7;
            const uint32_t off = row * 128 + ((g ^ (row & 7)) << 4);
            const size_t src = base + (size_t)row * 64 + g * 8;
            cp_async16(st + off,         Kh + src);
            cp_async16(st + 16384 + off, Kl + src);
            cp_async16(st + 32768 + off, Vh + src);
            cp_async16(st + 49152 + off, Vl + src);
        }
    };
    load_kv(0, 0);
    CP_COMMIT();

    uint32_t qfh[4][4], qfl[4][4];
    float ofr[8][4];
    float mrow[2] = {-INFINITY, -INFINITY};
    float lrow[2] = {0.f, 0.f};
#pragma unroll
    for (int f = 0; f < 8; f++)
#pragma unroll
        for (int c = 0; c < 4; c++) ofr[f][c] = 0.f;

    const int rb = qt * 128 + w * 16 + (lane >> 2);

    for (int jt = 0; jt <= qt; jt++) {
        if (jt < qt) { load_kv(jt + 1, (jt + 1) & 1); CP_COMMIT(); CP_WAIT(1); }
        else CP_WAIT(0);
        __syncthreads();

        if (jt == 0) {
#pragma unroll
            for (int kk = 0; kk < 4; kk++) {
                const int row = w * 16 + (lane & 15);
                const uint32_t c = (uint32_t)((kk * 2 + (lane >> 4)) ^ (row & 7));
                const uint32_t addr = sb + row * 128 + (c << 4);
                ldmatrix_x4(qfh[kk][0], qfh[kk][1], qfh[kk][2], qfh[kk][3], addr);
                ldmatrix_x4(qfl[kk][0], qfl[kk][1], qfl[kk][2], qfl[kk][3], addr + 16384);
            }
        }

        const uint32_t st = sb + 32768 + (jt & 1) * 65536;

        float cfr[16][4];
#pragma unroll
        for (int f = 0; f < 16; f++)
#pragma unroll
            for (int c = 0; c < 4; c++) cfr[f][c] = 0.f;

#pragma unroll
        for (int kk = 0; kk < 4; kk++) {
#pragma unroll
            for (int nq = 0; nq < 8; nq++) {
                const int row = nq * 16 + (lane & 15);
                const uint32_t c = (uint32_t)((kk * 2 + (lane >> 4)) ^ (row & 7));
                const uint32_t addr = st + row * 128 + (c << 4);
                uint32_t r0, r1, r2, r3, s0, s1, s2, s3;
                ldmatrix_x4(r0, r1, r2, r3, addr);
                ldmatrix_x4(s0, s1, s2, s3, addr + 16384);
                uint32_t bh0[2] = {r0, r2}, bh1[2] = {r1, r3};
                uint32_t bl0[2] = {s0, s2}, bl1[2] = {s1, s3};
                mma_bf16(cfr[2 * nq],     qfh[kk], bh0);
                mma_bf16(cfr[2 * nq],     qfh[kk], bl0);
                mma_bf16(cfr[2 * nq],     qfl[kk], bh0);
                mma_bf16(cfr[2 * nq + 1], qfh[kk], bh1);
                mma_bf16(cfr[2 * nq + 1], qfh[kk], bl1);
                mma_bf16(cfr[2 * nq + 1], qfl[kk], bh1);
            }
        }

        float tm[2] = {-INFINITY, -INFINITY};
#pragma unroll
        for (int f = 0; f < 16; f++) {
            const int col = jt * 128 + f * 8 + (lane & 3) * 2;
#pragma unroll
            for (int h2 = 0; h2 < 2; h2++) {
                const int rg = rb + h2 * 8;
                float v0 = cfr[f][2 * h2], v1 = cfr[f][2 * h2 + 1];
                v0 = (v0 == 0.f || col > rg)     ? -INFINITY : v0 * 0.125f;
                v1 = (v1 == 0.f || col + 1 > rg) ? -INFINITY : v1 * 0.125f;
                cfr[f][2 * h2] = v0; cfr[f][2 * h2 + 1] = v1;
                tm[h2] = fmaxf(tm[h2], fmaxf(v0, v1));
            }
        }
#pragma unroll
        for (int h2 = 0; h2 < 2; h2++) {
            tm[h2] = fmaxf(tm[h2], __shfl_xor_sync(0xffffffffu, tm[h2], 1));
            tm[h2] = fmaxf(tm[h2], __shfl_xor_sync(0xffffffffu, tm[h2], 2));
            const float mn = fmaxf(mrow[h2], tm[h2]);
            const float alpha = __expf(mrow[h2] - mn);
            mrow[h2] = mn;
            lrow[h2] *= alpha;
#pragma unroll
            for (int f = 0; f < 8; f++) {
                ofr[f][2 * h2]     *= alpha;
                ofr[f][2 * h2 + 1] *= alpha;
            }
        }
        float rs[2] = {0.f, 0.f};
#pragma unroll
        for (int f = 0; f < 16; f++) {
#pragma unroll
            for (int h2 = 0; h2 < 2; h2++) {
                const float p0 = __expf(cfr[f][2 * h2]     - mrow[h2]);
                const float p1 = __expf(cfr[f][2 * h2 + 1] - mrow[h2]);
                cfr[f][2 * h2] = p0; cfr[f][2 * h2 + 1] = p1;
                rs[h2] += p0 + p1;
            }
        }
#pragma unroll
        for (int h2 = 0; h2 < 2; h2++) {
            rs[h2] += __shfl_xor_sync(0xffffffffu, rs[h2], 1);
            rs[h2] += __shfl_xor_sync(0xffffffffu, rs[h2], 2);
            lrow[h2] += rs[h2];
        }

#pragma unroll
        for (int kk2 = 0; kk2 < 8; kk2++) {
            uint32_t pah[4], pal[4];
#pragma unroll
            for (int r = 0; r < 4; r++) {
                const int f = 2 * kk2 + (r >> 1);
                const int c0 = (r & 1) * 2;
                const float f0 = cfr[f][c0], f1 = cfr[f][c0 + 1];
                const __nv_bfloat16 h0 = __float2bfloat16(f0);
                const __nv_bfloat16 h1 = __float2bfloat16(f1);
                const __nv_bfloat16 l0 = __float2bfloat16(f0 - __bfloat162float(h0));
                const __nv_bfloat16 l1 = __float2bfloat16(f1 - __bfloat162float(h1));
                pah[r] = pack_bf16x2(h0, h1);
                pal[r] = pack_bf16x2(l0, l1);
            }
#pragma unroll
            for (int of2 = 0; of2 < 4; of2++) {
                const int row = kk2 * 16 + (lane & 15);
                const uint32_t c = (uint32_t)((of2 * 2 + (lane >> 4)) ^ (row & 7));
                const uint32_t addr = st + 32768 + row * 128 + (c << 4);
                uint32_t d0, d1, d2, d3, e0, e1, e2, e3;
                ldmatrix_x4_trans(d0, d1, d2, d3, addr);
                ldmatrix_x4_trans(e0, e1, e2, e3, addr + 16384);
                uint32_t v0h[2] = {d0, d1}, v1h[2] = {d2, d3};
                uint32_t v0l[2] = {e0, e1}, v1l[2] = {e2, e3};
                mma_bf16(ofr[2 * of2],     pah, v0h);
                mma_bf16(ofr[2 * of2],     pah, v0l);
                mma_bf16(ofr[2 * of2],     pal, v0h);
                mma_bf16(ofr[2 * of2 + 1], pah, v1h);
                mma_bf16(ofr[2 * of2 + 1], pah, v1l);
                mma_bf16(ofr[2 * of2 + 1], pal, v1h);
            }
        }
        __syncthreads();
    }

    // ---- finalize: O /= l, tf32-round, write fp32 concat layout ----
    const float inv0 = 1.f / lrow[0], inv1 = 1.f / lrow[1];
    const int hI = hb >> 2, bI = hb & 3;
    const int s0 = qt * 128 + w * 16 + (lane >> 2);
#pragma unroll
    for (int f = 0; f < 8; f++) {
        const int col = hI * 64 + f * 8 + (lane & 3) * 2;
#pragma unroll
        for (int h2 = 0; h2 < 2; h2++) {
            const int token = bI * SS + s0 + h2 * 8;
            const float inv = h2 ? inv1 : inv0;
            float2 v;
            v.x = to_tf32(ofr[f][2 * h2] * inv);
            v.y = to_tf32(ofr[f][2 * h2 + 1] * inv);
            *(float2*)(o + (size_t)token * EE + col) = v;
        }
    }
}

// ================= fused LayerNorm -> tf32-rounded fp32 =================
__global__ __launch_bounds__(256) void ln_tf32_kernel(
    const float* __restrict__ x, const float* __restrict__ g,
    const float* __restrict__ b, float* __restrict__ out)
{
    __shared__ float row[EE];
    __shared__ float red[256];
    const int r = blockIdx.x;
    const int t = threadIdx.x;
    const float* xr = x + (size_t)r * EE;

    float s = 0.f;
    for (int i = t; i < EE; i += 256) { float v = xr[i]; row[i] = v; s += v; }
    red[t] = s; __syncthreads();
    for (int o = 128; o > 0; o >>= 1) { if (t < o) red[t] += red[t + o]; __syncthreads(); }
    const float mean = red[0] * (1.0f / EE);
    __syncthreads();

    float vs = 0.f;
    for (int i = t; i < EE; i += 256) { float d = row[i] - mean; vs += d * d; }
    red[t] = vs; __syncthreads();
    for (int o = 128; o > 0; o >>= 1) { if (t < o) red[t] += red[t + o]; __syncthreads(); }
    const float rstd = rsqrtf(red[0] * (1.0f / EE) + LNEPS);

    float* orow = out + (size_t)r * EE;
    for (int i = t; i < EE; i += 256)
        orow[i] = to_tf32((row[i] - mean) * rstd * g[i] + b[i]);
}

// Weight prep: W fp32 [K,N] -> fragment-order tf32 tiles
// layout [K/64][N/128][kt:8][nt:16][64 words]
__global__ __launch_bounds__(256) void ffnw_prep(
    const float* __restrict__ W, float* __restrict__ outw, int K, int N)
{
    const int gid = blockIdx.x * 256 + threadIdx.x;
    const int w  = gid & 63;
    const int nt = (gid >> 6) & 15;
    const int kt = (gid >> 10) & 7;
    const int rest = gid >> 13;
    const int nx = rest % (N >> 7);
    const int kc = rest / (N >> 7);
    const int l = w >> 1, h = w & 1;
    const int k = kc * 64 + kt * 8 + h * 4 + (l & 3);
    const int n = nx * 128 + nt * 8 + (l >> 2);
    outw[gid] = to_tf32(W[(size_t)k * N + n]);
}

// QKV weight prep: Wq/Wk/Wv [H][E][64] -> fragment-order tf32, N=3072 (q|k|v), K=E
__global__ __launch_bounds__(256) void qkvw_prep(
    const float* __restrict__ Wq, const float* __restrict__ Wk,
    const float* __restrict__ Wv, float* __restrict__ outw)
{
    const int gid = blockIdx.x * 256 + threadIdx.x;   // K*N = 1024*3072
    const int w  = gid & 63;
    const int nt = (gid >> 6) & 15;
    const int kt = (gid >> 10) & 7;
    const int rest = gid >> 13;
    const int nx = rest % (3072 >> 7);                // 24
    const int kc = rest / (3072 >> 7);
    const int l = w >> 1, h = w & 1;
    const int k = kc * 64 + kt * 8 + h * 4 + (l & 3); // = e
    const int n = nx * 128 + nt * 8 + (l >> 2);       // 0..3071
    const float* W = (n < 1024) ? Wq : (n < 2048 ? Wk : Wv);
    const int cc = n & 1023;
    const int hd = cc >> 6, kd = cc & 63;
    outw[gid] = to_tf32(W[(size_t)hd * EE * 64 + (size_t)k * 64 + kd]);
}

// split QKV GEMM output [t][3072] -> q/k/v [hb][s][64]
__global__ __launch_bounds__(256) void qkv_reorder_bf(
    const __nv_bfloat16* __restrict__ sh, const __nv_bfloat16* __restrict__ sl,
    __nv_bfloat16* __restrict__ qh, __nv_bfloat16* __restrict__ ql,
    __nv_bfloat16* __restrict__ kh, __nv_bfloat16* __restrict__ kl,
    __nv_bfloat16* __restrict__ vh, __nv_bfloat16* __restrict__ vl)
{
    const int idx = blockIdx.x * 256 + threadIdx.x;
    const int kd = idx & 63;
    const int t  = (idx >> 6) & (MTOK - 1);
    const int h  = idx >> 18;
    const size_t src = (size_t)t * 3072 + h * 64 + kd;
    qh[idx] = sh[src];          ql[idx] = sl[src];
    kh[idx] = sh[src + 1024];   kl[idx] = sl[src + 1024];
    vh[idx] = sh[src + 2048];   vl[idx] = sl[src + 2048];
}

// ================= launcher =================
extern "C" void kernel_launch(void* const* d_in, const int* in_sizes, int n_in,
                              void* d_out, int out_size)
{
    (void)in_sizes; (void)n_in; (void)out_size;
    const float* x      = (const float*)d_in[0];
    const float* ln1_g  = (const float*)d_in[1];
    const float* ln1_b  = (const float*)d_in[2];
    const float* Wq     = (const float*)d_in[3];
    const float* Wk     = (const float*)d_in[4];
    const float* Wv     = (const float*)d_in[5];
    const float* proj_W = (const float*)d_in[6];
    const float* proj_b = (const float*)d_in[7];
    const float* ln2_g  = (const float*)d_in[8];
    const float* ln2_b  = (const float*)d_in[9];
    const float* fin_W  = (const float*)d_in[10];
    const float* fin_b  = (const float*)d_in[11];
    const float* hid_W  = (const float*)d_in[12];
    const float* hid_b  = (const float*)d_in[13];
    const float* fout_W = (const float*)d_in[14];
    const float* fout_b = (const float*)d_in[15];
    float* out = (float*)d_out;

    float *x1, *fa, *fb, *wt;
    __nv_bfloat16 *sbh, *sbl, *qh, *ql, *kh, *kl, *vh, *vl;
    cudaGetSymbolAddress((void**)&x1,  g_x1);
    cudaGetSymbolAddress((void**)&fa,  g_fa);
    cudaGetSymbolAddress((void**)&fb,  g_fb);
    cudaGetSymbolAddress((void**)&wt,  g_wt);
    cudaGetSymbolAddress((void**)&sbh, g_sbh);
    cudaGetSymbolAddress((void**)&sbl, g_sbl);
    cudaGetSymbolAddress((void**)&qh,  g_qh);
    cudaGetSymbolAddress((void**)&ql,  g_ql);
    cudaGetSymbolAddress((void**)&kh,  g_kh);
    cudaGetSymbolAddress((void**)&kl,  g_kl);
    cudaGetSymbolAddress((void**)&vh,  g_vh);
    cudaGetSymbolAddress((void**)&vl,  g_vl);

    constexpr int SMG = 196608;    // 3 stages x 64KB
    constexpr int SMF = 163840;    // flash
    cudaFuncSetAttribute((const void*)tf32_gemm<false, false, false, false, true>,
                         cudaFuncAttributeMaxDynamicSharedMemorySize, SMG);
    cudaFuncSetAttribute((const void*)tf32_gemm<true, false, true, false, false>,
                         cudaFuncAttributeMaxDynamicSharedMemorySize, SMG);
    cudaFuncSetAttribute((const void*)tf32_gemm<true, true, false, true, false>,
                         cudaFuncAttributeMaxDynamicSharedMemorySize, SMG);
    cudaFuncSetAttribute((const void*)flash_kernel,
                         cudaFuncAttributeMaxDynamicSharedMemorySize, SMF);

    // ---------- attention ----------
    ln_tf32_kernel<<<MTOK, 256>>>(x, ln1_g, ln1_b, fa);
    qkvw_prep<<<EE * 3072 / 256, 256>>>(Wq, Wk, Wv, wt);

    // QKV: [4096,1024] @ [1024,3072] -> split-bf16 [t][3072]
    tf32_gemm<false, false, false, false, true><<<dim3(3072 / 128, MTOK / 128), 256, SMG>>>(
        fa, wt, nullptr, nullptr, nullptr, sbh, sbl, MTOK, 3072, EE);
    qkv_reorder_bf<<<HH * MTOK * KDIM / 256, 256>>>(sbh, sbl, qh, ql, kh, kl, vh, vl);

    // fused causal attention (split-bf16 internally) -> fp32 tf32-rounded concat
    flash_kernel<<<dim3(SS / 128, HH * BB), 256, SMF>>>(
        qh, ql, kh, kl, vh, vl, fb);

    // x1 = x + o @ proj_W + proj_b
    ffnw_prep<<<EE * EE / 256, 256>>>(proj_W, wt, EE, EE);
    tf32_gemm<true, false, true, false, false><<<dim3(EE / 128, MTOK / 128), 256, SMG>>>(
        fb, wt, proj_b, x, x1, nullptr, nullptr, MTOK, EE, EE);

    // ---------- FFN (all tf32) ----------
    ln_tf32_kernel<<<MTOK, 256>>>(x1, ln2_g, ln2_b, fa);

    ffnw_prep<<<EE * DD / 256, 256>>>(fin_W, wt, EE, DD);
    tf32_gemm<true, true, false, true, false><<<dim3(DD / 128, MTOK / 128), 256, SMG>>>(
        fa, wt, fin_b, nullptr, fb, nullptr, nullptr, MTOK, DD, EE);

    ffnw_prep<<<DD * DD / 256, 256>>>(hid_W, wt, DD, DD);
    tf32_gemm<true, true, false, true, false><<<dim3(DD / 128, MTOK / 128), 256, SMG>>>(
        fb, wt, hid_b, nullptr, fa, nullptr, nullptr, MTOK, DD, DD);

    ffnw_prep<<<DD * DD / 256, 256>>>(hid_W + (size_t)DD * DD, wt, DD, DD);
    tf32_gemm<true, true, false, true, false><<<dim3(DD / 128, MTOK / 128), 256, SMG>>>(
        fa, wt, hid_b + DD, nullptr, fb, nullptr, nullptr, MTOK, DD, DD);

    ffnw_prep<<<DD * EE / 256, 256>>>(fout_W, wt, DD, EE);
    tf32_gemm<true, false, true, false, false><<<dim3(EE / 128, MTOK / 128), 256, SMG>>>(
        fb, wt, fout_b, x1, out, nullptr, nullptr, MTOK, EE, DD);
}

// round 17
// speedup vs baseline: 3.0798x; 1.9380x over previous
#include <cuda_runtime.h>
#include <cuda_bf16.h>
#include <cuda_fp16.h>
#include <math.h>
#include <stdint.h>
#include <string.h>

// ---------------- problem constants ----------------
#define BB   4
#define SS   1024
#define EE   1024
#define HH   16
#define KDIM 64
#define VDIM 64
#define DD   4096
#define MTOK 4096            // B*S tokens
#define LNEPS 1e-5f

// ---------------- device scratch (static globals; no allocations) ----------------
__device__ float g_x1[MTOK * EE];
__device__ __half g_ha[(size_t)MTOK * DD];             // fp16 activations (A operands)
__device__ __half g_hb[(size_t)MTOK * DD];
__device__ __half g_w16[(size_t)DD * DD];              // fp16 weights [K,N]
__device__ __nv_bfloat16 g_sbh[(size_t)MTOK * 3072];   // QKV gemm split output
__device__ __nv_bfloat16 g_sbl[(size_t)MTOK * 3072];
__device__ __nv_bfloat16 g_qh[HH * MTOK * KDIM];
__device__ __nv_bfloat16 g_ql[HH * MTOK * KDIM];
__device__ __nv_bfloat16 g_kh[HH * MTOK * KDIM];
__device__ __nv_bfloat16 g_kl[HH * MTOK * KDIM];
__device__ __nv_bfloat16 g_vh[HH * MTOK * VDIM];
__device__ __nv_bfloat16 g_vl[HH * MTOK * VDIM];

// ================= low-level helpers (sm_80+ base-target PTX only) =================
__device__ __forceinline__ uint32_t smem_to_u32(const void* p) {
    uint32_t a;
    asm("{ .reg .u64 t; cvta.to.shared.u64 t, %1; cvt.u32.u64 %0, t; }"
        : "=r"(a) : "l"(p));
    return a;
}
__device__ __forceinline__ void cp_async16(uint32_t dst, const void* src) {
    asm volatile("cp.async.cg.shared.global [%0], [%1], 16;"
                 :: "r"(dst), "l"(src) : "memory");
}
#define CP_COMMIT() asm volatile("cp.async.commit_group;" ::: "memory")
#define CP_WAIT(n)  asm volatile("cp.async.wait_group %0;" :: "n"(n) : "memory")

__device__ __forceinline__ void ldmatrix_x4(uint32_t& r0, uint32_t& r1,
                                            uint32_t& r2, uint32_t& r3, uint32_t addr) {
    asm volatile("ldmatrix.sync.aligned.m8n8.x4.shared.b16 {%0,%1,%2,%3}, [%4];"
                 : "=r"(r0), "=r"(r1), "=r"(r2), "=r"(r3) : "r"(addr));
}
__device__ __forceinline__ void ldmatrix_x4_trans(uint32_t& r0, uint32_t& r1,
                                                  uint32_t& r2, uint32_t& r3, uint32_t addr) {
    asm volatile("ldmatrix.sync.aligned.m8n8.x4.trans.shared.b16 {%0,%1,%2,%3}, [%4];"
                 : "=r"(r0), "=r"(r1), "=r"(r2), "=r"(r3) : "r"(addr));
}
__device__ __forceinline__ void mma_bf16(float* d, const uint32_t* a, const uint32_t* b) {
    asm volatile(
        "mma.sync.aligned.m16n8k16.row.col.f32.bf16.bf16.f32 "
        "{%0,%1,%2,%3}, {%4,%5,%6,%7}, {%8,%9}, {%0,%1,%2,%3};"
        : "+f"(d[0]), "+f"(d[1]), "+f"(d[2]), "+f"(d[3])
        : "r"(a[0]), "r"(a[1]), "r"(a[2]), "r"(a[3]), "r"(b[0]), "r"(b[1]));
}
__device__ __forceinline__ void mma_f16(float* d, const uint32_t* a, const uint32_t* b) {
    asm volatile(
        "mma.sync.aligned.m16n8k16.row.col.f32.f16.f16.f32 "
        "{%0,%1,%2,%3}, {%4,%5,%6,%7}, {%8,%9}, {%0,%1,%2,%3};"
        : "+f"(d[0]), "+f"(d[1]), "+f"(d[2]), "+f"(d[3])
        : "r"(a[0]), "r"(a[1]), "r"(a[2]), "r"(a[3]), "r"(b[0]), "r"(b[1]));
}
__device__ __forceinline__ uint32_t pack_bf16x2(__nv_bfloat16 a, __nv_bfloat16 b) {
    return (uint32_t)__bfloat16_as_ushort(a) | ((uint32_t)__bfloat16_as_ushort(b) << 16);
}
__device__ __forceinline__ uint32_t pack_h2(float a, float b) {
    const __half2 h = __halves2half2(__float2half_rn(a), __float2half_rn(b));
    return *(const uint32_t*)&h;
}

// ================= fp16 single-pass tensor-core GEMM (all linears) =================
// C[M,N] = A[M,K] @ B[K,N] (+bias)(+relu)(+res).
// A: fp16 row-major. B: fp16 natural [K,N]; fragments via ldmatrix.trans.
// Output: fp32 (OHALF=0,OSPLIT=0), packed fp16 (OHALF), or bf16 hi/lo (OSPLIT).
// CTA 128 x 128, BK=64, 3-stage cp.async pipeline, 2 CTAs/SM.
template<bool BIAS, bool RELU, bool RES, bool OSPLIT, bool OHALF>
__global__ __launch_bounds__(256, 2) void h16_gemm(
    const __half* __restrict__ A, const __half* __restrict__ B,
    const float* __restrict__ bias, const float* __restrict__ res,
    float* __restrict__ C, __half* __restrict__ Cf16,
    __nv_bfloat16* __restrict__ Ch, __nv_bfloat16* __restrict__ Cl,
    int M, int N, int K)
{
    constexpr int BK = 64;
    constexpr int NFRAG = 8;
    constexpr int ASZ = 128 * 128;              // 16384 (128 rows x 128B)
    constexpr int BSZ = BK * 256;               // 16384 (64 k-rows x 256B)
    constexpr int STAGE = ASZ + BSZ;            // 32768

    extern __shared__ char smem[];
    const uint32_t sb = smem_to_u32(smem);

    const int m0 = blockIdx.y * 128;
    const int n0 = blockIdx.x * 128;
    const int tid = threadIdx.x;
    const int lane = tid & 31;
    const int wid = tid >> 5;
    const int wm = wid >> 1;
    const int wn = wid & 1;

    auto load_stage = [&](int kc, int s) {
        const uint32_t st = sb + s * STAGE;
        const int koff = kc * BK;
#pragma unroll
        for (int i = 0; i < 4; i++) {           // A: 128 rows x 8 groups of 16B
            const int idx = tid + i * 256;
            const int row = idx >> 3, g = idx & 7;
            const uint32_t d = st + row * 128 + ((g ^ (row & 7)) << 4);
            cp_async16(d, A + (size_t)(m0 + row) * K + koff + g * 8);
        }
#pragma unroll
        for (int i = 0; i < 4; i++) {           // B: 64 k-rows x 16 groups of 16B
            const int idx = tid + i * 256;
            const int row = idx >> 4, g = idx & 15;
            const uint32_t d = st + ASZ + row * 256 + ((g ^ (row & 7)) << 4);
            cp_async16(d, B + (size_t)(koff + row) * N + n0 + g * 8);
        }
    };

    float acc[2][NFRAG][4];
#pragma unroll
    for (int i = 0; i < 2; i++)
#pragma unroll
        for (int j = 0; j < NFRAG; j++)
#pragma unroll
            for (int c = 0; c < 4; c++) acc[i][j][c] = 0.f;

    const int KC = K / BK;
    load_stage(0, 0);
    CP_COMMIT();
    if (KC > 1) { load_stage(1, 1); CP_COMMIT(); }

    int sidx = 0;
    for (int kc = 0; kc < KC; kc++) {
        if (kc + 1 < KC) CP_WAIT(1); else CP_WAIT(0);
        __syncthreads();
        if (kc + 2 < KC) {
            int ns = sidx + 2; if (ns >= 3) ns -= 3;
            load_stage(kc + 2, ns);
            CP_COMMIT();
        }
        const uint32_t st = sb + sidx * STAGE;
#pragma unroll
        for (int ks = 0; ks < 4; ks++) {         // 4 x K=16 per chunk
            uint32_t af[2][4];
#pragma unroll
            for (int mf = 0; mf < 2; mf++) {
                const int row = wm * 32 + mf * 16 + (lane & 15);
                const int g = (ks * 2 + (lane >> 4)) ^ (row & 7);
                const uint32_t addr = st + row * 128 + (g << 4);
                ldmatrix_x4(af[mf][0], af[mf][1], af[mf][2], af[mf][3], addr);
            }
            uint32_t bf[NFRAG][2];
#pragma unroll
            for (int nq = 0; nq < NFRAG / 2; nq++) {
                const int row = ks * 16 + (lane & 15);
                const int g = (wn * 8 + nq * 2 + (lane >> 4)) ^ (row & 7);
                const uint32_t addr = st + ASZ + row * 256 + (g << 4);
                uint32_t d0, d1, d2, d3;
                ldmatrix_x4_trans(d0, d1, d2, d3, addr);
                bf[2 * nq][0] = d0; bf[2 * nq][1] = d1;
                bf[2 * nq + 1][0] = d2; bf[2 * nq + 1][1] = d3;
            }
#pragma unroll
            for (int mf = 0; mf < 2; mf++)
#pragma unroll
                for (int nf = 0; nf < NFRAG; nf++)
                    mma_f16(acc[mf][nf], af[mf], bf[nf]);
        }
        if (++sidx == 3) sidx = 0;
    }

    // ---- epilogue ----
#pragma unroll
    for (int mf = 0; mf < 2; mf++) {
        const int r0i = m0 + wm * 32 + mf * 16 + (lane >> 2);
#pragma unroll
        for (int nf = 0; nf < NFRAG; nf++) {
            const int col = n0 + wn * 64 + nf * 8 + (lane & 3) * 2;
            float2 bv = make_float2(0.f, 0.f);
            if (BIAS) { bv.x = bias[col]; bv.y = bias[col + 1]; }
#pragma unroll
            for (int hrow = 0; hrow < 2; hrow++) {
                const int rr = r0i + hrow * 8;
                float2 v;
                v.x = acc[mf][nf][2 * hrow + 0] + bv.x;
                v.y = acc[mf][nf][2 * hrow + 1] + bv.y;
                if (RES) {
                    const float2 rv = *(const float2*)(res + (size_t)rr * N + col);
                    v.x += rv.x; v.y += rv.y;
                }
                if (RELU) { v.x = fmaxf(v.x, 0.f); v.y = fmaxf(v.y, 0.f); }
                if (OSPLIT) {
                    const __nv_bfloat16 h0 = __float2bfloat16(v.x);
                    const __nv_bfloat16 h1 = __float2bfloat16(v.y);
                    const __nv_bfloat16 l0 = __float2bfloat16(v.x - __bfloat162float(h0));
                    const __nv_bfloat16 l1 = __float2bfloat16(v.y - __bfloat162float(h1));
                    *(uint32_t*)(Ch + (size_t)rr * N + col) = pack_bf16x2(h0, h1);
                    *(uint32_t*)(Cl + (size_t)rr * N + col) = pack_bf16x2(l0, l1);
                } else if (OHALF) {
                    *(uint32_t*)(Cf16 + (size_t)rr * N + col) = pack_h2(v.x, v.y);
                } else {
                    *(float2*)(C + (size_t)rr * N + col) = v;
                }
            }
        }
    }
}

// ================= flash attention (causal, faithful ==0 mask) =================
// grid (qt=8, hb=64); q/k/v split bf16 [hb][S][64]; output fp16 concat [token][EE].
__global__ __launch_bounds__(256, 1) void flash_kernel(
    const __nv_bfloat16* __restrict__ qh, const __nv_bfloat16* __restrict__ ql,
    const __nv_bfloat16* __restrict__ kh, const __nv_bfloat16* __restrict__ kl,
    const __nv_bfloat16* __restrict__ vh, const __nv_bfloat16* __restrict__ vl,
    __half* __restrict__ o)
{
    extern __shared__ char smem[];
    const uint32_t sb = smem_to_u32(smem);
    const int qt = blockIdx.x;
    const int hb = blockIdx.y;
    const int tid = threadIdx.x, lane = tid & 31, w = tid >> 5;

    const size_t hbase = (size_t)hb * SS * 64;
    const __nv_bfloat16* Qh = qh + hbase + (size_t)qt * 128 * 64;
    const __nv_bfloat16* Ql = ql + hbase + (size_t)qt * 128 * 64;
    const __nv_bfloat16* Kh = kh + hbase;
    const __nv_bfloat16* Kl = kl + hbase;
    const __nv_bfloat16* Vh = vh + hbase;
    const __nv_bfloat16* Vl = vl + hbase;

#pragma unroll
    for (int i = 0; i < 4; i++) {
        const int idx = tid + i * 256;
        const int row = idx >> 3, g = idx & 7;
        const uint32_t off = row * 128 + ((g ^ (row & 7)) << 4);
        const size_t src = (size_t)row * 64 + g * 8;
        cp_async16(sb + off,         Qh + src);
        cp_async16(sb + 16384 + off, Ql + src);
    }
    auto load_kv = [&](int jt, int s) {
        const uint32_t st = sb + 32768 + s * 65536;
        const size_t base = (size_t)jt * 128 * 64;
#pragma unroll
        for (int i = 0; i < 4; i++) {
            const int idx = tid + i * 256;
            const int row = idx >> 3, g = idx & 7;
            const uint32_t off = row * 128 + ((g ^ (row & 7)) << 4);
            const size_t src = base + (size_t)row * 64 + g * 8;
            cp_async16(st + off,         Kh + src);
            cp_async16(st + 16384 + off, Kl + src);
            cp_async16(st + 32768 + off, Vh + src);
            cp_async16(st + 49152 + off, Vl + src);
        }
    };
    load_kv(0, 0);
    CP_COMMIT();

    uint32_t qfh[4][4], qfl[4][4];
    float ofr[8][4];
    float mrow[2] = {-INFINITY, -INFINITY};
    float lrow[2] = {0.f, 0.f};
#pragma unroll
    for (int f = 0; f < 8; f++)
#pragma unroll
        for (int c = 0; c < 4; c++) ofr[f][c] = 0.f;

    const int rb = qt * 128 + w * 16 + (lane >> 2);

    for (int jt = 0; jt <= qt; jt++) {
        if (jt < qt) { load_kv(jt + 1, (jt + 1) & 1); CP_COMMIT(); CP_WAIT(1); }
        else CP_WAIT(0);
        __syncthreads();

        if (jt == 0) {
#pragma unroll
            for (int kk = 0; kk < 4; kk++) {
                const int row = w * 16 + (lane & 15);
                const uint32_t c = (uint32_t)((kk * 2 + (lane >> 4)) ^ (row & 7));
                const uint32_t addr = sb + row * 128 + (c << 4);
                ldmatrix_x4(qfh[kk][0], qfh[kk][1], qfh[kk][2], qfh[kk][3], addr);
                ldmatrix_x4(qfl[kk][0], qfl[kk][1], qfl[kk][2], qfl[kk][3], addr + 16384);
            }
        }

        const uint32_t st = sb + 32768 + (jt & 1) * 65536;

        float cfr[16][4];
#pragma unroll
        for (int f = 0; f < 16; f++)
#pragma unroll
            for (int c = 0; c < 4; c++) cfr[f][c] = 0.f;

#pragma unroll
        for (int kk = 0; kk < 4; kk++) {
#pragma unroll
            for (int nq = 0; nq < 8; nq++) {
                const int row = nq * 16 + (lane & 15);
                const uint32_t c = (uint32_t)((kk * 2 + (lane >> 4)) ^ (row & 7));
                const uint32_t addr = st + row * 128 + (c << 4);
                uint32_t r0, r1, r2, r3, s0, s1, s2, s3;
                ldmatrix_x4(r0, r1, r2, r3, addr);
                ldmatrix_x4(s0, s1, s2, s3, addr + 16384);
                uint32_t bh0[2] = {r0, r2}, bh1[2] = {r1, r3};
                uint32_t bl0[2] = {s0, s2}, bl1[2] = {s1, s3};
                mma_bf16(cfr[2 * nq],     qfh[kk], bh0);
                mma_bf16(cfr[2 * nq],     qfh[kk], bl0);
                mma_bf16(cfr[2 * nq],     qfl[kk], bh0);
                mma_bf16(cfr[2 * nq + 1], qfh[kk], bh1);
                mma_bf16(cfr[2 * nq + 1], qfh[kk], bl1);
                mma_bf16(cfr[2 * nq + 1], qfl[kk], bh1);
            }
        }

        float tm[2] = {-INFINITY, -INFINITY};
#pragma unroll
        for (int f = 0; f < 16; f++) {
            const int col = jt * 128 + f * 8 + (lane & 3) * 2;
#pragma unroll
            for (int h2 = 0; h2 < 2; h2++) {
                const int rg = rb + h2 * 8;
                float v0 = cfr[f][2 * h2], v1 = cfr[f][2 * h2 + 1];
                v0 = (v0 == 0.f || col > rg)     ? -INFINITY : v0 * 0.125f;
                v1 = (v1 == 0.f || col + 1 > rg) ? -INFINITY : v1 * 0.125f;
                cfr[f][2 * h2] = v0; cfr[f][2 * h2 + 1] = v1;
                tm[h2] = fmaxf(tm[h2], fmaxf(v0, v1));
            }
        }
#pragma unroll
        for (int h2 = 0; h2 < 2; h2++) {
            tm[h2] = fmaxf(tm[h2], __shfl_xor_sync(0xffffffffu, tm[h2], 1));
            tm[h2] = fmaxf(tm[h2], __shfl_xor_sync(0xffffffffu, tm[h2], 2));
            const float mn = fmaxf(mrow[h2], tm[h2]);
            const float alpha = __expf(mrow[h2] - mn);
            mrow[h2] = mn;
            lrow[h2] *= alpha;
#pragma unroll
            for (int f = 0; f < 8; f++) {
                ofr[f][2 * h2]     *= alpha;
                ofr[f][2 * h2 + 1] *= alpha;
            }
        }
        float rs[2] = {0.f, 0.f};
#pragma unroll
        for (int f = 0; f < 16; f++) {
#pragma unroll
            for (int h2 = 0; h2 < 2; h2++) {
                const float p0 = __expf(cfr[f][2 * h2]     - mrow[h2]);
                const float p1 = __expf(cfr[f][2 * h2 + 1] - mrow[h2]);
                cfr[f][2 * h2] = p0; cfr[f][2 * h2 + 1] = p1;
                rs[h2] += p0 + p1;
            }
        }
#pragma unroll
        for (int h2 = 0; h2 < 2; h2++) {
            rs[h2] += __shfl_xor_sync(0xffffffffu, rs[h2], 1);
            rs[h2] += __shfl_xor_sync(0xffffffffu, rs[h2], 2);
            lrow[h2] += rs[h2];
        }

#pragma unroll
        for (int kk2 = 0; kk2 < 8; kk2++) {
            uint32_t pah[4], pal[4];
#pragma unroll
            for (int r = 0; r < 4; r++) {
                const int f = 2 * kk2 + (r >> 1);
                const int c0 = (r & 1) * 2;
                const float f0 = cfr[f][c0], f1 = cfr[f][c0 + 1];
                const __nv_bfloat16 h0 = __float2bfloat16(f0);
                const __nv_bfloat16 h1 = __float2bfloat16(f1);
                const __nv_bfloat16 l0 = __float2bfloat16(f0 - __bfloat162float(h0));
                const __nv_bfloat16 l1 = __float2bfloat16(f1 - __bfloat162float(h1));
                pah[r] = pack_bf16x2(h0, h1);
                pal[r] = pack_bf16x2(l0, l1);
            }
#pragma unroll
            for (int of2 = 0; of2 < 4; of2++) {
                const int row = kk2 * 16 + (lane & 15);
                const uint32_t c = (uint32_t)((of2 * 2 + (lane >> 4)) ^ (row & 7));
                const uint32_t addr = st + 32768 + row * 128 + (c << 4);
                uint32_t d0, d1, d2, d3, e0, e1, e2, e3;
                ldmatrix_x4_trans(d0, d1, d2, d3, addr);
                ldmatrix_x4_trans(e0, e1, e2, e3, addr + 16384);
                uint32_t v0h[2] = {d0, d1}, v1h[2] = {d2, d3};
                uint32_t v0l[2] = {e0, e1}, v1l[2] = {e2, e3};
                mma_bf16(ofr[2 * of2],     pah, v0h);
                mma_bf16(ofr[2 * of2],     pah, v0l);
                mma_bf16(ofr[2 * of2],     pal, v0h);
                mma_bf16(ofr[2 * of2 + 1], pah, v1h);
                mma_bf16(ofr[2 * of2 + 1], pah, v1l);
                mma_bf16(ofr[2 * of2 + 1], pal, v1h);
            }
        }
        __syncthreads();
    }

    // ---- finalize: O /= l, write fp16 concat layout ----
    const float inv0 = 1.f / lrow[0], inv1 = 1.f / lrow[1];
    const int hI = hb >> 2, bI = hb & 3;
    const int s0 = qt * 128 + w * 16 + (lane >> 2);
#pragma unroll
    for (int f = 0; f < 8; f++) {
        const int col = hI * 64 + f * 8 + (lane & 3) * 2;
#pragma unroll
        for (int h2 = 0; h2 < 2; h2++) {
            const int token = bI * SS + s0 + h2 * 8;
            const float inv = h2 ? inv1 : inv0;
            *(uint32_t*)(o + (size_t)token * EE + col) =
                pack_h2(ofr[f][2 * h2] * inv, ofr[f][2 * h2 + 1] * inv);
        }
    }
}

// ================= fused LayerNorm -> fp16 =================
__global__ __launch_bounds__(256) void ln_h_kernel(
    const float* __restrict__ x, const float* __restrict__ g,
    const float* __restrict__ b, __half* __restrict__ out)
{
    __shared__ float row[EE];
    __shared__ float red[256];
    const int r = blockIdx.x;
    const int t = threadIdx.x;
    const float* xr = x + (size_t)r * EE;

    float s = 0.f;
    for (int i = t; i < EE; i += 256) { float v = xr[i]; row[i] = v; s += v; }
    red[t] = s; __syncthreads();
    for (int o = 128; o > 0; o >>= 1) { if (t < o) red[t] += red[t + o]; __syncthreads(); }
    const float mean = red[0] * (1.0f / EE);
    __syncthreads();

    float vs = 0.f;
    for (int i = t; i < EE; i += 256) { float d = row[i] - mean; vs += d * d; }
    red[t] = vs; __syncthreads();
    for (int o = 128; o > 0; o >>= 1) { if (t < o) red[t] += red[t + o]; __syncthreads(); }
    const float rstd = rsqrtf(red[0] * (1.0f / EE) + LNEPS);

    __half* orow = out + (size_t)r * EE;
    for (int i = t; i < EE; i += 256)
        orow[i] = __float2half_rn((row[i] - mean) * rstd * g[i] + b[i]);
}

// ================= elementwise fp32 [K,N] -> fp16 =================
__global__ __launch_bounds__(256) void w16_prep(
    const float* __restrict__ W, __half* __restrict__ out, int n)
{
    const int i = (blockIdx.x * 256 + threadIdx.x) * 4;
    if (i >= n) return;
    const float4 v = *(const float4*)(W + i);
    uint2* p = (uint2*)(out + i);
    *p = make_uint2(pack_h2(v.x, v.y), pack_h2(v.z, v.w));
}

// QKV weights [H][E][64] x3 -> combined fp16 [E][3072]
__global__ __launch_bounds__(256) void qkvw16_prep(
    const float* __restrict__ Wq, const float* __restrict__ Wk,
    const float* __restrict__ Wv, __half* __restrict__ out)
{
    const int idx = blockIdx.x * 256 + threadIdx.x;   // over E*3072
    const int e = idx / 3072;
    const int c = idx % 3072;
    const float* W = (c < 1024) ? Wq : (c < 2048 ? Wk : Wv);
    const int cc = c & 1023;
    const int h = cc >> 6, kd = cc & 63;
    out[idx] = __float2half_rn(W[(size_t)h * EE * 64 + (size_t)e * 64 + kd]);
}

// split QKV GEMM output [t][3072] -> q/k/v [hb][s][64]
__global__ __launch_bounds__(256) void qkv_reorder_bf(
    const __nv_bfloat16* __restrict__ sh, const __nv_bfloat16* __restrict__ sl,
    __nv_bfloat16* __restrict__ qh, __nv_bfloat16* __restrict__ ql,
    __nv_bfloat16* __restrict__ kh, __nv_bfloat16* __restrict__ kl,
    __nv_bfloat16* __restrict__ vh, __nv_bfloat16* __restrict__ vl)
{
    const int idx = blockIdx.x * 256 + threadIdx.x;
    const int kd = idx & 63;
    const int t  = (idx >> 6) & (MTOK - 1);
    const int h  = idx >> 18;
    const size_t src = (size_t)t * 3072 + h * 64 + kd;
    qh[idx] = sh[src];          ql[idx] = sl[src];
    kh[idx] = sh[src + 1024];   kl[idx] = sl[src + 1024];
    vh[idx] = sh[src + 2048];   vl[idx] = sl[src + 2048];
}

// ================= launcher =================
extern "C" void kernel_launch(void* const* d_in, const int* in_sizes, int n_in,
                              void* d_out, int out_size)
{
    (void)in_sizes; (void)n_in; (void)out_size;
    const float* x      = (const float*)d_in[0];
    const float* ln1_g  = (const float*)d_in[1];
    const float* ln1_b  = (const float*)d_in[2];
    const float* Wq     = (const float*)d_in[3];
    const float* Wk     = (const float*)d_in[4];
    const float* Wv     = (const float*)d_in[5];
    const float* proj_W = (const float*)d_in[6];
    const float* proj_b = (const float*)d_in[7];
    const float* ln2_g  = (const float*)d_in[8];
    const float* ln2_b  = (const float*)d_in[9];
    const float* fin_W  = (const float*)d_in[10];
    const float* fin_b  = (const float*)d_in[11];
    const float* hid_W  = (const float*)d_in[12];
    const float* hid_b  = (const float*)d_in[13];
    const float* fout_W = (const float*)d_in[14];
    const float* fout_b = (const float*)d_in[15];
    float* out = (float*)d_out;

    float *x1;
    __half *ha, *hb, *w16;
    __nv_bfloat16 *sbh, *sbl, *qh, *ql, *kh, *kl, *vh, *vl;
    cudaGetSymbolAddress((void**)&x1,  g_x1);
    cudaGetSymbolAddress((void**)&ha,  g_ha);
    cudaGetSymbolAddress((void**)&hb,  g_hb);
    cudaGetSymbolAddress((void**)&w16, g_w16);
    cudaGetSymbolAddress((void**)&sbh, g_sbh);
    cudaGetSymbolAddress((void**)&sbl, g_sbl);
    cudaGetSymbolAddress((void**)&qh,  g_qh);
    cudaGetSymbolAddress((void**)&ql,  g_ql);
    cudaGetSymbolAddress((void**)&kh,  g_kh);
    cudaGetSymbolAddress((void**)&kl,  g_kl);
    cudaGetSymbolAddress((void**)&vh,  g_vh);
    cudaGetSymbolAddress((void**)&vl,  g_vl);

    constexpr int SMG = 98304;     // 3 stages x 32KB (2 CTAs/SM)
    constexpr int SMF = 163840;    // flash
    cudaFuncSetAttribute((const void*)h16_gemm<false, false, false, true, false>,
                         cudaFuncAttributeMaxDynamicSharedMemorySize, SMG);
    cudaFuncSetAttribute((const void*)h16_gemm<true, false, true, false, false>,
                         cudaFuncAttributeMaxDynamicSharedMemorySize, SMG);
    cudaFuncSetAttribute((const void*)h16_gemm<true, true, false, false, true>,
                         cudaFuncAttributeMaxDynamicSharedMemorySize, SMG);
    cudaFuncSetAttribute((const void*)flash_kernel,
                         cudaFuncAttributeMaxDynamicSharedMemorySize, SMF);

    // ---------- attention ----------
    ln_h_kernel<<<MTOK, 256>>>(x, ln1_g, ln1_b, ha);
    qkvw16_prep<<<EE * 3072 / 256, 256>>>(Wq, Wk, Wv, w16);

    // QKV: [4096,1024] @ [1024,3072] -> split-bf16 [t][3072] for flash
    h16_gemm<false, false, false, true, false><<<dim3(3072 / 128, MTOK / 128), 256, SMG>>>(
        ha, w16, nullptr, nullptr, nullptr, nullptr, sbh, sbl, MTOK, 3072, EE);
    qkv_reorder_bf<<<HH * MTOK * KDIM / 256, 256>>>(sbh, sbl, qh, ql, kh, kl, vh, vl);

    // fused causal attention (split-bf16 internally) -> fp16 concat
    flash_kernel<<<dim3(SS / 128, HH * BB), 256, SMF>>>(
        qh, ql, kh, kl, vh, vl, hb);

    // x1 = x + o @ proj_W + proj_b
    w16_prep<<<EE * EE / 1024, 256>>>(proj_W, w16, EE * EE);
    h16_gemm<true, false, true, false, false><<<dim3(EE / 128, MTOK / 128), 256, SMG>>>(
        hb, w16, proj_b, x, x1, nullptr, nullptr, nullptr, MTOK, EE, EE);

    // ---------- FFN (all fp16 single-pass) ----------
    ln_h_kernel<<<MTOK, 256>>>(x1, ln2_g, ln2_b, ha);

    w16_prep<<<EE * DD / 1024, 256>>>(fin_W, w16, EE * DD);
    h16_gemm<true, true, false, false, true><<<dim3(DD / 128, MTOK / 128), 256, SMG>>>(
        ha, w16, fin_b, nullptr, nullptr, hb, nullptr, nullptr, MTOK, DD, EE);

    w16_prep<<<DD * DD / 1024, 256>>>(hid_W, w16, DD * DD);
    h16_gemm<true, true, false, false, true><<<dim3(DD / 128, MTOK / 128), 256, SMG>>>(
        hb, w16, hid_b, nullptr, nullptr, ha, nullptr, nullptr, MTOK, DD, DD);

    w16_prep<<<DD * DD / 1024, 256>>>(hid_W + (size_t)DD * DD, w16, DD * DD);
    h16_gemm<true, true, false, false, true><<<dim3(DD / 128, MTOK / 128), 256, SMG>>>(
        ha, w16, hid_b + DD, nullptr, nullptr, hb, nullptr, nullptr, MTOK, DD, DD);

    w16_prep<<<DD * EE / 1024, 256>>>(fout_W, w16, DD * EE);
    h16_gemm<true, false, true, false, false><<<dim3(EE / 128, MTOK / 128), 256, SMG>>>(
        hb, w16, fout_b, x1, out, nullptr, nullptr, nullptr, MTOK, EE, DD);
}